// round 1
// baseline (speedup 1.0000x reference)
#include <cuda_runtime.h>
#include <cuda_bf16.h>
#include <math.h>

// ---------------------------------------------------------------------------
// Problem constants
// ---------------------------------------------------------------------------
#define BB   4
#define NN   256
#define OBS  64
#define QDIM 32
#define HH   256
#define DD   128
#define NOPS 8
#define QE   64
#define BN   (BB*NN)          // 1024 rows

#define EDGE_OFF 0
#define OP_OFF   (BB*NN*NN)                 // 262144
#define NEXT_OFF (OP_OFF + BB*NN*NN*NOPS)   // 2359296

// ---------------------------------------------------------------------------
// Device scratch (no allocation allowed)
// ---------------------------------------------------------------------------
__device__ float g_lat[BN*DD];
__device__ float g_EL[BN*HH];
__device__ float g_ER[BN*HH];
__device__ float g_OL[BN*HH];
__device__ float g_OR[BN*HH];

__device__ __forceinline__ float sigf(float x){ return 1.0f/(1.0f+expf(-x)); }

__device__ __forceinline__ unsigned long long splat2(float x){
    unsigned long long r;
    unsigned int u = __float_as_uint(x);
    asm("mov.b64 %0, {%1, %1};" : "=l"(r) : "r"(u));
    return r;
}
__device__ __forceinline__ unsigned long long fma2(unsigned long long a,
                                                   unsigned long long b,
                                                   unsigned long long c){
    unsigned long long d;
    asm("fma.rn.f32x2 %0, %1, %2, %3;" : "=l"(d) : "l"(a), "l"(b), "l"(c));
    return d;
}

// ---------------------------------------------------------------------------
// Kernel A: per-node pipeline.  8 rows per block, 128 blocks, 256 threads.
// obs->h1->node_emb->upd ; GRU(upd, latent)->lat ; q_emb ; next_pred.
// ---------------------------------------------------------------------------
__global__ __launch_bounds__(256)
void nodeKernel(const float* __restrict__ obs, const float* __restrict__ latent,
                const float* __restrict__ query,
                const float* __restrict__ enc_w1, const float* __restrict__ enc_b1,
                const float* __restrict__ enc_w2, const float* __restrict__ enc_b2,
                const float* __restrict__ upd_w,  const float* __restrict__ upd_b,
                const float* __restrict__ gru_wi, const float* __restrict__ gru_bi,
                const float* __restrict__ gru_wh, const float* __restrict__ gru_bh,
                const float* __restrict__ q_w,    const float* __restrict__ q_b,
                const float* __restrict__ nh_w1,  const float* __restrict__ nh_b1,
                const float* __restrict__ nh_w2,  const float* __restrict__ nh_b2,
                float* __restrict__ out_next)
{
    __shared__ float s_obs[8*64];     // later reused as q_emb [8][64]
    __shared__ float s_h1 [8*256];    // later: [0:1024)=upd [8][128], [1024:2048)=lat [8][128]
    __shared__ float s_emb[8*256];
    __shared__ float s_gi [8*384];    // later query tmp [8][32]
    __shared__ float s_gh [8*384];    // later nh hidden [8][256]

    const int t    = threadIdx.x;
    const int row0 = blockIdx.x * 8;

    for (int idx = t; idx < 8*64; idx += 256) s_obs[idx] = obs[row0*64 + idx];
    __syncthreads();

    // ---- h1 = relu(obs @ enc_w1 + b1) ----
    {
        float acc[8];
        #pragma unroll
        for (int r=0;r<8;r++) acc[r] = enc_b1[t];
        for (int k=0;k<64;k++){
            float w = enc_w1[k*256 + t];
            #pragma unroll
            for (int r=0;r<8;r++) acc[r] = fmaf(s_obs[r*64+k], w, acc[r]);
        }
        #pragma unroll
        for (int r=0;r<8;r++) s_h1[r*256+t] = fmaxf(acc[r], 0.0f);
    }
    __syncthreads();

    // ---- node_emb = relu(h1 @ enc_w2 + b2) ----
    {
        float acc[8];
        #pragma unroll
        for (int r=0;r<8;r++) acc[r] = enc_b2[t];
        for (int k=0;k<256;k++){
            float w = enc_w2[k*256 + t];
            #pragma unroll
            for (int r=0;r<8;r++) acc[r] = fmaf(s_h1[r*256+k], w, acc[r]);
        }
        __syncthreads();   // everyone done reading s_h1 before we overwrite it
        #pragma unroll
        for (int r=0;r<8;r++) s_emb[r*256+t] = fmaxf(acc[r], 0.0f);
    }
    __syncthreads();

    float* s_upd = s_h1;          // [8][128]
    float* s_lat = s_h1 + 1024;   // [8][128]

    // ---- upd = node_emb @ upd_w + b ----
    {
        const int o = t & 127;
        const int rbase = (t >> 7) * 4;
        float acc[4];
        #pragma unroll
        for (int rr=0;rr<4;rr++) acc[rr] = upd_b[o];
        for (int k=0;k<256;k++){
            float w = upd_w[k*128 + o];
            #pragma unroll
            for (int rr=0;rr<4;rr++) acc[rr] = fmaf(s_emb[(rbase+rr)*256+k], w, acc[rr]);
        }
        #pragma unroll
        for (int rr=0;rr<4;rr++) s_upd[(rbase+rr)*128+o] = acc[rr];
    }
    for (int idx = t; idx < 1024; idx += 256) s_lat[idx] = latent[row0*128 + idx];
    __syncthreads();

    // ---- gi = upd @ gru_wi + bi ; gh = latent @ gru_wh + bh ----
    for (int o = t; o < 384; o += 256){
        float ai[8], ah[8];
        #pragma unroll
        for (int r=0;r<8;r++){ ai[r] = gru_bi[o]; ah[r] = gru_bh[o]; }
        for (int k=0;k<128;k++){
            float wi = gru_wi[k*384 + o];
            float wh = gru_wh[k*384 + o];
            #pragma unroll
            for (int r=0;r<8;r++){
                ai[r] = fmaf(s_upd[r*128+k], wi, ai[r]);
                ah[r] = fmaf(s_lat[r*128+k], wh, ah[r]);
            }
        }
        #pragma unroll
        for (int r=0;r<8;r++){ s_gi[r*384+o] = ai[r]; s_gh[r*384+o] = ah[r]; }
    }
    __syncthreads();

    // ---- GRU elementwise ----
    for (int idx = t; idx < 1024; idx += 256){
        int r = idx >> 7, d = idx & 127;
        float ir = s_gi[r*384 + d],       iz = s_gi[r*384 + 128 + d], inn = s_gi[r*384 + 256 + d];
        float hr = s_gh[r*384 + d],       hz = s_gh[r*384 + 128 + d], hn  = s_gh[r*384 + 256 + d];
        float rg = sigf(ir + hr);
        float zg = sigf(iz + hz);
        float nh = tanhf(inn + rg*hn);
        float lv = (1.0f - zg)*nh + zg*s_lat[idx];
        s_lat[idx] = lv;
        g_lat[row0*128 + idx] = lv;
    }
    __syncthreads();

    // ---- q_emb = relu(query @ q_w + b) ----
    for (int idx = t; idx < 8*32; idx += 256) s_gi[idx] = query[row0*32 + idx];
    __syncthreads();
    for (int idx = t; idx < 512; idx += 256){
        int r = idx >> 6, o = idx & 63;
        float acc = q_b[o];
        for (int k=0;k<32;k++) acc = fmaf(s_gi[r*32+k], q_w[k*64+o], acc);
        s_obs[idx] = fmaxf(acc, 0.0f);
    }
    __syncthreads();

    // ---- nh hidden = relu([lat, emb, q] @ nh_w1 + b) ----
    {
        float acc[8];
        #pragma unroll
        for (int r=0;r<8;r++) acc[r] = nh_b1[t];
        for (int k=0;k<128;k++){
            float w = nh_w1[k*256 + t];
            #pragma unroll
            for (int r=0;r<8;r++) acc[r] = fmaf(s_lat[r*128+k], w, acc[r]);
        }
        for (int k=0;k<256;k++){
            float w = nh_w1[(128+k)*256 + t];
            #pragma unroll
            for (int r=0;r<8;r++) acc[r] = fmaf(s_emb[r*256+k], w, acc[r]);
        }
        for (int k=0;k<64;k++){
            float w = nh_w1[(384+k)*256 + t];
            #pragma unroll
            for (int r=0;r<8;r++) acc[r] = fmaf(s_obs[r*64+k], w, acc[r]);
        }
        #pragma unroll
        for (int r=0;r<8;r++) s_gh[r*256+t] = fmaxf(acc[r], 0.0f);
    }
    __syncthreads();

    // ---- next_pred = hidden @ nh_w2 + b ----
    {
        const int w = t >> 5, l = t & 31;   // warp w -> row w
        float p = 0.0f;
        for (int o = l; o < 256; o += 32) p = fmaf(s_gh[w*256 + o], nh_w2[o], p);
        #pragma unroll
        for (int off = 16; off; off >>= 1) p += __shfl_down_sync(0xffffffffu, p, off);
        if (l == 0) out_next[row0 + w] = p + nh_b2[0];
    }
}

// ---------------------------------------------------------------------------
// Kernel B: EL/ER/OL/OR = lat @ W_slice (+bias).  grid (64 row-tiles, 4 mats).
// ---------------------------------------------------------------------------
__global__ __launch_bounds__(256)
void elKernel(const float* __restrict__ eh_w1, const float* __restrict__ eh_b1,
              const float* __restrict__ oh_w1, const float* __restrict__ oh_b1)
{
    __shared__ float s_lat[16*128];
    const int t = threadIdx.x;
    const int row0 = blockIdx.x * 16;
    const int m = blockIdx.y;

    const float* W; const float* bias = nullptr; float* dst;
    if (m == 0)      { W = eh_w1;            bias = eh_b1; dst = g_EL; }
    else if (m == 1) { W = eh_w1 + 128*256;                dst = g_ER; }
    else if (m == 2) { W = oh_w1;            bias = oh_b1; dst = g_OL; }
    else             { W = oh_w1 + 128*256;                dst = g_OR; }

    for (int idx = t; idx < 2048; idx += 256) s_lat[idx] = g_lat[row0*128 + idx];
    __syncthreads();

    float acc[16];
    float bv = bias ? bias[t] : 0.0f;
    #pragma unroll
    for (int r=0;r<16;r++) acc[r] = bv;
    for (int k=0;k<128;k++){
        float w = W[k*256 + t];
        #pragma unroll
        for (int r=0;r<16;r++) acc[r] = fmaf(s_lat[r*128+k], w, acc[r]);
    }
    #pragma unroll
    for (int r=0;r<16;r++) dst[(row0+r)*256 + t] = acc[r];
}

// ---------------------------------------------------------------------------
// Kernel C: fused pair MLP.  Block = 8 i's x 16 j's (128 pairs) for one batch.
// hidden[p][h] = relu( |lat_i - lat_j| @ wA  + EL[i][h] + ER[j][h] )
// edge[p] = hidden . w2 ; op[p][8] = hidden @ w2op   (fused, smem-only)
// Inner GEMM uses packed fma.rn.f32x2 (2 MACs/instr -> ~128 MAC/cyc/SM).
// ---------------------------------------------------------------------------
#define TI 8
#define TJ 16
#define KT 16

__global__ __launch_bounds__(256)
void pairKernel(const float* __restrict__ eh_w1, const float* __restrict__ eh_w2,
                const float* __restrict__ eh_b2,
                const float* __restrict__ oh_w1, const float* __restrict__ oh_w2,
                const float* __restrict__ oh_b2,
                float* __restrict__ out)
{
    __shared__ float s_li[TI*128];                 // lat rows for i's
    __shared__ float s_lj[TJ*129];                 // padded, conflict-free fill
    __shared__ __align__(16) float s_u[4224];      // union: {a,w} mainloop | {eli,erj,w2e,w2o} epilogue
    __shared__ float s_edge[128];
    __shared__ float s_op[128*8];

    float* s_a   = s_u;              // [KT][128]
    float* s_w   = s_u + KT*128;     // [KT][128]
    float* s_eli = s_u;              // [TI][128]
    float* s_erj = s_u + 1024;       // [TJ][128]
    float* s_w2e = s_u + 3072;       // [128]
    float* s_w2o = s_u + 3200;       // [128][8]

    const int t  = threadIdx.x;
    const int tx = t & 15, ty = t >> 4;
    const int b  = blockIdx.z;
    const int i0 = blockIdx.y * TI;
    const int j0 = blockIdx.x * TJ;
    const int base = b * NN;

    for (int idx = t; idx < TI*128; idx += 256)
        s_li[idx] = g_lat[(base + i0)*128 + idx];
    for (int idx = t; idx < TJ*128; idx += 256){
        int r = idx >> 7, c = idx & 127;
        s_lj[r*129 + c] = g_lat[(base + j0 + r)*128 + c];
    }

    // thread's pairs: p = ty*8 + pi ;  i_loc = p>>4 = ty>>1 (const per thread)
    const int iloc  = ty >> 1;
    const int jbase = (ty & 1) * 8;

    for (int head = 0; head < 2; head++){
        const float* wA = (head == 0 ? eh_w1 : oh_w1) + 256*256;  // rows [256:384)
        const float* gL = head == 0 ? g_EL : g_OL;
        const float* gR = head == 0 ? g_ER : g_OR;

        if (head == 0){ if (t < 128) s_edge[t] = 0.0f; }
        else          { for (int idx = t; idx < 1024; idx += 256) s_op[idx] = 0.0f; }

        for (int h0 = 0; h0 < 256; h0 += 128){
            // acc[hi][pp] : packed f32x2 over pair-pairs (2*pp, 2*pp+1)
            unsigned long long acc[8][4];
            #pragma unroll
            for (int hi=0; hi<8; hi++)
                #pragma unroll
                for (int pp=0; pp<4; pp++) acc[hi][pp] = 0ull;

            for (int kt = 0; kt < 128; kt += KT){
                __syncthreads();   // previous use of s_u finished
                for (int idx = t; idx < KT*128; idx += 256){
                    int kk = idx >> 7, p = idx & 127;
                    s_a[idx] = fabsf(s_li[(p>>4)*128 + kt + kk] - s_lj[(p&15)*129 + kt + kk]);
                }
                for (int idx = t; idx < KT*128; idx += 256){
                    int kk = idx >> 7, h = idx & 127;
                    s_w[idx] = wA[(kt + kk)*256 + h0 + h];
                }
                __syncthreads();
                #pragma unroll
                for (int kk = 0; kk < KT; kk++){
                    const ulonglong2* ap = (const ulonglong2*)&s_a[kk*128 + ty*8];
                    ulonglong2 A0 = ap[0], A1 = ap[1];
                    unsigned long long a2[4] = {A0.x, A0.y, A1.x, A1.y};
                    const float4* bp = (const float4*)&s_w[kk*128 + tx*8];
                    float4 Bv0 = bp[0], Bv1 = bp[1];
                    float bv[8] = {Bv0.x,Bv0.y,Bv0.z,Bv0.w,Bv1.x,Bv1.y,Bv1.z,Bv1.w};
                    #pragma unroll
                    for (int hi = 0; hi < 8; hi++){
                        unsigned long long bs = splat2(bv[hi]);
                        #pragma unroll
                        for (int pp = 0; pp < 4; pp++)
                            acc[hi][pp] = fma2(a2[pp], bs, acc[hi][pp]);
                    }
                }
            }

            // ---- epilogue: load EL/ER/w2 into s_u (overwrites a/w), reduce ----
            __syncthreads();
            for (int idx = t; idx < TI*128; idx += 256)
                s_eli[idx] = gL[(base + i0 + (idx>>7))*256 + h0 + (idx & 127)];
            for (int idx = t; idx < TJ*128; idx += 256)
                s_erj[idx] = gR[(base + j0 + (idx>>7))*256 + h0 + (idx & 127)];
            if (head == 0){ if (t < 128) s_w2e[t] = eh_w2[h0 + t]; }
            else          { for (int idx = t; idx < 1024; idx += 256) s_w2o[idx] = oh_w2[h0*8 + idx]; }
            __syncthreads();

            #pragma unroll
            for (int pi = 0; pi < 8; pi++){
                const int j = jbase + pi;
                const int p = ty*8 + pi;
                float rv[8];
                #pragma unroll
                for (int hi = 0; hi < 8; hi++){
                    float2 v2 = *reinterpret_cast<float2*>(&acc[hi][pi >> 1]);
                    float av = (pi & 1) ? v2.y : v2.x;
                    float hval = av + s_eli[iloc*128 + tx*8 + hi] + s_erj[j*128 + tx*8 + hi];
                    rv[hi] = fmaxf(hval, 0.0f);
                }
                if (head == 0){
                    float ep = 0.0f;
                    #pragma unroll
                    for (int hi = 0; hi < 8; hi++) ep = fmaf(rv[hi], s_w2e[tx*8 + hi], ep);
                    #pragma unroll
                    for (int off = 8; off; off >>= 1) ep += __shfl_down_sync(0xffffffffu, ep, off, 16);
                    if (tx == 0) s_edge[p] += ep;
                } else {
                    #pragma unroll
                    for (int op = 0; op < 8; op++){
                        float po = 0.0f;
                        #pragma unroll
                        for (int hi = 0; hi < 8; hi++) po = fmaf(rv[hi], s_w2o[(tx*8+hi)*8 + op], po);
                        #pragma unroll
                        for (int off = 8; off; off >>= 1) po += __shfl_down_sync(0xffffffffu, po, off, 16);
                        if (tx == 0) s_op[p*8 + op] += po;
                    }
                }
            }
            __syncthreads();
        }

        // ---- write outputs for this head ----
        if (head == 0){
            if (t < 128){
                int p = t;
                int ig = i0 + (p >> 4), jg = j0 + (p & 15);
                float v = s_edge[p] + eh_b2[0];
                if (ig == jg) v = -8.0f;
                out[EDGE_OFF + b*NN*NN + ig*NN + jg] = v;
            }
        } else {
            for (int idx = t; idx < 1024; idx += 256){
                int p = idx >> 3, op = idx & 7;
                int ig = i0 + (p >> 4), jg = j0 + (p & 15);
                out[OP_OFF + (b*NN*NN + ig*NN + jg)*NOPS + op] = s_op[idx] + oh_b2[op];
            }
        }
        __syncthreads();
    }
}

// ---------------------------------------------------------------------------
// Launch
// ---------------------------------------------------------------------------
extern "C" void kernel_launch(void* const* d_in, const int* in_sizes, int n_in,
                              void* d_out, int out_size)
{
    const float* obs    = (const float*)d_in[0];
    const float* latent = (const float*)d_in[1];
    const float* query  = (const float*)d_in[2];
    const float* enc_w1 = (const float*)d_in[3];
    const float* enc_b1 = (const float*)d_in[4];
    const float* enc_w2 = (const float*)d_in[5];
    const float* enc_b2 = (const float*)d_in[6];
    const float* upd_w  = (const float*)d_in[7];
    const float* upd_b  = (const float*)d_in[8];
    const float* gru_wi = (const float*)d_in[9];
    const float* gru_bi = (const float*)d_in[10];
    const float* gru_wh = (const float*)d_in[11];
    const float* gru_bh = (const float*)d_in[12];
    const float* eh_w1  = (const float*)d_in[13];
    const float* eh_b1  = (const float*)d_in[14];
    const float* eh_w2  = (const float*)d_in[15];
    const float* eh_b2  = (const float*)d_in[16];
    const float* oh_w1  = (const float*)d_in[17];
    const float* oh_b1  = (const float*)d_in[18];
    const float* oh_w2  = (const float*)d_in[19];
    const float* oh_b2  = (const float*)d_in[20];
    const float* q_w    = (const float*)d_in[21];
    const float* q_b    = (const float*)d_in[22];
    const float* nh_w1  = (const float*)d_in[23];
    const float* nh_b1  = (const float*)d_in[24];
    const float* nh_w2  = (const float*)d_in[25];
    const float* nh_b2  = (const float*)d_in[26];

    float* out = (float*)d_out;

    nodeKernel<<<128, 256>>>(obs, latent, query,
                             enc_w1, enc_b1, enc_w2, enc_b2,
                             upd_w, upd_b,
                             gru_wi, gru_bi, gru_wh, gru_bh,
                             q_w, q_b, nh_w1, nh_b1, nh_w2, nh_b2,
                             out + NEXT_OFF);

    elKernel<<<dim3(64, 4), 256>>>(eh_w1, eh_b1, oh_w1, oh_b1);

    pairKernel<<<dim3(NN/TJ, NN/TI, BB), 256>>>(eh_w1, eh_w2, eh_b2,
                                                oh_w1, oh_w2, oh_b2,
                                                out);
}

// round 3
// speedup vs baseline: 2.6222x; 2.6222x over previous
#include <cuda_runtime.h>
#include <cuda_bf16.h>
#include <math.h>
#include <stdint.h>

// ---------------------------------------------------------------------------
// Problem constants
// ---------------------------------------------------------------------------
#define BB   4
#define NN   256
#define OBS  64
#define QDIM 32
#define HH   256
#define DD   128
#define NOPS 8
#define QE   64
#define BN   (BB*NN)          // 1024 rows

#define EDGE_OFF 0
#define OP_OFF   (BB*NN*NN)                 // 262144
#define NEXT_OFF (OP_OFF + BB*NN*NN*NOPS)   // 2359296

// ---------------------------------------------------------------------------
// Device scratch
// ---------------------------------------------------------------------------
__device__ float g_lat[BN*DD];
__device__ float g_EL[BN*HH];
__device__ float g_ER[BN*HH];
__device__ float g_OL[BN*HH];
__device__ float g_OR[BN*HH];
// packed bf16 hi/lo pair-head weights: [s(4)][part(2)][n(128)][k(128)]
__device__ __nv_bfloat16 g_Bpk[4*2*128*128];

__device__ __forceinline__ float sigf(float x){ return 1.0f/(1.0f+expf(-x)); }

__device__ __forceinline__ unsigned long long splat2(float x){
    unsigned long long r; unsigned int u = __float_as_uint(x);
    asm("mov.b64 %0, {%1, %1};" : "=l"(r) : "r"(u));
    return r;
}
__device__ __forceinline__ unsigned long long fma2(unsigned long long a,
                                                   unsigned long long b,
                                                   unsigned long long c){
    unsigned long long d;
    asm("fma.rn.f32x2 %0, %1, %2, %3;" : "=l"(d) : "l"(a), "l"(b), "l"(c));
    return d;
}

__device__ __forceinline__ uint32_t smem_u32(const void* p){
    uint32_t a;
    asm("{ .reg .u64 t; cvta.to.shared.u64 t, %1; cvt.u32.u64 %0, t; }"
        : "=r"(a) : "l"(p));
    return a;
}

__device__ __forceinline__ void ldsm4(uint32_t& r0, uint32_t& r1, uint32_t& r2,
                                      uint32_t& r3, uint32_t addr){
    asm volatile("ldmatrix.sync.aligned.m8n8.x4.shared.b16 {%0,%1,%2,%3}, [%4];"
                 : "=r"(r0), "=r"(r1), "=r"(r2), "=r"(r3) : "r"(addr));
}
__device__ __forceinline__ void mma16816(float* d, uint32_t a0, uint32_t a1,
                                         uint32_t a2, uint32_t a3,
                                         uint32_t b0, uint32_t b1){
    asm volatile(
        "mma.sync.aligned.m16n8k16.row.col.f32.bf16.bf16.f32 "
        "{%0,%1,%2,%3}, {%4,%5,%6,%7}, {%8,%9}, {%0,%1,%2,%3};"
        : "+f"(d[0]), "+f"(d[1]), "+f"(d[2]), "+f"(d[3])
        : "r"(a0), "r"(a1), "r"(a2), "r"(a3), "r"(b0), "r"(b1));
}

// ---------------------------------------------------------------------------
// Kernel A: per-node pipeline. 4 rows/block, 256 blocks.
// ---------------------------------------------------------------------------
__global__ __launch_bounds__(256)
void nodeKernel(const float* __restrict__ obs, const float* __restrict__ latent,
                const float* __restrict__ query,
                const float* __restrict__ enc_w1, const float* __restrict__ enc_b1,
                const float* __restrict__ enc_w2, const float* __restrict__ enc_b2,
                const float* __restrict__ upd_w,  const float* __restrict__ upd_b,
                const float* __restrict__ gru_wi, const float* __restrict__ gru_bi,
                const float* __restrict__ gru_wh, const float* __restrict__ gru_bh,
                const float* __restrict__ q_w,    const float* __restrict__ q_b,
                const float* __restrict__ nh_w1,  const float* __restrict__ nh_b1,
                const float* __restrict__ nh_w2,  const float* __restrict__ nh_b2,
                float* __restrict__ out_next)
{
    __shared__ float s_obs[4*64];     // later reused as q_emb [4][64]
    __shared__ float s_h1 [4*256];    // later: [0:512)=upd, [512:1024)=lat
    __shared__ float s_emb[4*256];
    __shared__ float s_gi [4*384];    // later query tmp [4][32]
    __shared__ float s_gh [4*384];    // later nh hidden [4][256]

    const int t    = threadIdx.x;
    const int row0 = blockIdx.x * 4;

    s_obs[t] = obs[row0*64 + t];
    __syncthreads();

    // h1 = relu(obs @ enc_w1 + b1)
    {
        float acc[4];
        #pragma unroll
        for (int r=0;r<4;r++) acc[r] = enc_b1[t];
        #pragma unroll 4
        for (int k=0;k<64;k++){
            float w = enc_w1[k*256 + t];
            #pragma unroll
            for (int r=0;r<4;r++) acc[r] = fmaf(s_obs[r*64+k], w, acc[r]);
        }
        #pragma unroll
        for (int r=0;r<4;r++) s_h1[r*256+t] = fmaxf(acc[r], 0.0f);
    }
    __syncthreads();

    // node_emb = relu(h1 @ enc_w2 + b2)
    {
        float acc[4];
        #pragma unroll
        for (int r=0;r<4;r++) acc[r] = enc_b2[t];
        #pragma unroll 4
        for (int k=0;k<256;k++){
            float w = enc_w2[k*256 + t];
            #pragma unroll
            for (int r=0;r<4;r++) acc[r] = fmaf(s_h1[r*256+k], w, acc[r]);
        }
        __syncthreads();
        #pragma unroll
        for (int r=0;r<4;r++) s_emb[r*256+t] = fmaxf(acc[r], 0.0f);
    }
    __syncthreads();

    float* s_upd = s_h1;
    float* s_lat = s_h1 + 512;

    // upd = node_emb @ upd_w + b
    {
        const int o = t & 127;
        const int rbase = (t >> 7) * 2;
        float acc[2];
        #pragma unroll
        for (int rr=0;rr<2;rr++) acc[rr] = upd_b[o];
        #pragma unroll 4
        for (int k=0;k<256;k++){
            float w = upd_w[k*128 + o];
            #pragma unroll
            for (int rr=0;rr<2;rr++) acc[rr] = fmaf(s_emb[(rbase+rr)*256+k], w, acc[rr]);
        }
        #pragma unroll
        for (int rr=0;rr<2;rr++) s_upd[(rbase+rr)*128+o] = acc[rr];
    }
    for (int idx = t; idx < 512; idx += 256) s_lat[idx] = latent[row0*128 + idx];
    __syncthreads();

    // gi / gh
    for (int o = t; o < 384; o += 256){
        float ai[4], ah[4];
        #pragma unroll
        for (int r=0;r<4;r++){ ai[r] = gru_bi[o]; ah[r] = gru_bh[o]; }
        #pragma unroll 4
        for (int k=0;k<128;k++){
            float wi = gru_wi[k*384 + o];
            float wh = gru_wh[k*384 + o];
            #pragma unroll
            for (int r=0;r<4;r++){
                ai[r] = fmaf(s_upd[r*128+k], wi, ai[r]);
                ah[r] = fmaf(s_lat[r*128+k], wh, ah[r]);
            }
        }
        #pragma unroll
        for (int r=0;r<4;r++){ s_gi[r*384+o] = ai[r]; s_gh[r*384+o] = ah[r]; }
    }
    __syncthreads();

    // GRU elementwise
    for (int idx = t; idx < 512; idx += 256){
        int r = idx >> 7, d = idx & 127;
        float ir = s_gi[r*384 + d],  iz = s_gi[r*384 + 128 + d], inn = s_gi[r*384 + 256 + d];
        float hr = s_gh[r*384 + d],  hz = s_gh[r*384 + 128 + d], hn  = s_gh[r*384 + 256 + d];
        float rg = sigf(ir + hr);
        float zg = sigf(iz + hz);
        float nh = tanhf(inn + rg*hn);
        float lv = (1.0f - zg)*nh + zg*s_lat[idx];
        s_lat[idx] = lv;
        g_lat[row0*128 + idx] = lv;
    }
    __syncthreads();

    // q_emb = relu(query @ q_w + b)
    for (int idx = t; idx < 4*32; idx += 256) s_gi[idx] = query[row0*32 + idx];
    __syncthreads();
    {
        int r = t >> 6, o = t & 63;
        float acc = q_b[o];
        #pragma unroll
        for (int k=0;k<32;k++) acc = fmaf(s_gi[r*32+k], q_w[k*64+o], acc);
        s_obs[t] = fmaxf(acc, 0.0f);
    }
    __syncthreads();

    // nh hidden
    {
        float acc[4];
        #pragma unroll
        for (int r=0;r<4;r++) acc[r] = nh_b1[t];
        #pragma unroll 4
        for (int k=0;k<128;k++){
            float w = nh_w1[k*256 + t];
            #pragma unroll
            for (int r=0;r<4;r++) acc[r] = fmaf(s_lat[r*128+k], w, acc[r]);
        }
        #pragma unroll 4
        for (int k=0;k<256;k++){
            float w = nh_w1[(128+k)*256 + t];
            #pragma unroll
            for (int r=0;r<4;r++) acc[r] = fmaf(s_emb[r*256+k], w, acc[r]);
        }
        #pragma unroll 4
        for (int k=0;k<64;k++){
            float w = nh_w1[(384+k)*256 + t];
            #pragma unroll
            for (int r=0;r<4;r++) acc[r] = fmaf(s_obs[r*64+k], w, acc[r]);
        }
        #pragma unroll
        for (int r=0;r<4;r++) s_gh[r*256+t] = fmaxf(acc[r], 0.0f);
    }
    __syncthreads();

    // next_pred
    {
        const int w = t >> 5, l = t & 31;
        if (w < 4){
            float p = 0.0f;
            for (int o = l; o < 256; o += 32) p = fmaf(s_gh[w*256 + o], nh_w2[o], p);
            #pragma unroll
            for (int off = 16; off; off >>= 1) p += __shfl_down_sync(0xffffffffu, p, off);
            if (l == 0) out_next[row0 + w] = p + nh_b2[0];
        }
    }
}

// ---------------------------------------------------------------------------
// Kernel B: EL/ER/OL/OR = lat @ W_slice (+bias). grid (128,4).
// ---------------------------------------------------------------------------
__global__ __launch_bounds__(256)
void elKernel(const float* __restrict__ eh_w1, const float* __restrict__ eh_b1,
              const float* __restrict__ oh_w1, const float* __restrict__ oh_b1)
{
    __shared__ float s_lat[8*128];
    const int t = threadIdx.x;
    const int row0 = blockIdx.x * 8;
    const int m = blockIdx.y;

    const float* W; const float* bias = nullptr; float* dst;
    if (m == 0)      { W = eh_w1;            bias = eh_b1; dst = g_EL; }
    else if (m == 1) { W = eh_w1 + 128*256;                dst = g_ER; }
    else if (m == 2) { W = oh_w1;            bias = oh_b1; dst = g_OL; }
    else             { W = oh_w1 + 128*256;                dst = g_OR; }

    for (int idx = t; idx < 1024; idx += 256) s_lat[idx] = g_lat[row0*128 + idx];
    __syncthreads();

    float acc[8];
    float bv = bias ? bias[t] : 0.0f;
    #pragma unroll
    for (int r=0;r<8;r++) acc[r] = bv;
    #pragma unroll 4
    for (int k=0;k<128;k++){
        float w = W[k*256 + t];
        #pragma unroll
        for (int r=0;r<8;r++) acc[r] = fmaf(s_lat[r*128+k], w, acc[r]);
    }
    #pragma unroll
    for (int r=0;r<8;r++) dst[(row0+r)*256 + t] = acc[r];
}

// ---------------------------------------------------------------------------
// Kernel P: pre-split pair-head weights into bf16 hi/lo.
// g_Bpk[s][part][n][k] with s = head*2 + half; B[n][k] = W1[256+k][half*128+n]
// ---------------------------------------------------------------------------
__global__ __launch_bounds__(256)
void prepB(const float* __restrict__ eh_w1, const float* __restrict__ oh_w1)
{
    int gi0 = blockIdx.x * 1024 + threadIdx.x;
    #pragma unroll
    for (int i = 0; i < 4; i++){
        int gi = gi0 + i*256;            // 0..65535 over (s,n,k)
        int s   = gi >> 14;
        int rem = gi & 16383;
        int n   = rem >> 7;
        int k   = rem & 127;
        int head = s >> 1, half = s & 1;
        const float* w = head ? oh_w1 : eh_w1;
        float v = w[(256 + k)*256 + half*128 + n];
        __nv_bfloat16 hi = __float2bfloat16(v);
        float lo_f = v - __bfloat162float(hi);
        __nv_bfloat16 lo = __float2bfloat16(lo_f);
        g_Bpk[((s*2 + 0)*128 + n)*128 + k] = hi;
        g_Bpk[((s*2 + 1)*128 + n)*128 + k] = lo;
    }
}

// ---------------------------------------------------------------------------
// Kernel C: pair MLP via mma.sync bf16 (3-pass hi/lo), fused epilogue.
// Block: 8 i x 16 j = 128 pairs, 4 stages s=(head,half), N=128 per stage.
// ---------------------------------------------------------------------------
#define ASTRIDE 136                       // bf16 elems per row (272 B = 17*16B)
#define OFF_AH   0                        // 128*272 = 34816
#define OFF_AL   34816
#define OFF_BH   69632
#define OFF_BL   104448
#define OFF_ELI  139264                   // 8*132*4   = 4224
#define OFF_ERJ  143488                   // 16*132*4  = 8448
#define OFF_W2E  151936                   // 1024
#define OFF_W2O  152960                   // 8192
#define PAIR_SMEM 161152

__global__ __launch_bounds__(256, 1)
void pairKernel(const float* __restrict__ eh_w2, const float* __restrict__ eh_b2,
                const float* __restrict__ oh_w2, const float* __restrict__ oh_b2,
                float* __restrict__ out)
{
    extern __shared__ __align__(16) char sm[];
    float* s_li  = (float*)(sm + OFF_ELI);   // prologue staging [8][128]
    float* s_lj  = (float*)(sm + OFF_ERJ);   // prologue staging [16][128]
    float* s_eli = (float*)(sm + OFF_ELI);   // per-stage [8][132]
    float* s_erj = (float*)(sm + OFF_ERJ);   // per-stage [16][132]
    float* s_w2e = (float*)(sm + OFF_W2E);   // [256]
    float* s_w2o = (float*)(sm + OFF_W2O);   // [256][8]

    const uint32_t smb = smem_u32(sm);
    const int t    = threadIdx.x;
    const int wid  = t >> 5;
    const int lane = t & 31;
    const int b    = blockIdx.z;
    const int i0   = blockIdx.y * 8;
    const int j0   = blockIdx.x * 16;
    const int base = b * NN;

    // ---- prologue: stage lat rows + w2 tables ----
    for (int idx = t; idx < 1024; idx += 256) s_li[idx] = g_lat[(base + i0)*128 + idx];
    for (int idx = t; idx < 2048; idx += 256) s_lj[idx] = g_lat[(base + j0)*128 + idx];
    if (t < 256) s_w2e[t] = eh_w2[t];
    for (int idx = t; idx < 2048; idx += 256) s_w2o[idx] = oh_w2[idx];
    __syncthreads();

    // ---- build A = |li - lj| as bf16 hi/lo, padded row stride 136 ----
    for (int c = t; c < 2048; c += 256){
        int p = c >> 4, kg = c & 15;
        int il = p >> 4, jl = p & 15;
        const float4* li4 = (const float4*)&s_li[il*128 + kg*8];
        const float4* lj4 = (const float4*)&s_lj[jl*128 + kg*8];
        float4 x0 = li4[0], x1 = li4[1], y0 = lj4[0], y1 = lj4[1];
        float a[8] = { fabsf(x0.x-y0.x), fabsf(x0.y-y0.y), fabsf(x0.z-y0.z), fabsf(x0.w-y0.w),
                       fabsf(x1.x-y1.x), fabsf(x1.y-y1.y), fabsf(x1.z-y1.z), fabsf(x1.w-y1.w) };
        uint32_t hp[4], lp[4];
        #pragma unroll
        for (int q = 0; q < 4; q++){
            __nv_bfloat16 h0 = __float2bfloat16(a[2*q]);
            __nv_bfloat16 h1 = __float2bfloat16(a[2*q+1]);
            __nv_bfloat16 l0 = __float2bfloat16(a[2*q]   - __bfloat162float(h0));
            __nv_bfloat16 l1 = __float2bfloat16(a[2*q+1] - __bfloat162float(h1));
            hp[q] = (uint32_t)__bfloat16_as_ushort(h0) | ((uint32_t)__bfloat16_as_ushort(h1) << 16);
            lp[q] = (uint32_t)__bfloat16_as_ushort(l0) | ((uint32_t)__bfloat16_as_ushort(l1) << 16);
        }
        uint32_t boff = (uint32_t)(p*(ASTRIDE*2) + kg*16);
        *(uint4*)(sm + OFF_AH + boff) = make_uint4(hp[0],hp[1],hp[2],hp[3]);
        *(uint4*)(sm + OFF_AL + boff) = make_uint4(lp[0],lp[1],lp[2],lp[3]);
    }
    __syncthreads();

    // per-thread ldmatrix addressing
    const uint32_t aoff = (uint32_t)((wid*16 + (lane&7) + ((lane>>3)&1)*8) * (ASTRIDE*2)
                                     + ((lane>>4)&1)*16);
    const uint32_t boff = (uint32_t)(((lane&7) + ((lane>>4)&1)*8) * (ASTRIDE*2)
                                     + ((lane>>3)&1)*16);

    // epilogue geometry
    const int q     = lane >> 2;          // 0..7
    const int iloc  = wid;                // all 16 rows of this warp share i
    const int jlo   = q, jhi = q + 8;
    const int ig    = i0 + iloc;
    const int jglo  = j0 + jlo, jghi = j0 + jhi;

    float eacc[2] = {0.0f, 0.0f};
    unsigned long long oacc[2][4];
    #pragma unroll
    for (int rh=0;rh<2;rh++)
        #pragma unroll
        for (int v=0;v<4;v++) oacc[rh][v] = 0ull;

    for (int s = 0; s < 4; s++){
        const int head = s >> 1, half = s & 1;

        // ---- load B (hi+lo) for this stage, padded layout ----
        const __nv_bfloat16* srcB = &g_Bpk[(size_t)(s*2)*16384];
        for (int idx = t; idx < 4096; idx += 256){
            int part = idx >> 11, rem = idx & 2047;
            int n = rem >> 4, kg = rem & 15;
            uint4 v = *(const uint4*)(srcB + part*16384 + n*128 + kg*8);
            *(uint4*)(sm + (part ? OFF_BL : OFF_BH) + n*(ASTRIDE*2) + kg*16) = v;
        }
        // ---- load EL/ER slices for this (head,half) ----
        const float* gl = head ? g_OL : g_EL;
        const float* gr = head ? g_OR : g_ER;
        for (int idx = t; idx < 1024; idx += 256){
            int r = idx >> 7, c = idx & 127;
            s_eli[r*132 + c] = gl[(base + i0 + r)*256 + half*128 + c];
        }
        for (int idx = t; idx < 2048; idx += 256){
            int r = idx >> 7, c = idx & 127;
            s_erj[r*132 + c] = gr[(base + j0 + r)*256 + half*128 + c];
        }
        __syncthreads();

        // ---- 3-pass MMA: AhBh + AlBh + AhBl ----
        float acc[16][4];
        #pragma unroll
        for (int nt=0;nt<16;nt++)
            #pragma unroll
            for (int v=0;v<4;v++) acc[nt][v] = 0.0f;

        #pragma unroll
        for (int pass = 0; pass < 3; pass++){
            const uint32_t aBase = smb + (pass == 1 ? OFF_AL : OFF_AH) + aoff;
            const uint32_t bBase = smb + (pass == 2 ? OFF_BL : OFF_BH) + boff;
            #pragma unroll
            for (int ks = 0; ks < 8; ks++){
                uint32_t a0,a1,a2,a3;
                ldsm4(a0,a1,a2,a3, aBase + ks*32);
                #pragma unroll
                for (int ntp = 0; ntp < 8; ntp++){
                    uint32_t b0,b1,b2,b3;
                    ldsm4(b0,b1,b2,b3, bBase + ntp*(16*ASTRIDE*2) + ks*32);
                    mma16816(acc[2*ntp],   a0,a1,a2,a3, b0,b1);
                    mma16816(acc[2*ntp+1], a0,a1,a2,a3, b2,b3);
                }
            }
        }

        // ---- epilogue: relu(acc + EL + ER), fold layer-2 ----
        #pragma unroll
        for (int nt = 0; nt < 16; nt++){
            const int c0 = nt*8 + 2*(lane & 3);
            const float el0 = s_eli[iloc*132 + c0],     el1 = s_eli[iloc*132 + c0 + 1];
            const float rl0 = s_erj[jlo*132 + c0],      rl1 = s_erj[jlo*132 + c0 + 1];
            const float rh0 = s_erj[jhi*132 + c0],      rh1 = s_erj[jhi*132 + c0 + 1];
            float h00 = fmaxf(acc[nt][0] + el0 + rl0, 0.0f);
            float h01 = fmaxf(acc[nt][1] + el1 + rl1, 0.0f);
            float h10 = fmaxf(acc[nt][2] + el0 + rh0, 0.0f);
            float h11 = fmaxf(acc[nt][3] + el1 + rh1, 0.0f);
            if (head == 0){
                float w0 = s_w2e[half*128 + c0], w1 = s_w2e[half*128 + c0 + 1];
                eacc[0] = fmaf(h00, w0, fmaf(h01, w1, eacc[0]));
                eacc[1] = fmaf(h10, w0, fmaf(h11, w1, eacc[1]));
            } else {
                const ulonglong2* wp0 = (const ulonglong2*)&s_w2o[(half*128 + c0)*8];
                const ulonglong2* wp1 = (const ulonglong2*)&s_w2o[(half*128 + c0 + 1)*8];
                ulonglong2 wa = wp0[0], wb = wp0[1], wc = wp1[0], wd = wp1[1];
                unsigned long long v00 = splat2(h00), v01 = splat2(h01);
                unsigned long long v10 = splat2(h10), v11 = splat2(h11);
                oacc[0][0] = fma2(v00, wa.x, oacc[0][0]); oacc[0][1] = fma2(v00, wa.y, oacc[0][1]);
                oacc[0][2] = fma2(v00, wb.x, oacc[0][2]); oacc[0][3] = fma2(v00, wb.y, oacc[0][3]);
                oacc[0][0] = fma2(v01, wc.x, oacc[0][0]); oacc[0][1] = fma2(v01, wc.y, oacc[0][1]);
                oacc[0][2] = fma2(v01, wd.x, oacc[0][2]); oacc[0][3] = fma2(v01, wd.y, oacc[0][3]);
                oacc[1][0] = fma2(v10, wa.x, oacc[1][0]); oacc[1][1] = fma2(v10, wa.y, oacc[1][1]);
                oacc[1][2] = fma2(v10, wb.x, oacc[1][2]); oacc[1][3] = fma2(v10, wb.y, oacc[1][3]);
                oacc[1][0] = fma2(v11, wc.x, oacc[1][0]); oacc[1][1] = fma2(v11, wc.y, oacc[1][1]);
                oacc[1][2] = fma2(v11, wd.x, oacc[1][2]); oacc[1][3] = fma2(v11, wd.y, oacc[1][3]);
            }
        }

        if (s == 1){
            // reduce edge across quad, write
            #pragma unroll
            for (int rh = 0; rh < 2; rh++){
                float v = eacc[rh];
                v += __shfl_xor_sync(0xffffffffu, v, 1);
                v += __shfl_xor_sync(0xffffffffu, v, 2);
                eacc[rh] = v;
            }
            if ((lane & 3) == 0){
                float b2 = eh_b2[0];
                float v0 = eacc[0] + b2;
                float v1 = eacc[1] + b2;
                if (ig == jglo) v0 = -8.0f;
                if (ig == jghi) v1 = -8.0f;
                out[EDGE_OFF + b*NN*NN + ig*NN + jglo] = v0;
                out[EDGE_OFF + b*NN*NN + ig*NN + jghi] = v1;
            }
        }
        if (s == 3){
            #pragma unroll
            for (int rh = 0; rh < 2; rh++){
                float ov[8];
                #pragma unroll
                for (int v = 0; v < 4; v++){
                    float2 f = *reinterpret_cast<float2*>(&oacc[rh][v]);
                    float x = f.x, y = f.y;
                    x += __shfl_xor_sync(0xffffffffu, x, 1);
                    x += __shfl_xor_sync(0xffffffffu, x, 2);
                    y += __shfl_xor_sync(0xffffffffu, y, 1);
                    y += __shfl_xor_sync(0xffffffffu, y, 2);
                    ov[2*v] = x; ov[2*v+1] = y;
                }
                if ((lane & 3) == 0){
                    int jg = rh ? jghi : jglo;
                    float4* dst = (float4*)&out[OP_OFF + ((size_t)(b*NN*NN + ig*NN + jg))*NOPS];
                    dst[0] = make_float4(ov[0]+oh_b2[0], ov[1]+oh_b2[1], ov[2]+oh_b2[2], ov[3]+oh_b2[3]);
                    dst[1] = make_float4(ov[4]+oh_b2[4], ov[5]+oh_b2[5], ov[6]+oh_b2[6], ov[7]+oh_b2[7]);
                }
            }
        }
        __syncthreads();   // B/eli/erj reuse next stage
    }
}

// ---------------------------------------------------------------------------
// Launch
// ---------------------------------------------------------------------------
extern "C" void kernel_launch(void* const* d_in, const int* in_sizes, int n_in,
                              void* d_out, int out_size)
{
    const float* obs    = (const float*)d_in[0];
    const float* latent = (const float*)d_in[1];
    const float* query  = (const float*)d_in[2];
    const float* enc_w1 = (const float*)d_in[3];
    const float* enc_b1 = (const float*)d_in[4];
    const float* enc_w2 = (const float*)d_in[5];
    const float* enc_b2 = (const float*)d_in[6];
    const float* upd_w  = (const float*)d_in[7];
    const float* upd_b  = (const float*)d_in[8];
    const float* gru_wi = (const float*)d_in[9];
    const float* gru_bi = (const float*)d_in[10];
    const float* gru_wh = (const float*)d_in[11];
    const float* gru_bh = (const float*)d_in[12];
    const float* eh_w1  = (const float*)d_in[13];
    const float* eh_b1  = (const float*)d_in[14];
    const float* eh_w2  = (const float*)d_in[15];
    const float* eh_b2  = (const float*)d_in[16];
    const float* oh_w1  = (const float*)d_in[17];
    const float* oh_b1  = (const float*)d_in[18];
    const float* oh_w2  = (const float*)d_in[19];
    const float* oh_b2  = (const float*)d_in[20];
    const float* q_w    = (const float*)d_in[21];
    const float* q_b    = (const float*)d_in[22];
    const float* nh_w1  = (const float*)d_in[23];
    const float* nh_b1  = (const float*)d_in[24];
    const float* nh_w2  = (const float*)d_in[25];
    const float* nh_b2  = (const float*)d_in[26];

    float* out = (float*)d_out;

    static bool inited = false;
    if (!inited){
        cudaFuncSetAttribute(pairKernel, cudaFuncAttributeMaxDynamicSharedMemorySize, PAIR_SMEM);
        inited = true;
    }

    prepB<<<64, 256>>>(eh_w1, oh_w1);

    nodeKernel<<<256, 256>>>(obs, latent, query,
                             enc_w1, enc_b1, enc_w2, enc_b2,
                             upd_w, upd_b,
                             gru_wi, gru_bi, gru_wh, gru_bh,
                             q_w, q_b, nh_w1, nh_b1, nh_w2, nh_b2,
                             out + NEXT_OFF);

    elKernel<<<dim3(128, 4), 256>>>(eh_w1, eh_b1, oh_w1, oh_b1);

    pairKernel<<<dim3(16, 32, 4), 256, PAIR_SMEM>>>(eh_w2, eh_b2, oh_w2, oh_b2, out);
}

// round 4
// speedup vs baseline: 2.8690x; 1.0941x over previous
#include <cuda_runtime.h>
#include <cuda_bf16.h>
#include <cuda_fp16.h>
#include <math.h>
#include <stdint.h>

// ---------------------------------------------------------------------------
// Problem constants
// ---------------------------------------------------------------------------
#define BB   4
#define NN   256
#define OBS  64
#define QDIM 32
#define HH   256
#define DD   128
#define NOPS 8
#define QE   64
#define BN   (BB*NN)          // 1024 rows

#define EDGE_OFF 0
#define OP_OFF   (BB*NN*NN)                 // 262144
#define NEXT_OFF (OP_OFF + BB*NN*NN*NOPS)   // 2359296

// ---------------------------------------------------------------------------
// Device scratch
// ---------------------------------------------------------------------------
__device__ float g_lat[BN*DD];
__device__ float g_EL[BN*HH];
__device__ float g_ER[BN*HH];
__device__ float g_OL[BN*HH];
__device__ float g_OR[BN*HH];
// fp16 pair-head weights: [s(4)][n(128)][k(128)], s = head*2 + half
__device__ __half g_Bfp[4*128*128];

__device__ __forceinline__ float sigf(float x){ return 1.0f/(1.0f+expf(-x)); }

__device__ __forceinline__ unsigned long long splat2(float x){
    unsigned long long r; unsigned int u = __float_as_uint(x);
    asm("mov.b64 %0, {%1, %1};" : "=l"(r) : "r"(u));
    return r;
}
__device__ __forceinline__ unsigned long long fma2(unsigned long long a,
                                                   unsigned long long b,
                                                   unsigned long long c){
    unsigned long long d;
    asm("fma.rn.f32x2 %0, %1, %2, %3;" : "=l"(d) : "l"(a), "l"(b), "l"(c));
    return d;
}

__device__ __forceinline__ uint32_t smem_u32(const void* p){
    uint32_t a;
    asm("{ .reg .u64 t; cvta.to.shared.u64 t, %1; cvt.u32.u64 %0, t; }"
        : "=r"(a) : "l"(p));
    return a;
}

__device__ __forceinline__ void ldsm4(uint32_t& r0, uint32_t& r1, uint32_t& r2,
                                      uint32_t& r3, uint32_t addr){
    asm volatile("ldmatrix.sync.aligned.m8n8.x4.shared.b16 {%0,%1,%2,%3}, [%4];"
                 : "=r"(r0), "=r"(r1), "=r"(r2), "=r"(r3) : "r"(addr));
}
__device__ __forceinline__ void mma16816(float* d, uint32_t a0, uint32_t a1,
                                         uint32_t a2, uint32_t a3,
                                         uint32_t b0, uint32_t b1){
    asm volatile(
        "mma.sync.aligned.m16n8k16.row.col.f32.f16.f16.f32 "
        "{%0,%1,%2,%3}, {%4,%5,%6,%7}, {%8,%9}, {%0,%1,%2,%3};"
        : "+f"(d[0]), "+f"(d[1]), "+f"(d[2]), "+f"(d[3])
        : "r"(a0), "r"(a1), "r"(a2), "r"(a3), "r"(b0), "r"(b1));
}

// ---------------------------------------------------------------------------
// Kernel A: per-node pipeline. 4 rows/block, 256 blocks.
// ---------------------------------------------------------------------------
__global__ __launch_bounds__(256)
void nodeKernel(const float* __restrict__ obs, const float* __restrict__ latent,
                const float* __restrict__ query,
                const float* __restrict__ enc_w1, const float* __restrict__ enc_b1,
                const float* __restrict__ enc_w2, const float* __restrict__ enc_b2,
                const float* __restrict__ upd_w,  const float* __restrict__ upd_b,
                const float* __restrict__ gru_wi, const float* __restrict__ gru_bi,
                const float* __restrict__ gru_wh, const float* __restrict__ gru_bh,
                const float* __restrict__ q_w,    const float* __restrict__ q_b,
                const float* __restrict__ nh_w1,  const float* __restrict__ nh_b1,
                const float* __restrict__ nh_w2,  const float* __restrict__ nh_b2,
                float* __restrict__ out_next)
{
    __shared__ float s_obs[4*64];
    __shared__ float s_h1 [4*256];
    __shared__ float s_emb[4*256];
    __shared__ float s_gi [4*384];
    __shared__ float s_gh [4*384];

    const int t    = threadIdx.x;
    const int row0 = blockIdx.x * 4;

    s_obs[t] = obs[row0*64 + t];
    __syncthreads();

    {
        float acc[4];
        #pragma unroll
        for (int r=0;r<4;r++) acc[r] = enc_b1[t];
        #pragma unroll 4
        for (int k=0;k<64;k++){
            float w = enc_w1[k*256 + t];
            #pragma unroll
            for (int r=0;r<4;r++) acc[r] = fmaf(s_obs[r*64+k], w, acc[r]);
        }
        #pragma unroll
        for (int r=0;r<4;r++) s_h1[r*256+t] = fmaxf(acc[r], 0.0f);
    }
    __syncthreads();

    {
        float acc[4];
        #pragma unroll
        for (int r=0;r<4;r++) acc[r] = enc_b2[t];
        #pragma unroll 4
        for (int k=0;k<256;k++){
            float w = enc_w2[k*256 + t];
            #pragma unroll
            for (int r=0;r<4;r++) acc[r] = fmaf(s_h1[r*256+k], w, acc[r]);
        }
        __syncthreads();
        #pragma unroll
        for (int r=0;r<4;r++) s_emb[r*256+t] = fmaxf(acc[r], 0.0f);
    }
    __syncthreads();

    float* s_upd = s_h1;
    float* s_lat = s_h1 + 512;

    {
        const int o = t & 127;
        const int rbase = (t >> 7) * 2;
        float acc[2];
        #pragma unroll
        for (int rr=0;rr<2;rr++) acc[rr] = upd_b[o];
        #pragma unroll 4
        for (int k=0;k<256;k++){
            float w = upd_w[k*128 + o];
            #pragma unroll
            for (int rr=0;rr<2;rr++) acc[rr] = fmaf(s_emb[(rbase+rr)*256+k], w, acc[rr]);
        }
        #pragma unroll
        for (int rr=0;rr<2;rr++) s_upd[(rbase+rr)*128+o] = acc[rr];
    }
    for (int idx = t; idx < 512; idx += 256) s_lat[idx] = latent[row0*128 + idx];
    __syncthreads();

    for (int o = t; o < 384; o += 256){
        float ai[4], ah[4];
        #pragma unroll
        for (int r=0;r<4;r++){ ai[r] = gru_bi[o]; ah[r] = gru_bh[o]; }
        #pragma unroll 4
        for (int k=0;k<128;k++){
            float wi = gru_wi[k*384 + o];
            float wh = gru_wh[k*384 + o];
            #pragma unroll
            for (int r=0;r<4;r++){
                ai[r] = fmaf(s_upd[r*128+k], wi, ai[r]);
                ah[r] = fmaf(s_lat[r*128+k], wh, ah[r]);
            }
        }
        #pragma unroll
        for (int r=0;r<4;r++){ s_gi[r*384+o] = ai[r]; s_gh[r*384+o] = ah[r]; }
    }
    __syncthreads();

    for (int idx = t; idx < 512; idx += 256){
        int r = idx >> 7, d = idx & 127;
        float ir = s_gi[r*384 + d],  iz = s_gi[r*384 + 128 + d], inn = s_gi[r*384 + 256 + d];
        float hr = s_gh[r*384 + d],  hz = s_gh[r*384 + 128 + d], hn  = s_gh[r*384 + 256 + d];
        float rg = sigf(ir + hr);
        float zg = sigf(iz + hz);
        float nh = tanhf(inn + rg*hn);
        float lv = (1.0f - zg)*nh + zg*s_lat[idx];
        s_lat[idx] = lv;
        g_lat[row0*128 + idx] = lv;
    }
    __syncthreads();

    for (int idx = t; idx < 4*32; idx += 256) s_gi[idx] = query[row0*32 + idx];
    __syncthreads();
    {
        int r = t >> 6, o = t & 63;
        float acc = q_b[o];
        #pragma unroll
        for (int k=0;k<32;k++) acc = fmaf(s_gi[r*32+k], q_w[k*64+o], acc);
        s_obs[t] = fmaxf(acc, 0.0f);
    }
    __syncthreads();

    {
        float acc[4];
        #pragma unroll
        for (int r=0;r<4;r++) acc[r] = nh_b1[t];
        #pragma unroll 4
        for (int k=0;k<128;k++){
            float w = nh_w1[k*256 + t];
            #pragma unroll
            for (int r=0;r<4;r++) acc[r] = fmaf(s_lat[r*128+k], w, acc[r]);
        }
        #pragma unroll 4
        for (int k=0;k<256;k++){
            float w = nh_w1[(128+k)*256 + t];
            #pragma unroll
            for (int r=0;r<4;r++) acc[r] = fmaf(s_emb[r*256+k], w, acc[r]);
        }
        #pragma unroll 4
        for (int k=0;k<64;k++){
            float w = nh_w1[(384+k)*256 + t];
            #pragma unroll
            for (int r=0;r<4;r++) acc[r] = fmaf(s_obs[r*64+k], w, acc[r]);
        }
        #pragma unroll
        for (int r=0;r<4;r++) s_gh[r*256+t] = fmaxf(acc[r], 0.0f);
    }
    __syncthreads();

    {
        const int w = t >> 5, l = t & 31;
        if (w < 4){
            float p = 0.0f;
            for (int o = l; o < 256; o += 32) p = fmaf(s_gh[w*256 + o], nh_w2[o], p);
            #pragma unroll
            for (int off = 16; off; off >>= 1) p += __shfl_down_sync(0xffffffffu, p, off);
            if (l == 0) out_next[row0 + w] = p + nh_b2[0];
        }
    }
}

// ---------------------------------------------------------------------------
// Kernel B: EL/ER/OL/OR = lat @ W_slice (+bias). grid (128,4).
// ---------------------------------------------------------------------------
__global__ __launch_bounds__(256)
void elKernel(const float* __restrict__ eh_w1, const float* __restrict__ eh_b1,
              const float* __restrict__ oh_w1, const float* __restrict__ oh_b1)
{
    __shared__ float s_lat[8*128];
    const int t = threadIdx.x;
    const int row0 = blockIdx.x * 8;
    const int m = blockIdx.y;

    const float* W; const float* bias = nullptr; float* dst;
    if (m == 0)      { W = eh_w1;            bias = eh_b1; dst = g_EL; }
    else if (m == 1) { W = eh_w1 + 128*256;                dst = g_ER; }
    else if (m == 2) { W = oh_w1;            bias = oh_b1; dst = g_OL; }
    else             { W = oh_w1 + 128*256;                dst = g_OR; }

    for (int idx = t; idx < 1024; idx += 256) s_lat[idx] = g_lat[row0*128 + idx];
    __syncthreads();

    float acc[8];
    float bv = bias ? bias[t] : 0.0f;
    #pragma unroll
    for (int r=0;r<8;r++) acc[r] = bv;
    #pragma unroll 4
    for (int k=0;k<128;k++){
        float w = W[k*256 + t];
        #pragma unroll
        for (int r=0;r<8;r++) acc[r] = fmaf(s_lat[r*128+k], w, acc[r]);
    }
    #pragma unroll
    for (int r=0;r<8;r++) dst[(row0+r)*256 + t] = acc[r];
}

// ---------------------------------------------------------------------------
// Kernel P: pre-convert pair-head |diff| weights to fp16.
// g_Bfp[s][n][k], s = head*2 + half; B[n][k] = W1[256+k][half*128+n]
// ---------------------------------------------------------------------------
__global__ __launch_bounds__(256)
void prepB(const float* __restrict__ eh_w1, const float* __restrict__ oh_w1)
{
    int gi0 = blockIdx.x * 1024 + threadIdx.x;
    #pragma unroll
    for (int i = 0; i < 4; i++){
        int gi = gi0 + i*256;            // 0..65535 over (s,n,k)
        int s   = gi >> 14;
        int rem = gi & 16383;
        int n   = rem >> 7;
        int k   = rem & 127;
        int head = s >> 1, half = s & 1;
        const float* w = head ? oh_w1 : eh_w1;
        g_Bfp[(s*128 + n)*128 + k] = __float2half(w[(256 + k)*256 + half*128 + n]);
    }
}

// ---------------------------------------------------------------------------
// Kernel C: pair MLP via mma.sync fp16 hi/lo (2-pass), fused epilogue.
// Block: 16 i x 16 j = 256 pairs, 512 threads (16 warps), 4 stages.
// Warp w handles i = i0 + w (A rows p = w*16 + j), N=128 in 2 chunks of 64.
// XOR-swizzled smem (chunk ^= row&7) for conflict-free ldmatrix.
// ---------------------------------------------------------------------------
#define OFF_AH   0                         // 256 rows * 256B = 65536
#define OFF_AL   65536                     // 65536
#define OFF_B    131072                    // 128 rows * 256B = 32768
#define OFF_ELI  163840                    // 16*130*4 = 8320
#define OFF_ERJ  172160                    // 8320
#define OFF_W2E  180480                    // 512
#define OFF_W2O  180992                    // 4096
#define PAIR_SMEM 185088

__global__ __launch_bounds__(512, 1)
void pairKernel(const float* __restrict__ eh_w2, const float* __restrict__ eh_b2,
                const float* __restrict__ oh_w2, const float* __restrict__ oh_b2,
                float* __restrict__ out)
{
    extern __shared__ __align__(16) char sm[];
    float* s_li  = (float*)(sm + OFF_ELI);   // prologue staging [16][128]
    float* s_lj  = (float*)(sm + OFF_ERJ);   // prologue staging [16][128]
    float* s_eli = (float*)(sm + OFF_ELI);   // per-stage [16][130]
    float* s_erj = (float*)(sm + OFF_ERJ);   // per-stage [16][130]
    float* s_w2e = (float*)(sm + OFF_W2E);   // per-stage [128]
    float* s_w2o = (float*)(sm + OFF_W2O);   // per-stage [128][8]

    const uint32_t smb = smem_u32(sm);
    const int t    = threadIdx.x;
    const int wid  = t >> 5;
    const int lane = t & 31;
    const int b    = blockIdx.z;
    const int i0   = blockIdx.y * 16;
    const int j0   = blockIdx.x * 16;
    const int base = b * NN;

    // ---- prologue: stage lat rows ----
    for (int idx = t; idx < 2048; idx += 512) s_li[idx] = g_lat[(base + i0)*128 + idx];
    for (int idx = t; idx < 2048; idx += 512) s_lj[idx] = g_lat[(base + j0)*128 + idx];
    __syncthreads();

    // ---- build A = |li - lj| as fp16 hi/lo, XOR-swizzled 256B rows ----
    for (int c = t; c < 4096; c += 512){
        int p = c >> 4, kg = c & 15;          // p: pair row, kg: 16B chunk (8 elems)
        int il = p >> 4, jl = p & 15;
        const float4* li4 = (const float4*)&s_li[il*128 + kg*8];
        const float4* lj4 = (const float4*)&s_lj[jl*128 + kg*8];
        float4 x0 = li4[0], x1 = li4[1], y0 = lj4[0], y1 = lj4[1];
        float a[8] = { fabsf(x0.x-y0.x), fabsf(x0.y-y0.y), fabsf(x0.z-y0.z), fabsf(x0.w-y0.w),
                       fabsf(x1.x-y1.x), fabsf(x1.y-y1.y), fabsf(x1.z-y1.z), fabsf(x1.w-y1.w) };
        uint32_t hp[4], lp[4];
        #pragma unroll
        for (int q = 0; q < 4; q++){
            __half h0 = __float2half(a[2*q]);
            __half h1 = __float2half(a[2*q+1]);
            __half l0 = __float2half(a[2*q]   - __half2float(h0));
            __half l1 = __float2half(a[2*q+1] - __half2float(h1));
            hp[q] = (uint32_t)__half_as_ushort(h0) | ((uint32_t)__half_as_ushort(h1) << 16);
            lp[q] = (uint32_t)__half_as_ushort(l0) | ((uint32_t)__half_as_ushort(l1) << 16);
        }
        uint32_t boff = (uint32_t)(p*256 + ((kg ^ (p & 7)) << 4));
        *(uint4*)(sm + OFF_AH + boff) = make_uint4(hp[0],hp[1],hp[2],hp[3]);
        *(uint4*)(sm + OFF_AL + boff) = make_uint4(lp[0],lp[1],lp[2],lp[3]);
    }

    // ldmatrix per-thread geometry
    const uint32_t sw    = (uint32_t)(lane & 7);
    const uint32_t aRow  = (uint32_t)(wid*16 + (lane & 7) + ((lane >> 3) & 1)*8);
    const uint32_t aRowOff = aRow * 256;
    const uint32_t kbitA = (uint32_t)((lane >> 4) & 1);
    const uint32_t bRow0 = (uint32_t)((lane & 7) + ((lane >> 4) & 1)*8);
    const uint32_t kbitB = (uint32_t)((lane >> 3) & 1);

    // epilogue geometry: C rows = j within warp tile (i fixed = wid)
    const int jlo  = lane >> 2, jhi = jlo + 8;
    const int ig   = i0 + wid;
    const int jglo = j0 + jlo, jghi = j0 + jhi;

    float eacc[2] = {0.0f, 0.0f};
    unsigned long long oacc[2][4];
    #pragma unroll
    for (int rh=0;rh<2;rh++)
        #pragma unroll
        for (int v=0;v<4;v++) oacc[rh][v] = 0ull;

    for (int s = 0; s < 4; s++){
        const int head = s >> 1, half = s & 1;
        __syncthreads();     // A-build done (s=0) / prev stage epilogue done

        // stage loads: B fp16 (swizzled), EL/ER slices, layer-2 weights
        const __half* srcB = &g_Bfp[(size_t)s*16384];
        for (int idx = t; idx < 2048; idx += 512){
            int n = idx >> 4, kg = idx & 15;
            uint4 v = *(const uint4*)(srcB + n*128 + kg*8);
            *(uint4*)(sm + OFF_B + n*256 + ((kg ^ (n & 7)) << 4)) = v;
        }
        const float* gl = head ? g_OL : g_EL;
        const float* gr = head ? g_OR : g_ER;
        for (int idx = t; idx < 2048; idx += 512){
            int r = idx >> 7, c = idx & 127;
            s_eli[r*130 + c] = gl[(base + i0 + r)*256 + half*128 + c];
        }
        for (int idx = t; idx < 2048; idx += 512){
            int r = idx >> 7, c = idx & 127;
            s_erj[r*130 + c] = gr[(base + j0 + r)*256 + half*128 + c];
        }
        if (head == 0){
            if (t < 128) s_w2e[t] = eh_w2[half*128 + t];
        } else {
            for (int idx = t; idx < 1024; idx += 512)
                s_w2o[idx] = oh_w2[(half*128 + (idx >> 3))*8 + (idx & 7)];
        }
        __syncthreads();

        #pragma unroll
        for (int chunk = 0; chunk < 2; chunk++){
            float acc[8][4];
            #pragma unroll
            for (int nt=0;nt<8;nt++)
                #pragma unroll
                for (int v=0;v<4;v++) acc[nt][v] = 0.0f;

            #pragma unroll
            for (int pass = 0; pass < 2; pass++){
                const uint32_t aBase = smb + (pass ? OFF_AL : OFF_AH) + aRowOff;
                #pragma unroll
                for (int ks = 0; ks < 8; ks++){
                    uint32_t a0,a1,a2,a3;
                    uint32_t ach = (uint32_t)(2*ks) + kbitA;
                    ldsm4(a0,a1,a2,a3, aBase + ((ach ^ sw) << 4));
                    #pragma unroll
                    for (int ntp = 0; ntp < 4; ntp++){
                        uint32_t bRow = (uint32_t)(chunk*64 + ntp*16) + bRow0;
                        uint32_t bch = (uint32_t)(2*ks) + kbitB;
                        uint32_t baddr = smb + OFF_B + bRow*256 + ((bch ^ sw) << 4);
                        uint32_t b0,b1,b2,b3;
                        ldsm4(b0,b1,b2,b3, baddr);
                        mma16816(acc[2*ntp],   a0,a1,a2,a3, b0,b1);
                        mma16816(acc[2*ntp+1], a0,a1,a2,a3, b2,b3);
                    }
                }
            }

            // ---- epilogue for this 64-col chunk ----
            #pragma unroll
            for (int nt = 0; nt < 8; nt++){
                const int c0 = chunk*64 + nt*8 + 2*(lane & 3);
                const float el0 = s_eli[wid*130 + c0], el1 = s_eli[wid*130 + c0 + 1];
                const float rl0 = s_erj[jlo*130 + c0], rl1 = s_erj[jlo*130 + c0 + 1];
                const float rh0 = s_erj[jhi*130 + c0], rh1 = s_erj[jhi*130 + c0 + 1];
                float h00 = fmaxf(acc[nt][0] + el0 + rl0, 0.0f);
                float h01 = fmaxf(acc[nt][1] + el1 + rl1, 0.0f);
                float h10 = fmaxf(acc[nt][2] + el0 + rh0, 0.0f);
                float h11 = fmaxf(acc[nt][3] + el1 + rh1, 0.0f);
                if (head == 0){
                    float w0 = s_w2e[c0], w1 = s_w2e[c0 + 1];
                    eacc[0] = fmaf(h00, w0, fmaf(h01, w1, eacc[0]));
                    eacc[1] = fmaf(h10, w0, fmaf(h11, w1, eacc[1]));
                } else {
                    const ulonglong2* wp0 = (const ulonglong2*)&s_w2o[c0*8];
                    const ulonglong2* wp1 = (const ulonglong2*)&s_w2o[(c0 + 1)*8];
                    ulonglong2 wa = wp0[0], wb = wp0[1], wc = wp1[0], wd = wp1[1];
                    unsigned long long v00 = splat2(h00), v01 = splat2(h01);
                    unsigned long long v10 = splat2(h10), v11 = splat2(h11);
                    oacc[0][0] = fma2(v00, wa.x, oacc[0][0]); oacc[0][1] = fma2(v00, wa.y, oacc[0][1]);
                    oacc[0][2] = fma2(v00, wb.x, oacc[0][2]); oacc[0][3] = fma2(v00, wb.y, oacc[0][3]);
                    oacc[0][0] = fma2(v01, wc.x, oacc[0][0]); oacc[0][1] = fma2(v01, wc.y, oacc[0][1]);
                    oacc[0][2] = fma2(v01, wd.x, oacc[0][2]); oacc[0][3] = fma2(v01, wd.y, oacc[0][3]);
                    oacc[1][0] = fma2(v10, wa.x, oacc[1][0]); oacc[1][1] = fma2(v10, wa.y, oacc[1][1]);
                    oacc[1][2] = fma2(v10, wb.x, oacc[1][2]); oacc[1][3] = fma2(v10, wb.y, oacc[1][3]);
                    oacc[1][0] = fma2(v11, wc.x, oacc[1][0]); oacc[1][1] = fma2(v11, wc.y, oacc[1][1]);
                    oacc[1][2] = fma2(v11, wd.x, oacc[1][2]); oacc[1][3] = fma2(v11, wd.y, oacc[1][3]);
                }
            }
        }

        if (s == 1){
            #pragma unroll
            for (int rh = 0; rh < 2; rh++){
                float v = eacc[rh];
                v += __shfl_xor_sync(0xffffffffu, v, 1);
                v += __shfl_xor_sync(0xffffffffu, v, 2);
                eacc[rh] = v;
            }
            if ((lane & 3) == 0){
                float b2 = eh_b2[0];
                float v0 = eacc[0] + b2;
                float v1 = eacc[1] + b2;
                if (ig == jglo) v0 = -8.0f;
                if (ig == jghi) v1 = -8.0f;
                out[EDGE_OFF + b*NN*NN + ig*NN + jglo] = v0;
                out[EDGE_OFF + b*NN*NN + ig*NN + jghi] = v1;
            }
        }
        if (s == 3){
            #pragma unroll
            for (int rh = 0; rh < 2; rh++){
                float ov[8];
                #pragma unroll
                for (int v = 0; v < 4; v++){
                    float2 f = *reinterpret_cast<float2*>(&oacc[rh][v]);
                    float x = f.x, y = f.y;
                    x += __shfl_xor_sync(0xffffffffu, x, 1);
                    x += __shfl_xor_sync(0xffffffffu, x, 2);
                    y += __shfl_xor_sync(0xffffffffu, y, 1);
                    y += __shfl_xor_sync(0xffffffffu, y, 2);
                    ov[2*v] = x; ov[2*v+1] = y;
                }
                if ((lane & 3) == 0){
                    int jg = rh ? jghi : jglo;
                    float4* dst = (float4*)&out[OP_OFF + ((size_t)(b*NN*NN + ig*NN + jg))*NOPS];
                    dst[0] = make_float4(ov[0]+oh_b2[0], ov[1]+oh_b2[1], ov[2]+oh_b2[2], ov[3]+oh_b2[3]);
                    dst[1] = make_float4(ov[4]+oh_b2[4], ov[5]+oh_b2[5], ov[6]+oh_b2[6], ov[7]+oh_b2[7]);
                }
            }
        }
    }
}

// ---------------------------------------------------------------------------
// Launch
// ---------------------------------------------------------------------------
extern "C" void kernel_launch(void* const* d_in, const int* in_sizes, int n_in,
                              void* d_out, int out_size)
{
    const float* obs    = (const float*)d_in[0];
    const float* latent = (const float*)d_in[1];
    const float* query  = (const float*)d_in[2];
    const float* enc_w1 = (const float*)d_in[3];
    const float* enc_b1 = (const float*)d_in[4];
    const float* enc_w2 = (const float*)d_in[5];
    const float* enc_b2 = (const float*)d_in[6];
    const float* upd_w  = (const float*)d_in[7];
    const float* upd_b  = (const float*)d_in[8];
    const float* gru_wi = (const float*)d_in[9];
    const float* gru_bi = (const float*)d_in[10];
    const float* gru_wh = (const float*)d_in[11];
    const float* gru_bh = (const float*)d_in[12];
    const float* eh_w1  = (const float*)d_in[13];
    const float* eh_b1  = (const float*)d_in[14];
    const float* eh_w2  = (const float*)d_in[15];
    const float* eh_b2  = (const float*)d_in[16];
    const float* oh_w1  = (const float*)d_in[17];
    const float* oh_b1  = (const float*)d_in[18];
    const float* oh_w2  = (const float*)d_in[19];
    const float* oh_b2  = (const float*)d_in[20];
    const float* q_w    = (const float*)d_in[21];
    const float* q_b    = (const float*)d_in[22];
    const float* nh_w1  = (const float*)d_in[23];
    const float* nh_b1  = (const float*)d_in[24];
    const float* nh_w2  = (const float*)d_in[25];
    const float* nh_b2  = (const float*)d_in[26];

    float* out = (float*)d_out;

    static bool inited = false;
    if (!inited){
        cudaFuncSetAttribute(pairKernel, cudaFuncAttributeMaxDynamicSharedMemorySize, PAIR_SMEM);
        inited = true;
    }

    prepB<<<64, 256>>>(eh_w1, oh_w1);

    nodeKernel<<<256, 256>>>(obs, latent, query,
                             enc_w1, enc_b1, enc_w2, enc_b2,
                             upd_w, upd_b,
                             gru_wi, gru_bi, gru_wh, gru_bh,
                             q_w, q_b, nh_w1, nh_b1, nh_w2, nh_b2,
                             out + NEXT_OFF);

    elKernel<<<dim3(128, 4), 256>>>(eh_w1, eh_b1, oh_w1, oh_b1);

    pairKernel<<<dim3(16, 16, 4), 512, PAIR_SMEM>>>(eh_w2, eh_b2, oh_w2, oh_b2, out);
}

// round 6
// speedup vs baseline: 3.9649x; 1.3820x over previous
#include <cuda_runtime.h>
#include <cuda_bf16.h>
#include <cuda_fp16.h>
#include <math.h>
#include <stdint.h>

// ---------------------------------------------------------------------------
// Problem constants
// ---------------------------------------------------------------------------
#define BB   4
#define NN   256
#define OBS  64
#define QDIM 32
#define HH   256
#define DD   128
#define NOPS 8
#define QE   64
#define BN   (BB*NN)          // 1024 rows

#define EDGE_OFF 0
#define OP_OFF   (BB*NN*NN)                 // 262144
#define NEXT_OFF (OP_OFF + BB*NN*NN*NOPS)   // 2359296

// ---------------------------------------------------------------------------
// Device scratch
// ---------------------------------------------------------------------------
__device__ float g_lat[BN*DD];
__device__ float g_EL[BN*HH];
__device__ float g_ER[BN*HH];
__device__ float g_OL[BN*HH];
__device__ float g_OR[BN*HH];
// fp16 pair-head weights: [s(4)][n(128)][k(128)], s = head*2 + half
__device__ __half g_Bfp[4*128*128];

__device__ __forceinline__ float sigf(float x){ return 1.0f/(1.0f+expf(-x)); }

__device__ __forceinline__ unsigned long long splat2(float x){
    unsigned long long r; unsigned int u = __float_as_uint(x);
    asm("mov.b64 %0, {%1, %1};" : "=l"(r) : "r"(u));
    return r;
}
__device__ __forceinline__ unsigned long long fma2(unsigned long long a,
                                                   unsigned long long b,
                                                   unsigned long long c){
    unsigned long long d;
    asm("fma.rn.f32x2 %0, %1, %2, %3;" : "=l"(d) : "l"(a), "l"(b), "l"(c));
    return d;
}

__device__ __forceinline__ uint32_t smem_u32(const void* p){
    uint32_t a;
    asm("{ .reg .u64 t; cvta.to.shared.u64 t, %1; cvt.u32.u64 %0, t; }"
        : "=r"(a) : "l"(p));
    return a;
}

__device__ __forceinline__ void ldsm4(uint32_t& r0, uint32_t& r1, uint32_t& r2,
                                      uint32_t& r3, uint32_t addr){
    asm volatile("ldmatrix.sync.aligned.m8n8.x4.shared.b16 {%0,%1,%2,%3}, [%4];"
                 : "=r"(r0), "=r"(r1), "=r"(r2), "=r"(r3) : "r"(addr));
}
__device__ __forceinline__ void mma16816(float* d, uint32_t a0, uint32_t a1,
                                         uint32_t a2, uint32_t a3,
                                         uint32_t b0, uint32_t b1){
    asm volatile(
        "mma.sync.aligned.m16n8k16.row.col.f32.f16.f16.f32 "
        "{%0,%1,%2,%3}, {%4,%5,%6,%7}, {%8,%9}, {%0,%1,%2,%3};"
        : "+f"(d[0]), "+f"(d[1]), "+f"(d[2]), "+f"(d[3])
        : "r"(a0), "r"(a1), "r"(a2), "r"(a3), "r"(b0), "r"(b1));
}

// ---------------------------------------------------------------------------
// Kernel A: per-node pipeline. 4 rows/block, 256 blocks.
// ---------------------------------------------------------------------------
__global__ __launch_bounds__(256)
void nodeKernel(const float* __restrict__ obs, const float* __restrict__ latent,
                const float* __restrict__ query,
                const float* __restrict__ enc_w1, const float* __restrict__ enc_b1,
                const float* __restrict__ enc_w2, const float* __restrict__ enc_b2,
                const float* __restrict__ upd_w,  const float* __restrict__ upd_b,
                const float* __restrict__ gru_wi, const float* __restrict__ gru_bi,
                const float* __restrict__ gru_wh, const float* __restrict__ gru_bh,
                const float* __restrict__ q_w,    const float* __restrict__ q_b,
                const float* __restrict__ nh_w1,  const float* __restrict__ nh_b1,
                const float* __restrict__ nh_w2,  const float* __restrict__ nh_b2,
                float* __restrict__ out_next)
{
    __shared__ float s_obs[4*64];
    __shared__ float s_h1 [4*256];
    __shared__ float s_emb[4*256];
    __shared__ float s_gi [4*384];
    __shared__ float s_gh [4*384];

    const int t    = threadIdx.x;
    const int row0 = blockIdx.x * 4;

    s_obs[t] = obs[row0*64 + t];
    __syncthreads();

    {
        float acc[4];
        #pragma unroll
        for (int r=0;r<4;r++) acc[r] = enc_b1[t];
        #pragma unroll 4
        for (int k=0;k<64;k++){
            float w = enc_w1[k*256 + t];
            #pragma unroll
            for (int r=0;r<4;r++) acc[r] = fmaf(s_obs[r*64+k], w, acc[r]);
        }
        #pragma unroll
        for (int r=0;r<4;r++) s_h1[r*256+t] = fmaxf(acc[r], 0.0f);
    }
    __syncthreads();

    {
        float acc[4];
        #pragma unroll
        for (int r=0;r<4;r++) acc[r] = enc_b2[t];
        #pragma unroll 4
        for (int k=0;k<256;k++){
            float w = enc_w2[k*256 + t];
            #pragma unroll
            for (int r=0;r<4;r++) acc[r] = fmaf(s_h1[r*256+k], w, acc[r]);
        }
        __syncthreads();
        #pragma unroll
        for (int r=0;r<4;r++) s_emb[r*256+t] = fmaxf(acc[r], 0.0f);
    }
    __syncthreads();

    float* s_upd = s_h1;
    float* s_lat = s_h1 + 512;

    {
        const int o = t & 127;
        const int rbase = (t >> 7) * 2;
        float acc[2];
        #pragma unroll
        for (int rr=0;rr<2;rr++) acc[rr] = upd_b[o];
        #pragma unroll 4
        for (int k=0;k<256;k++){
            float w = upd_w[k*128 + o];
            #pragma unroll
            for (int rr=0;rr<2;rr++) acc[rr] = fmaf(s_emb[(rbase+rr)*256+k], w, acc[rr]);
        }
        #pragma unroll
        for (int rr=0;rr<2;rr++) s_upd[(rbase+rr)*128+o] = acc[rr];
    }
    for (int idx = t; idx < 512; idx += 256) s_lat[idx] = latent[row0*128 + idx];
    __syncthreads();

    for (int o = t; o < 384; o += 256){
        float ai[4], ah[4];
        #pragma unroll
        for (int r=0;r<4;r++){ ai[r] = gru_bi[o]; ah[r] = gru_bh[o]; }
        #pragma unroll 4
        for (int k=0;k<128;k++){
            float wi = gru_wi[k*384 + o];
            float wh = gru_wh[k*384 + o];
            #pragma unroll
            for (int r=0;r<4;r++){
                ai[r] = fmaf(s_upd[r*128+k], wi, ai[r]);
                ah[r] = fmaf(s_lat[r*128+k], wh, ah[r]);
            }
        }
        #pragma unroll
        for (int r=0;r<4;r++){ s_gi[r*384+o] = ai[r]; s_gh[r*384+o] = ah[r]; }
    }
    __syncthreads();

    for (int idx = t; idx < 512; idx += 256){
        int r = idx >> 7, d = idx & 127;
        float ir = s_gi[r*384 + d],  iz = s_gi[r*384 + 128 + d], inn = s_gi[r*384 + 256 + d];
        float hr = s_gh[r*384 + d],  hz = s_gh[r*384 + 128 + d], hn  = s_gh[r*384 + 256 + d];
        float rg = sigf(ir + hr);
        float zg = sigf(iz + hz);
        float nh = tanhf(inn + rg*hn);
        float lv = (1.0f - zg)*nh + zg*s_lat[idx];
        s_lat[idx] = lv;
        g_lat[row0*128 + idx] = lv;
    }
    __syncthreads();

    for (int idx = t; idx < 4*32; idx += 256) s_gi[idx] = query[row0*32 + idx];
    __syncthreads();
    {
        int r = t >> 6, o = t & 63;
        float acc = q_b[o];
        #pragma unroll
        for (int k=0;k<32;k++) acc = fmaf(s_gi[r*32+k], q_w[k*64+o], acc);
        s_obs[t] = fmaxf(acc, 0.0f);
    }
    __syncthreads();

    {
        float acc[4];
        #pragma unroll
        for (int r=0;r<4;r++) acc[r] = nh_b1[t];
        #pragma unroll 4
        for (int k=0;k<128;k++){
            float w = nh_w1[k*256 + t];
            #pragma unroll
            for (int r=0;r<4;r++) acc[r] = fmaf(s_lat[r*128+k], w, acc[r]);
        }
        #pragma unroll 4
        for (int k=0;k<256;k++){
            float w = nh_w1[(128+k)*256 + t];
            #pragma unroll
            for (int r=0;r<4;r++) acc[r] = fmaf(s_emb[r*256+k], w, acc[r]);
        }
        #pragma unroll 4
        for (int k=0;k<64;k++){
            float w = nh_w1[(384+k)*256 + t];
            #pragma unroll
            for (int r=0;r<4;r++) acc[r] = fmaf(s_obs[r*64+k], w, acc[r]);
        }
        #pragma unroll
        for (int r=0;r<4;r++) s_gh[r*256+t] = fmaxf(acc[r], 0.0f);
    }
    __syncthreads();

    {
        const int w = t >> 5, l = t & 31;
        if (w < 4){
            float p = 0.0f;
            for (int o = l; o < 256; o += 32) p = fmaf(s_gh[w*256 + o], nh_w2[o], p);
            #pragma unroll
            for (int off = 16; off; off >>= 1) p += __shfl_down_sync(0xffffffffu, p, off);
            if (l == 0) out_next[row0 + w] = p + nh_b2[0];
        }
    }
}

// ---------------------------------------------------------------------------
// Kernel B: EL/ER/OL/OR = lat @ W_slice (+bias). grid (128,4).
// ---------------------------------------------------------------------------
__global__ __launch_bounds__(256)
void elKernel(const float* __restrict__ eh_w1, const float* __restrict__ eh_b1,
              const float* __restrict__ oh_w1, const float* __restrict__ oh_b1)
{
    __shared__ float s_lat[8*128];
    const int t = threadIdx.x;
    const int row0 = blockIdx.x * 8;
    const int m = blockIdx.y;

    const float* W; const float* bias = nullptr; float* dst;
    if (m == 0)      { W = eh_w1;            bias = eh_b1; dst = g_EL; }
    else if (m == 1) { W = eh_w1 + 128*256;                dst = g_ER; }
    else if (m == 2) { W = oh_w1;            bias = oh_b1; dst = g_OL; }
    else             { W = oh_w1 + 128*256;                dst = g_OR; }

    for (int idx = t; idx < 1024; idx += 256) s_lat[idx] = g_lat[row0*128 + idx];
    __syncthreads();

    float acc[8];
    float bv = bias ? bias[t] : 0.0f;
    #pragma unroll
    for (int r=0;r<8;r++) acc[r] = bv;
    #pragma unroll 4
    for (int k=0;k<128;k++){
        float w = W[k*256 + t];
        #pragma unroll
        for (int r=0;r<8;r++) acc[r] = fmaf(s_lat[r*128+k], w, acc[r]);
    }
    #pragma unroll
    for (int r=0;r<8;r++) dst[(row0+r)*256 + t] = acc[r];
}

// ---------------------------------------------------------------------------
// Kernel P: pre-convert pair-head |diff| weights to fp16.
// ---------------------------------------------------------------------------
__global__ __launch_bounds__(256)
void prepB(const float* __restrict__ eh_w1, const float* __restrict__ oh_w1)
{
    int gi0 = blockIdx.x * 1024 + threadIdx.x;
    #pragma unroll
    for (int i = 0; i < 4; i++){
        int gi = gi0 + i*256;            // 0..65535 over (s,n,k)
        int s   = gi >> 14;
        int rem = gi & 16383;
        int n   = rem >> 7;
        int k   = rem & 127;
        int head = s >> 1, half = s & 1;
        const float* w = head ? oh_w1 : eh_w1;
        g_Bfp[(s*128 + n)*128 + k] = __float2half(w[(256 + k)*256 + half*128 + n]);
    }
}

// ---------------------------------------------------------------------------
// Kernel C: pair MLP via mma.sync fp16 hi/lo (fused single k-loop), epilogue.
// Block: 16 i x 16 j = 256 pairs, 512 threads (16 warps), 4 stages.
// B fragments loaded ONCE per (chunk,ks,ntp) and reused for Ah and Al mma.
// ---------------------------------------------------------------------------
#define OFF_AH   0                         // 256 rows * 256B = 65536
#define OFF_AL   65536                     // 65536
#define OFF_B    131072                    // 128 rows * 256B = 32768
#define OFF_ELI  163840                    // 16*130*4 = 8320
#define OFF_ERJ  172160                    // 8320
#define OFF_W2E  180480                    // 512
#define OFF_W2O  180992                    // 4096
#define PAIR_SMEM 185088

__global__ __launch_bounds__(512, 1)
void pairKernel(const float* __restrict__ eh_w2, const float* __restrict__ eh_b2,
                const float* __restrict__ oh_w2, const float* __restrict__ oh_b2,
                float* __restrict__ out)
{
    extern __shared__ __align__(16) char sm[];
    float* s_li  = (float*)(sm + OFF_ELI);   // prologue staging [16][128]
    float* s_lj  = (float*)(sm + OFF_ERJ);   // prologue staging [16][128]
    float* s_eli = (float*)(sm + OFF_ELI);   // per-stage [16][130]
    float* s_erj = (float*)(sm + OFF_ERJ);   // per-stage [16][130]
    float* s_w2e = (float*)(sm + OFF_W2E);   // per-stage [128]
    float* s_w2o = (float*)(sm + OFF_W2O);   // per-stage [128][8]

    const uint32_t smb = smem_u32(sm);
    const int t    = threadIdx.x;
    const int wid  = t >> 5;
    const int lane = t & 31;
    const int b    = blockIdx.z;
    const int i0   = blockIdx.y * 16;
    const int j0   = blockIdx.x * 16;
    const int base = b * NN;

    // ---- prologue: stage lat rows ----
    for (int idx = t; idx < 2048; idx += 512) s_li[idx] = g_lat[(base + i0)*128 + idx];
    for (int idx = t; idx < 2048; idx += 512) s_lj[idx] = g_lat[(base + j0)*128 + idx];
    __syncthreads();

    // ---- build A = |li - lj| as fp16 hi/lo, XOR-swizzled 256B rows ----
    for (int c = t; c < 4096; c += 512){
        int p = c >> 4, kg = c & 15;
        int il = p >> 4, jl = p & 15;
        const float4* li4 = (const float4*)&s_li[il*128 + kg*8];
        const float4* lj4 = (const float4*)&s_lj[jl*128 + kg*8];
        float4 x0 = li4[0], x1 = li4[1], y0 = lj4[0], y1 = lj4[1];
        float a[8] = { fabsf(x0.x-y0.x), fabsf(x0.y-y0.y), fabsf(x0.z-y0.z), fabsf(x0.w-y0.w),
                       fabsf(x1.x-y1.x), fabsf(x1.y-y1.y), fabsf(x1.z-y1.z), fabsf(x1.w-y1.w) };
        uint32_t hp[4], lp[4];
        #pragma unroll
        for (int q = 0; q < 4; q++){
            __half h0 = __float2half(a[2*q]);
            __half h1 = __float2half(a[2*q+1]);
            __half l0 = __float2half(a[2*q]   - __half2float(h0));
            __half l1 = __float2half(a[2*q+1] - __half2float(h1));
            hp[q] = (uint32_t)__half_as_ushort(h0) | ((uint32_t)__half_as_ushort(h1) << 16);
            lp[q] = (uint32_t)__half_as_ushort(l0) | ((uint32_t)__half_as_ushort(l1) << 16);
        }
        uint32_t boff = (uint32_t)(p*256 + ((kg ^ (p & 7)) << 4));
        *(uint4*)(sm + OFF_AH + boff) = make_uint4(hp[0],hp[1],hp[2],hp[3]);
        *(uint4*)(sm + OFF_AL + boff) = make_uint4(lp[0],lp[1],lp[2],lp[3]);
    }

    // ldmatrix per-thread geometry
    const uint32_t sw    = (uint32_t)(lane & 7);
    const uint32_t aRow  = (uint32_t)(wid*16 + (lane & 7) + ((lane >> 3) & 1)*8);
    const uint32_t aRowOff = aRow * 256;
    const uint32_t kbitA = (uint32_t)((lane >> 4) & 1);
    const uint32_t bRow0 = (uint32_t)((lane & 7) + ((lane >> 4) & 1)*8);
    const uint32_t kbitB = (uint32_t)((lane >> 3) & 1);

    // epilogue geometry
    const int jlo  = lane >> 2, jhi = jlo + 8;
    const int ig   = i0 + wid;
    const int jglo = j0 + jlo, jghi = j0 + jhi;

    float eacc[2] = {0.0f, 0.0f};
    unsigned long long oacc[2][4];
    #pragma unroll
    for (int rh=0;rh<2;rh++)
        #pragma unroll
        for (int v=0;v<4;v++) oacc[rh][v] = 0ull;

    for (int s = 0; s < 4; s++){
        const int head = s >> 1, half = s & 1;
        __syncthreads();     // A-build done (s=0) / prev stage epilogue done

        // stage loads: B fp16 (swizzled), EL/ER slices, layer-2 weights
        const __half* srcB = &g_Bfp[(size_t)s*16384];
        for (int idx = t; idx < 2048; idx += 512){
            int n = idx >> 4, kg = idx & 15;
            uint4 v = *(const uint4*)(srcB + n*128 + kg*8);
            *(uint4*)(sm + OFF_B + n*256 + ((kg ^ (n & 7)) << 4)) = v;
        }
        const float* gl = head ? g_OL : g_EL;
        const float* gr = head ? g_OR : g_ER;
        for (int idx = t; idx < 2048; idx += 512){
            int r = idx >> 7, c = idx & 127;
            s_eli[r*130 + c] = gl[(base + i0 + r)*256 + half*128 + c];
        }
        for (int idx = t; idx < 2048; idx += 512){
            int r = idx >> 7, c = idx & 127;
            s_erj[r*130 + c] = gr[(base + j0 + r)*256 + half*128 + c];
        }
        if (head == 0){
            if (t < 128) s_w2e[t] = eh_w2[half*128 + t];
        } else {
            for (int idx = t; idx < 1024; idx += 512)
                s_w2o[idx] = oh_w2[(half*128 + (idx >> 3))*8 + (idx & 7)];
        }
        __syncthreads();

        #pragma unroll
        for (int chunk = 0; chunk < 2; chunk++){
            float acc[8][4];
            #pragma unroll
            for (int nt=0;nt<8;nt++)
                #pragma unroll
                for (int v=0;v<4;v++) acc[nt][v] = 0.0f;

            #pragma unroll
            for (int ks = 0; ks < 8; ks++){
                const uint32_t aoff = ((((uint32_t)(2*ks) + kbitA) ^ sw) << 4);
                uint32_t ah0,ah1,ah2,ah3, al0,al1,al2,al3;
                ldsm4(ah0,ah1,ah2,ah3, smb + OFF_AH + aRowOff + aoff);
                ldsm4(al0,al1,al2,al3, smb + OFF_AL + aRowOff + aoff);
                const uint32_t bch = ((((uint32_t)(2*ks) + kbitB) ^ sw) << 4);
                #pragma unroll
                for (int ntp = 0; ntp < 4; ntp++){
                    uint32_t bRow = (uint32_t)(chunk*64 + ntp*16) + bRow0;
                    uint32_t b0,b1,b2,b3;
                    ldsm4(b0,b1,b2,b3, smb + OFF_B + bRow*256 + bch);
                    mma16816(acc[2*ntp],   ah0,ah1,ah2,ah3, b0,b1);
                    mma16816(acc[2*ntp+1], ah0,ah1,ah2,ah3, b2,b3);
                    mma16816(acc[2*ntp],   al0,al1,al2,al3, b0,b1);
                    mma16816(acc[2*ntp+1], al0,al1,al2,al3, b2,b3);
                }
            }

            // ---- epilogue for this 64-col chunk (float2 LDS) ----
            #pragma unroll
            for (int nt = 0; nt < 8; nt++){
                const int c0 = chunk*64 + nt*8 + 2*(lane & 3);
                const float2 el = *(const float2*)&s_eli[wid*130 + c0];
                const float2 rl = *(const float2*)&s_erj[jlo*130 + c0];
                const float2 rh = *(const float2*)&s_erj[jhi*130 + c0];
                float h00 = fmaxf(acc[nt][0] + el.x + rl.x, 0.0f);
                float h01 = fmaxf(acc[nt][1] + el.y + rl.y, 0.0f);
                float h10 = fmaxf(acc[nt][2] + el.x + rh.x, 0.0f);
                float h11 = fmaxf(acc[nt][3] + el.y + rh.y, 0.0f);
                if (head == 0){
                    const float2 w2 = *(const float2*)&s_w2e[c0];
                    eacc[0] = fmaf(h00, w2.x, fmaf(h01, w2.y, eacc[0]));
                    eacc[1] = fmaf(h10, w2.x, fmaf(h11, w2.y, eacc[1]));
                } else {
                    const ulonglong2* wp0 = (const ulonglong2*)&s_w2o[c0*8];
                    const ulonglong2* wp1 = (const ulonglong2*)&s_w2o[(c0 + 1)*8];
                    ulonglong2 wa = wp0[0], wb = wp0[1], wc = wp1[0], wd = wp1[1];
                    unsigned long long v00 = splat2(h00), v01 = splat2(h01);
                    unsigned long long v10 = splat2(h10), v11 = splat2(h11);
                    oacc[0][0] = fma2(v00, wa.x, oacc[0][0]); oacc[0][1] = fma2(v00, wa.y, oacc[0][1]);
                    oacc[0][2] = fma2(v00, wb.x, oacc[0][2]); oacc[0][3] = fma2(v00, wb.y, oacc[0][3]);
                    oacc[0][0] = fma2(v01, wc.x, oacc[0][0]); oacc[0][1] = fma2(v01, wc.y, oacc[0][1]);
                    oacc[0][2] = fma2(v01, wd.x, oacc[0][2]); oacc[0][3] = fma2(v01, wd.y, oacc[0][3]);
                    oacc[1][0] = fma2(v10, wa.x, oacc[1][0]); oacc[1][1] = fma2(v10, wa.y, oacc[1][1]);
                    oacc[1][2] = fma2(v10, wb.x, oacc[1][2]); oacc[1][3] = fma2(v10, wb.y, oacc[1][3]);
                    oacc[1][0] = fma2(v11, wc.x, oacc[1][0]); oacc[1][1] = fma2(v11, wc.y, oacc[1][1]);
                    oacc[1][2] = fma2(v11, wd.x, oacc[1][2]); oacc[1][3] = fma2(v11, wd.y, oacc[1][3]);
                }
            }
        }

        if (s == 1){
            #pragma unroll
            for (int rh = 0; rh < 2; rh++){
                float v = eacc[rh];
                v += __shfl_xor_sync(0xffffffffu, v, 1);
                v += __shfl_xor_sync(0xffffffffu, v, 2);
                eacc[rh] = v;
            }
            if ((lane & 3) == 0){
                float b2 = eh_b2[0];
                float v0 = eacc[0] + b2;
                float v1 = eacc[1] + b2;
                if (ig == jglo) v0 = -8.0f;
                if (ig == jghi) v1 = -8.0f;
                out[EDGE_OFF + b*NN*NN + ig*NN + jglo] = v0;
                out[EDGE_OFF + b*NN*NN + ig*NN + jghi] = v1;
            }
        }
        if (s == 3){
            #pragma unroll
            for (int rh = 0; rh < 2; rh++){
                float ov[8];
                #pragma unroll
                for (int v = 0; v < 4; v++){
                    float2 f = *reinterpret_cast<float2*>(&oacc[rh][v]);
                    float x = f.x, y = f.y;
                    x += __shfl_xor_sync(0xffffffffu, x, 1);
                    x += __shfl_xor_sync(0xffffffffu, x, 2);
                    y += __shfl_xor_sync(0xffffffffu, y, 1);
                    y += __shfl_xor_sync(0xffffffffu, y, 2);
                    ov[2*v] = x; ov[2*v+1] = y;
                }
                if ((lane & 3) == 0){
                    int jg = rh ? jghi : jglo;
                    float4* dst = (float4*)&out[OP_OFF + ((size_t)(b*NN*NN + ig*NN + jg))*NOPS];
                    dst[0] = make_float4(ov[0]+oh_b2[0], ov[1]+oh_b2[1], ov[2]+oh_b2[2], ov[3]+oh_b2[3]);
                    dst[1] = make_float4(ov[4]+oh_b2[4], ov[5]+oh_b2[5], ov[6]+oh_b2[6], ov[7]+oh_b2[7]);
                }
            }
        }
    }
}

// ---------------------------------------------------------------------------
// Launch
// ---------------------------------------------------------------------------
extern "C" void kernel_launch(void* const* d_in, const int* in_sizes, int n_in,
                              void* d_out, int out_size)
{
    const float* obs    = (const float*)d_in[0];
    const float* latent = (const float*)d_in[1];
    const float* query  = (const float*)d_in[2];
    const float* enc_w1 = (const float*)d_in[3];
    const float* enc_b1 = (const float*)d_in[4];
    const float* enc_w2 = (const float*)d_in[5];
    const float* enc_b2 = (const float*)d_in[6];
    const float* upd_w  = (const float*)d_in[7];
    const float* upd_b  = (const float*)d_in[8];
    const float* gru_wi = (const float*)d_in[9];
    const float* gru_bi = (const float*)d_in[10];
    const float* gru_wh = (const float*)d_in[11];
    const float* gru_bh = (const float*)d_in[12];
    const float* eh_w1  = (const float*)d_in[13];
    const float* eh_b1  = (const float*)d_in[14];
    const float* eh_w2  = (const float*)d_in[15];
    const float* eh_b2  = (const float*)d_in[16];
    const float* oh_w1  = (const float*)d_in[17];
    const float* oh_b1  = (const float*)d_in[18];
    const float* oh_w2  = (const float*)d_in[19];
    const float* oh_b2  = (const float*)d_in[20];
    const float* q_w    = (const float*)d_in[21];
    const float* q_b    = (const float*)d_in[22];
    const float* nh_w1  = (const float*)d_in[23];
    const float* nh_b1  = (const float*)d_in[24];
    const float* nh_w2  = (const float*)d_in[25];
    const float* nh_b2  = (const float*)d_in[26];

    float* out = (float*)d_out;

    static bool inited = false;
    if (!inited){
        cudaFuncSetAttribute(pairKernel, cudaFuncAttributeMaxDynamicSharedMemorySize, PAIR_SMEM);
        inited = true;
    }

    prepB<<<64, 256>>>(eh_w1, oh_w1);

    nodeKernel<<<256, 256>>>(obs, latent, query,
                             enc_w1, enc_b1, enc_w2, enc_b2,
                             upd_w, upd_b,
                             gru_wi, gru_bi, gru_wh, gru_bh,
                             q_w, q_b, nh_w1, nh_b1, nh_w2, nh_b2,
                             out + NEXT_OFF);

    elKernel<<<dim3(128, 4), 256>>>(eh_w1, eh_b1, oh_w1, oh_b1);

    pairKernel<<<dim3(16, 16, 4), 512, PAIR_SMEM>>>(eh_w2, eh_b2, oh_w2, oh_b2, out);
}

// round 8
// speedup vs baseline: 4.3744x; 1.1033x over previous
#include <cuda_runtime.h>
#include <cuda_bf16.h>
#include <cuda_fp16.h>
#include <math.h>
#include <stdint.h>

// ---------------------------------------------------------------------------
// Problem constants
// ---------------------------------------------------------------------------
#define BB   4
#define NN   256
#define OBS  64
#define QDIM 32
#define HH   256
#define DD   128
#define NOPS 8
#define QE   64
#define BN   (BB*NN)          // 1024 rows

#define EDGE_OFF 0
#define OP_OFF   (BB*NN*NN)                 // 262144
#define NEXT_OFF (OP_OFF + BB*NN*NN*NOPS)   // 2359296

// ---------------------------------------------------------------------------
// Device scratch
// ---------------------------------------------------------------------------
__device__ float g_lat[BN*DD];
__device__ float g_EL[BN*HH];
__device__ float g_ER[BN*HH];
__device__ float g_OL[BN*HH];
__device__ float g_OR[BN*HH];
// fp16 pair-head weights: [s(4)][n(128)][k(128)], s = head*2 + half
__device__ __half g_Bfp[4*128*128];

__device__ __forceinline__ float sigf(float x){ return 1.0f/(1.0f+expf(-x)); }

__device__ __forceinline__ unsigned long long splat2(float x){
    unsigned long long r; unsigned int u = __float_as_uint(x);
    asm("mov.b64 %0, {%1, %1};" : "=l"(r) : "r"(u));
    return r;
}
__device__ __forceinline__ unsigned long long fma2(unsigned long long a,
                                                   unsigned long long b,
                                                   unsigned long long c){
    unsigned long long d;
    asm("fma.rn.f32x2 %0, %1, %2, %3;" : "=l"(d) : "l"(a), "l"(b), "l"(c));
    return d;
}

__device__ __forceinline__ uint32_t smem_u32(const void* p){
    uint32_t a;
    asm("{ .reg .u64 t; cvta.to.shared.u64 t, %1; cvt.u32.u64 %0, t; }"
        : "=r"(a) : "l"(p));
    return a;
}

__device__ __forceinline__ void ldsm4(uint32_t& r0, uint32_t& r1, uint32_t& r2,
                                      uint32_t& r3, uint32_t addr){
    asm volatile("ldmatrix.sync.aligned.m8n8.x4.shared.b16 {%0,%1,%2,%3}, [%4];"
                 : "=r"(r0), "=r"(r1), "=r"(r2), "=r"(r3) : "r"(addr));
}
__device__ __forceinline__ void mma16816(float* d, uint32_t a0, uint32_t a1,
                                         uint32_t a2, uint32_t a3,
                                         uint32_t b0, uint32_t b1){
    asm volatile(
        "mma.sync.aligned.m16n8k16.row.col.f32.f16.f16.f32 "
        "{%0,%1,%2,%3}, {%4,%5,%6,%7}, {%8,%9}, {%0,%1,%2,%3};"
        : "+f"(d[0]), "+f"(d[1]), "+f"(d[2]), "+f"(d[3])
        : "r"(a0), "r"(a1), "r"(a2), "r"(a3), "r"(b0), "r"(b1));
}

// ---------------------------------------------------------------------------
// Kernel A: per-node pipeline. 4 rows/block, 256 blocks.
// ---------------------------------------------------------------------------
__global__ __launch_bounds__(256)
void nodeKernel(const float* __restrict__ obs, const float* __restrict__ latent,
                const float* __restrict__ query,
                const float* __restrict__ enc_w1, const float* __restrict__ enc_b1,
                const float* __restrict__ enc_w2, const float* __restrict__ enc_b2,
                const float* __restrict__ upd_w,  const float* __restrict__ upd_b,
                const float* __restrict__ gru_wi, const float* __restrict__ gru_bi,
                const float* __restrict__ gru_wh, const float* __restrict__ gru_bh,
                const float* __restrict__ q_w,    const float* __restrict__ q_b,
                const float* __restrict__ nh_w1,  const float* __restrict__ nh_b1,
                const float* __restrict__ nh_w2,  const float* __restrict__ nh_b2,
                float* __restrict__ out_next)
{
    __shared__ float s_obs[4*64];
    __shared__ float s_h1 [4*256];
    __shared__ float s_emb[4*256];
    __shared__ float s_gi [4*384];
    __shared__ float s_gh [4*384];

    const int t    = threadIdx.x;
    const int row0 = blockIdx.x * 4;

    s_obs[t] = obs[row0*64 + t];
    __syncthreads();

    {
        float acc[4];
        #pragma unroll
        for (int r=0;r<4;r++) acc[r] = enc_b1[t];
        #pragma unroll 4
        for (int k=0;k<64;k++){
            float w = enc_w1[k*256 + t];
            #pragma unroll
            for (int r=0;r<4;r++) acc[r] = fmaf(s_obs[r*64+k], w, acc[r]);
        }
        #pragma unroll
        for (int r=0;r<4;r++) s_h1[r*256+t] = fmaxf(acc[r], 0.0f);
    }
    __syncthreads();

    {
        float acc[4];
        #pragma unroll
        for (int r=0;r<4;r++) acc[r] = enc_b2[t];
        #pragma unroll 4
        for (int k=0;k<256;k++){
            float w = enc_w2[k*256 + t];
            #pragma unroll
            for (int r=0;r<4;r++) acc[r] = fmaf(s_h1[r*256+k], w, acc[r]);
        }
        __syncthreads();
        #pragma unroll
        for (int r=0;r<4;r++) s_emb[r*256+t] = fmaxf(acc[r], 0.0f);
    }
    __syncthreads();

    float* s_upd = s_h1;
    float* s_lat = s_h1 + 512;

    {
        const int o = t & 127;
        const int rbase = (t >> 7) * 2;
        float acc[2];
        #pragma unroll
        for (int rr=0;rr<2;rr++) acc[rr] = upd_b[o];
        #pragma unroll 4
        for (int k=0;k<256;k++){
            float w = upd_w[k*128 + o];
            #pragma unroll
            for (int rr=0;rr<2;rr++) acc[rr] = fmaf(s_emb[(rbase+rr)*256+k], w, acc[rr]);
        }
        #pragma unroll
        for (int rr=0;rr<2;rr++) s_upd[(rbase+rr)*128+o] = acc[rr];
    }
    for (int idx = t; idx < 512; idx += 256) s_lat[idx] = latent[row0*128 + idx];
    __syncthreads();

    for (int o = t; o < 384; o += 256){
        float ai[4], ah[4];
        #pragma unroll
        for (int r=0;r<4;r++){ ai[r] = gru_bi[o]; ah[r] = gru_bh[o]; }
        #pragma unroll 4
        for (int k=0;k<128;k++){
            float wi = gru_wi[k*384 + o];
            float wh = gru_wh[k*384 + o];
            #pragma unroll
            for (int r=0;r<4;r++){
                ai[r] = fmaf(s_upd[r*128+k], wi, ai[r]);
                ah[r] = fmaf(s_lat[r*128+k], wh, ah[r]);
            }
        }
        #pragma unroll
        for (int r=0;r<4;r++){ s_gi[r*384+o] = ai[r]; s_gh[r*384+o] = ah[r]; }
    }
    __syncthreads();

    for (int idx = t; idx < 512; idx += 256){
        int r = idx >> 7, d = idx & 127;
        float ir = s_gi[r*384 + d],  iz = s_gi[r*384 + 128 + d], inn = s_gi[r*384 + 256 + d];
        float hr = s_gh[r*384 + d],  hz = s_gh[r*384 + 128 + d], hn  = s_gh[r*384 + 256 + d];
        float rg = sigf(ir + hr);
        float zg = sigf(iz + hz);
        float nh = tanhf(inn + rg*hn);
        float lv = (1.0f - zg)*nh + zg*s_lat[idx];
        s_lat[idx] = lv;
        g_lat[row0*128 + idx] = lv;
    }
    __syncthreads();

    for (int idx = t; idx < 4*32; idx += 256) s_gi[idx] = query[row0*32 + idx];
    __syncthreads();
    {
        int r = t >> 6, o = t & 63;
        float acc = q_b[o];
        #pragma unroll
        for (int k=0;k<32;k++) acc = fmaf(s_gi[r*32+k], q_w[k*64+o], acc);
        s_obs[t] = fmaxf(acc, 0.0f);
    }
    __syncthreads();

    {
        float acc[4];
        #pragma unroll
        for (int r=0;r<4;r++) acc[r] = nh_b1[t];
        #pragma unroll 4
        for (int k=0;k<128;k++){
            float w = nh_w1[k*256 + t];
            #pragma unroll
            for (int r=0;r<4;r++) acc[r] = fmaf(s_lat[r*128+k], w, acc[r]);
        }
        #pragma unroll 4
        for (int k=0;k<256;k++){
            float w = nh_w1[(128+k)*256 + t];
            #pragma unroll
            for (int r=0;r<4;r++) acc[r] = fmaf(s_emb[r*256+k], w, acc[r]);
        }
        #pragma unroll 4
        for (int k=0;k<64;k++){
            float w = nh_w1[(384+k)*256 + t];
            #pragma unroll
            for (int r=0;r<4;r++) acc[r] = fmaf(s_obs[r*64+k], w, acc[r]);
        }
        #pragma unroll
        for (int r=0;r<4;r++) s_gh[r*256+t] = fmaxf(acc[r], 0.0f);
    }
    __syncthreads();

    {
        const int w = t >> 5, l = t & 31;
        if (w < 4){
            float p = 0.0f;
            for (int o = l; o < 256; o += 32) p = fmaf(s_gh[w*256 + o], nh_w2[o], p);
            #pragma unroll
            for (int off = 16; off; off >>= 1) p += __shfl_down_sync(0xffffffffu, p, off);
            if (l == 0) out_next[row0 + w] = p + nh_b2[0];
        }
    }
}

// ---------------------------------------------------------------------------
// Kernel B: EL/ER/OL/OR = lat @ W_slice (+bias). grid (128,4).
// ---------------------------------------------------------------------------
__global__ __launch_bounds__(256)
void elKernel(const float* __restrict__ eh_w1, const float* __restrict__ eh_b1,
              const float* __restrict__ oh_w1, const float* __restrict__ oh_b1)
{
    __shared__ float s_lat[8*128];
    const int t = threadIdx.x;
    const int row0 = blockIdx.x * 8;
    const int m = blockIdx.y;

    const float* W; const float* bias = nullptr; float* dst;
    if (m == 0)      { W = eh_w1;            bias = eh_b1; dst = g_EL; }
    else if (m == 1) { W = eh_w1 + 128*256;                dst = g_ER; }
    else if (m == 2) { W = oh_w1;            bias = oh_b1; dst = g_OL; }
    else             { W = oh_w1 + 128*256;                dst = g_OR; }

    for (int idx = t; idx < 1024; idx += 256) s_lat[idx] = g_lat[row0*128 + idx];
    __syncthreads();

    float acc[8];
    float bv = bias ? bias[t] : 0.0f;
    #pragma unroll
    for (int r=0;r<8;r++) acc[r] = bv;
    #pragma unroll 4
    for (int k=0;k<128;k++){
        float w = W[k*256 + t];
        #pragma unroll
        for (int r=0;r<8;r++) acc[r] = fmaf(s_lat[r*128+k], w, acc[r]);
    }
    #pragma unroll
    for (int r=0;r<8;r++) dst[(row0+r)*256 + t] = acc[r];
}

// ---------------------------------------------------------------------------
// Kernel P: pre-convert pair-head |diff| weights to fp16.
// ---------------------------------------------------------------------------
__global__ __launch_bounds__(256)
void prepB(const float* __restrict__ eh_w1, const float* __restrict__ oh_w1)
{
    int gi0 = blockIdx.x * 1024 + threadIdx.x;
    #pragma unroll
    for (int i = 0; i < 4; i++){
        int gi = gi0 + i*256;            // 0..65535 over (s,n,k)
        int s   = gi >> 14;
        int rem = gi & 16383;
        int n   = rem >> 7;
        int k   = rem & 127;
        int head = s >> 1, half = s & 1;
        const float* w = head ? oh_w1 : eh_w1;
        g_Bfp[(s*128 + n)*128 + k] = __float2half(w[(256 + k)*256 + half*128 + n]);
    }
}

// ---------------------------------------------------------------------------
// Kernel C: pair MLP via mma.sync fp16 single-pass, fused epilogue.
// Block: 16 i x 16 j = 256 pairs, 512 threads (16 warps), 4 stages.
// A = |diff| quantized to fp16 once (error ~2^-12, combined with fp16 B
// stays well under the 1e-3 gate). B fragments loaded once per (chunk,ks,ntp).
// ---------------------------------------------------------------------------
#define OFF_A    0                         // 256 rows * 256B = 65536
#define OFF_B    65536                     // 128 rows * 256B = 32768
#define OFF_ELI  98304                     // 16*130*4 = 8320
#define OFF_ERJ  106624                    // 8320
#define OFF_W2E  114944                    // 512
#define OFF_W2O  115456                    // 4096
#define PAIR_SMEM 119552

__global__ __launch_bounds__(512, 1)
void pairKernel(const float* __restrict__ eh_w2, const float* __restrict__ eh_b2,
                const float* __restrict__ oh_w2, const float* __restrict__ oh_b2,
                float* __restrict__ out)
{
    extern __shared__ __align__(16) char sm[];
    float* s_li  = (float*)(sm + OFF_ELI);   // prologue staging [16][128]
    float* s_lj  = (float*)(sm + OFF_ERJ);   // prologue staging [16][128]
    float* s_eli = (float*)(sm + OFF_ELI);   // per-stage [16][130]
    float* s_erj = (float*)(sm + OFF_ERJ);   // per-stage [16][130]
    float* s_w2e = (float*)(sm + OFF_W2E);   // per-stage [128]
    float* s_w2o = (float*)(sm + OFF_W2O);   // per-stage [128][8]

    const uint32_t smb = smem_u32(sm);
    const int t    = threadIdx.x;
    const int wid  = t >> 5;
    const int lane = t & 31;
    const int b    = blockIdx.z;
    const int i0   = blockIdx.y * 16;
    const int j0   = blockIdx.x * 16;
    const int base = b * NN;

    // ---- prologue: stage lat rows ----
    for (int idx = t; idx < 2048; idx += 512) s_li[idx] = g_lat[(base + i0)*128 + idx];
    for (int idx = t; idx < 2048; idx += 512) s_lj[idx] = g_lat[(base + j0)*128 + idx];
    __syncthreads();

    // ---- build A = |li - lj| as fp16, XOR-swizzled 256B rows ----
    for (int c = t; c < 4096; c += 512){
        int p = c >> 4, kg = c & 15;
        int il = p >> 4, jl = p & 15;
        const float4* li4 = (const float4*)&s_li[il*128 + kg*8];
        const float4* lj4 = (const float4*)&s_lj[jl*128 + kg*8];
        float4 x0 = li4[0], x1 = li4[1], y0 = lj4[0], y1 = lj4[1];
        float a[8] = { fabsf(x0.x-y0.x), fabsf(x0.y-y0.y), fabsf(x0.z-y0.z), fabsf(x0.w-y0.w),
                       fabsf(x1.x-y1.x), fabsf(x1.y-y1.y), fabsf(x1.z-y1.z), fabsf(x1.w-y1.w) };
        uint32_t hp[4];
        #pragma unroll
        for (int q = 0; q < 4; q++){
            __half h0 = __float2half(a[2*q]);
            __half h1 = __float2half(a[2*q+1]);
            hp[q] = (uint32_t)__half_as_ushort(h0) | ((uint32_t)__half_as_ushort(h1) << 16);
        }
        uint32_t boff = (uint32_t)(p*256 + ((kg ^ (p & 7)) << 4));
        *(uint4*)(sm + OFF_A + boff) = make_uint4(hp[0],hp[1],hp[2],hp[3]);
    }

    // ldmatrix per-thread geometry
    const uint32_t sw    = (uint32_t)(lane & 7);
    const uint32_t aRow  = (uint32_t)(wid*16 + (lane & 7) + ((lane >> 3) & 1)*8);
    const uint32_t aRowOff = aRow * 256;
    const uint32_t kbitA = (uint32_t)((lane >> 4) & 1);
    const uint32_t bRow0 = (uint32_t)((lane & 7) + ((lane >> 4) & 1)*8);
    const uint32_t kbitB = (uint32_t)((lane >> 3) & 1);

    // epilogue geometry
    const int jlo  = lane >> 2, jhi = jlo + 8;
    const int ig   = i0 + wid;
    const int jglo = j0 + jlo, jghi = j0 + jhi;

    float eacc[2] = {0.0f, 0.0f};
    unsigned long long oacc[2][4];
    #pragma unroll
    for (int rh=0;rh<2;rh++)
        #pragma unroll
        for (int v=0;v<4;v++) oacc[rh][v] = 0ull;

    for (int s = 0; s < 4; s++){
        const int head = s >> 1, half = s & 1;
        __syncthreads();     // A-build done (s=0) / prev stage epilogue done

        // stage loads: B fp16 (swizzled), EL/ER slices, layer-2 weights
        const __half* srcB = &g_Bfp[(size_t)s*16384];
        for (int idx = t; idx < 2048; idx += 512){
            int n = idx >> 4, kg = idx & 15;
            uint4 v = *(const uint4*)(srcB + n*128 + kg*8);
            *(uint4*)(sm + OFF_B + n*256 + ((kg ^ (n & 7)) << 4)) = v;
        }
        const float* gl = head ? g_OL : g_EL;
        const float* gr = head ? g_OR : g_ER;
        for (int idx = t; idx < 2048; idx += 512){
            int r = idx >> 7, c = idx & 127;
            s_eli[r*130 + c] = gl[(base + i0 + r)*256 + half*128 + c];
        }
        for (int idx = t; idx < 2048; idx += 512){
            int r = idx >> 7, c = idx & 127;
            s_erj[r*130 + c] = gr[(base + j0 + r)*256 + half*128 + c];
        }
        if (head == 0){
            if (t < 128) s_w2e[t] = eh_w2[half*128 + t];
        } else {
            for (int idx = t; idx < 1024; idx += 512)
                s_w2o[idx] = oh_w2[(half*128 + (idx >> 3))*8 + (idx & 7)];
        }
        __syncthreads();

        #pragma unroll
        for (int chunk = 0; chunk < 2; chunk++){
            float acc[8][4];
            #pragma unroll
            for (int nt=0;nt<8;nt++)
                #pragma unroll
                for (int v=0;v<4;v++) acc[nt][v] = 0.0f;

            #pragma unroll
            for (int ks = 0; ks < 8; ks++){
                const uint32_t aoff = ((((uint32_t)(2*ks) + kbitA) ^ sw) << 4);
                uint32_t a0,a1,a2,a3;
                ldsm4(a0,a1,a2,a3, smb + OFF_A + aRowOff + aoff);
                const uint32_t bch = ((((uint32_t)(2*ks) + kbitB) ^ sw) << 4);
                #pragma unroll
                for (int ntp = 0; ntp < 4; ntp++){
                    uint32_t bRow = (uint32_t)(chunk*64 + ntp*16) + bRow0;
                    uint32_t b0,b1,b2,b3;
                    ldsm4(b0,b1,b2,b3, smb + OFF_B + bRow*256 + bch);
                    mma16816(acc[2*ntp],   a0,a1,a2,a3, b0,b1);
                    mma16816(acc[2*ntp+1], a0,a1,a2,a3, b2,b3);
                }
            }

            // ---- epilogue for this 64-col chunk (float2 LDS) ----
            #pragma unroll
            for (int nt = 0; nt < 8; nt++){
                const int c0 = chunk*64 + nt*8 + 2*(lane & 3);
                const float2 el = *(const float2*)&s_eli[wid*130 + c0];
                const float2 rl = *(const float2*)&s_erj[jlo*130 + c0];
                const float2 rh = *(const float2*)&s_erj[jhi*130 + c0];
                float h00 = fmaxf(acc[nt][0] + el.x + rl.x, 0.0f);
                float h01 = fmaxf(acc[nt][1] + el.y + rl.y, 0.0f);
                float h10 = fmaxf(acc[nt][2] + el.x + rh.x, 0.0f);
                float h11 = fmaxf(acc[nt][3] + el.y + rh.y, 0.0f);
                if (head == 0){
                    const float2 w2 = *(const float2*)&s_w2e[c0];
                    eacc[0] = fmaf(h00, w2.x, fmaf(h01, w2.y, eacc[0]));
                    eacc[1] = fmaf(h10, w2.x, fmaf(h11, w2.y, eacc[1]));
                } else {
                    const ulonglong2* wp0 = (const ulonglong2*)&s_w2o[c0*8];
                    const ulonglong2* wp1 = (const ulonglong2*)&s_w2o[(c0 + 1)*8];
                    ulonglong2 wa = wp0[0], wb = wp0[1], wc = wp1[0], wd = wp1[1];
                    unsigned long long v00 = splat2(h00), v01 = splat2(h01);
                    unsigned long long v10 = splat2(h10), v11 = splat2(h11);
                    oacc[0][0] = fma2(v00, wa.x, oacc[0][0]); oacc[0][1] = fma2(v00, wa.y, oacc[0][1]);
                    oacc[0][2] = fma2(v00, wb.x, oacc[0][2]); oacc[0][3] = fma2(v00, wb.y, oacc[0][3]);
                    oacc[0][0] = fma2(v01, wc.x, oacc[0][0]); oacc[0][1] = fma2(v01, wc.y, oacc[0][1]);
                    oacc[0][2] = fma2(v01, wd.x, oacc[0][2]); oacc[0][3] = fma2(v01, wd.y, oacc[0][3]);
                    oacc[1][0] = fma2(v10, wa.x, oacc[1][0]); oacc[1][1] = fma2(v10, wa.y, oacc[1][1]);
                    oacc[1][2] = fma2(v10, wb.x, oacc[1][2]); oacc[1][3] = fma2(v10, wb.y, oacc[1][3]);
                    oacc[1][0] = fma2(v11, wc.x, oacc[1][0]); oacc[1][1] = fma2(v11, wc.y, oacc[1][1]);
                    oacc[1][2] = fma2(v11, wd.x, oacc[1][2]); oacc[1][3] = fma2(v11, wd.y, oacc[1][3]);
                }
            }
        }

        if (s == 1){
            #pragma unroll
            for (int rh = 0; rh < 2; rh++){
                float v = eacc[rh];
                v += __shfl_xor_sync(0xffffffffu, v, 1);
                v += __shfl_xor_sync(0xffffffffu, v, 2);
                eacc[rh] = v;
            }
            if ((lane & 3) == 0){
                float b2 = eh_b2[0];
                float v0 = eacc[0] + b2;
                float v1 = eacc[1] + b2;
                if (ig == jglo) v0 = -8.0f;
                if (ig == jghi) v1 = -8.0f;
                out[EDGE_OFF + b*NN*NN + ig*NN + jglo] = v0;
                out[EDGE_OFF + b*NN*NN + ig*NN + jghi] = v1;
            }
        }
        if (s == 3){
            #pragma unroll
            for (int rh = 0; rh < 2; rh++){
                float ov[8];
                #pragma unroll
                for (int v = 0; v < 4; v++){
                    float2 f = *reinterpret_cast<float2*>(&oacc[rh][v]);
                    float x = f.x, y = f.y;
                    x += __shfl_xor_sync(0xffffffffu, x, 1);
                    x += __shfl_xor_sync(0xffffffffu, x, 2);
                    y += __shfl_xor_sync(0xffffffffu, y, 1);
                    y += __shfl_xor_sync(0xffffffffu, y, 2);
                    ov[2*v] = x; ov[2*v+1] = y;
                }
                if ((lane & 3) == 0){
                    int jg = rh ? jghi : jglo;
                    float4* dst = (float4*)&out[OP_OFF + ((size_t)(b*NN*NN + ig*NN + jg))*NOPS];
                    dst[0] = make_float4(ov[0]+oh_b2[0], ov[1]+oh_b2[1], ov[2]+oh_b2[2], ov[3]+oh_b2[3]);
                    dst[1] = make_float4(ov[4]+oh_b2[4], ov[5]+oh_b2[5], ov[6]+oh_b2[6], ov[7]+oh_b2[7]);
                }
            }
        }
    }
}

// ---------------------------------------------------------------------------
// Launch
// ---------------------------------------------------------------------------
extern "C" void kernel_launch(void* const* d_in, const int* in_sizes, int n_in,
                              void* d_out, int out_size)
{
    const float* obs    = (const float*)d_in[0];
    const float* latent = (const float*)d_in[1];
    const float* query  = (const float*)d_in[2];
    const float* enc_w1 = (const float*)d_in[3];
    const float* enc_b1 = (const float*)d_in[4];
    const float* enc_w2 = (const float*)d_in[5];
    const float* enc_b2 = (const float*)d_in[6];
    const float* upd_w  = (const float*)d_in[7];
    const float* upd_b  = (const float*)d_in[8];
    const float* gru_wi = (const float*)d_in[9];
    const float* gru_bi = (const float*)d_in[10];
    const float* gru_wh = (const float*)d_in[11];
    const float* gru_bh = (const float*)d_in[12];
    const float* eh_w1  = (const float*)d_in[13];
    const float* eh_b1  = (const float*)d_in[14];
    const float* eh_w2  = (const float*)d_in[15];
    const float* eh_b2  = (const float*)d_in[16];
    const float* oh_w1  = (const float*)d_in[17];
    const float* oh_b1  = (const float*)d_in[18];
    const float* oh_w2  = (const float*)d_in[19];
    const float* oh_b2  = (const float*)d_in[20];
    const float* q_w    = (const float*)d_in[21];
    const float* q_b    = (const float*)d_in[22];
    const float* nh_w1  = (const float*)d_in[23];
    const float* nh_b1  = (const float*)d_in[24];
    const float* nh_w2  = (const float*)d_in[25];
    const float* nh_b2  = (const float*)d_in[26];

    float* out = (float*)d_out;

    static bool inited = false;
    if (!inited){
        cudaFuncSetAttribute(pairKernel, cudaFuncAttributeMaxDynamicSharedMemorySize, PAIR_SMEM);
        inited = true;
    }

    prepB<<<64, 256>>>(eh_w1, oh_w1);

    nodeKernel<<<256, 256>>>(obs, latent, query,
                             enc_w1, enc_b1, enc_w2, enc_b2,
                             upd_w, upd_b,
                             gru_wi, gru_bi, gru_wh, gru_bh,
                             q_w, q_b, nh_w1, nh_b1, nh_w2, nh_b2,
                             out + NEXT_OFF);

    elKernel<<<dim3(128, 4), 256>>>(eh_w1, eh_b1, oh_w1, oh_b1);

    pairKernel<<<dim3(16, 16, 4), 512, PAIR_SMEM>>>(eh_w2, eh_b2, oh_w2, oh_b2, out);
}

// round 9
// speedup vs baseline: 5.8622x; 1.3401x over previous
#include <cuda_runtime.h>
#include <cuda_bf16.h>
#include <cuda_fp16.h>
#include <math.h>
#include <stdint.h>

// ---------------------------------------------------------------------------
// Problem constants
// ---------------------------------------------------------------------------
#define BB   4
#define NN   256
#define OBS  64
#define QDIM 32
#define HH   256
#define DD   128
#define NOPS 8
#define QE   64
#define BN   (BB*NN)          // 1024 rows

#define EDGE_OFF 0
#define OP_OFF   (BB*NN*NN)                 // 262144
#define NEXT_OFF (OP_OFF + BB*NN*NN*NOPS)   // 2359296

// ---------------------------------------------------------------------------
// Device scratch
// ---------------------------------------------------------------------------
__device__ float g_lat[BN*DD];
__device__ float g_EL[BN*HH];
__device__ float g_ER[BN*HH];
__device__ float g_OL[BN*HH];
__device__ float g_OR[BN*HH];
// fp16 pair-head weights: [s(4)][n(128)][k(128)], s = head*2 + half
__device__ __half g_Bfp[4*128*128];
// fp16 op layer-2 weights: [half(2)][n(8)][k(128)]
__device__ __half g_w2of[2*8*128];

__device__ __forceinline__ float sigf(float x){ return 1.0f/(1.0f+expf(-x)); }

__device__ __forceinline__ uint32_t smem_u32(const void* p){
    uint32_t a;
    asm("{ .reg .u64 t; cvta.to.shared.u64 t, %1; cvt.u32.u64 %0, t; }"
        : "=r"(a) : "l"(p));
    return a;
}

__device__ __forceinline__ void ldsm4(uint32_t& r0, uint32_t& r1, uint32_t& r2,
                                      uint32_t& r3, uint32_t addr){
    asm volatile("ldmatrix.sync.aligned.m8n8.x4.shared.b16 {%0,%1,%2,%3}, [%4];"
                 : "=r"(r0), "=r"(r1), "=r"(r2), "=r"(r3) : "r"(addr));
}
__device__ __forceinline__ void ldsm2(uint32_t& r0, uint32_t& r1, uint32_t addr){
    asm volatile("ldmatrix.sync.aligned.m8n8.x2.shared.b16 {%0,%1}, [%2];"
                 : "=r"(r0), "=r"(r1) : "r"(addr));
}
__device__ __forceinline__ void mma16816(float* d, uint32_t a0, uint32_t a1,
                                         uint32_t a2, uint32_t a3,
                                         uint32_t b0, uint32_t b1){
    asm volatile(
        "mma.sync.aligned.m16n8k16.row.col.f32.f16.f16.f32 "
        "{%0,%1,%2,%3}, {%4,%5,%6,%7}, {%8,%9}, {%0,%1,%2,%3};"
        : "+f"(d[0]), "+f"(d[1]), "+f"(d[2]), "+f"(d[3])
        : "r"(a0), "r"(a1), "r"(a2), "r"(a3), "r"(b0), "r"(b1));
}
__device__ __forceinline__ uint32_t packh2(float a, float b){
    __half2 h = __floats2half2_rn(a, b);
    return *reinterpret_cast<uint32_t*>(&h);
}

// ---------------------------------------------------------------------------
// Kernel A: per-node pipeline. 4 rows/block, 256 blocks.
// ---------------------------------------------------------------------------
__global__ __launch_bounds__(256)
void nodeKernel(const float* __restrict__ obs, const float* __restrict__ latent,
                const float* __restrict__ query,
                const float* __restrict__ enc_w1, const float* __restrict__ enc_b1,
                const float* __restrict__ enc_w2, const float* __restrict__ enc_b2,
                const float* __restrict__ upd_w,  const float* __restrict__ upd_b,
                const float* __restrict__ gru_wi, const float* __restrict__ gru_bi,
                const float* __restrict__ gru_wh, const float* __restrict__ gru_bh,
                const float* __restrict__ q_w,    const float* __restrict__ q_b,
                const float* __restrict__ nh_w1,  const float* __restrict__ nh_b1,
                const float* __restrict__ nh_w2,  const float* __restrict__ nh_b2,
                float* __restrict__ out_next)
{
    __shared__ float s_obs[4*64];
    __shared__ float s_h1 [4*256];
    __shared__ float s_emb[4*256];
    __shared__ float s_gi [4*384];
    __shared__ float s_gh [4*384];

    const int t    = threadIdx.x;
    const int row0 = blockIdx.x * 4;

    s_obs[t] = obs[row0*64 + t];
    __syncthreads();

    {
        float acc[4];
        #pragma unroll
        for (int r=0;r<4;r++) acc[r] = enc_b1[t];
        #pragma unroll 4
        for (int k=0;k<64;k++){
            float w = enc_w1[k*256 + t];
            #pragma unroll
            for (int r=0;r<4;r++) acc[r] = fmaf(s_obs[r*64+k], w, acc[r]);
        }
        #pragma unroll
        for (int r=0;r<4;r++) s_h1[r*256+t] = fmaxf(acc[r], 0.0f);
    }
    __syncthreads();

    {
        float acc[4];
        #pragma unroll
        for (int r=0;r<4;r++) acc[r] = enc_b2[t];
        #pragma unroll 4
        for (int k=0;k<256;k++){
            float w = enc_w2[k*256 + t];
            #pragma unroll
            for (int r=0;r<4;r++) acc[r] = fmaf(s_h1[r*256+k], w, acc[r]);
        }
        __syncthreads();
        #pragma unroll
        for (int r=0;r<4;r++) s_emb[r*256+t] = fmaxf(acc[r], 0.0f);
    }
    __syncthreads();

    float* s_upd = s_h1;
    float* s_lat = s_h1 + 512;

    {
        const int o = t & 127;
        const int rbase = (t >> 7) * 2;
        float acc[2];
        #pragma unroll
        for (int rr=0;rr<2;rr++) acc[rr] = upd_b[o];
        #pragma unroll 4
        for (int k=0;k<256;k++){
            float w = upd_w[k*128 + o];
            #pragma unroll
            for (int rr=0;rr<2;rr++) acc[rr] = fmaf(s_emb[(rbase+rr)*256+k], w, acc[rr]);
        }
        #pragma unroll
        for (int rr=0;rr<2;rr++) s_upd[(rbase+rr)*128+o] = acc[rr];
    }
    for (int idx = t; idx < 512; idx += 256) s_lat[idx] = latent[row0*128 + idx];
    __syncthreads();

    for (int o = t; o < 384; o += 256){
        float ai[4], ah[4];
        #pragma unroll
        for (int r=0;r<4;r++){ ai[r] = gru_bi[o]; ah[r] = gru_bh[o]; }
        #pragma unroll 4
        for (int k=0;k<128;k++){
            float wi = gru_wi[k*384 + o];
            float wh = gru_wh[k*384 + o];
            #pragma unroll
            for (int r=0;r<4;r++){
                ai[r] = fmaf(s_upd[r*128+k], wi, ai[r]);
                ah[r] = fmaf(s_lat[r*128+k], wh, ah[r]);
            }
        }
        #pragma unroll
        for (int r=0;r<4;r++){ s_gi[r*384+o] = ai[r]; s_gh[r*384+o] = ah[r]; }
    }
    __syncthreads();

    for (int idx = t; idx < 512; idx += 256){
        int r = idx >> 7, d = idx & 127;
        float ir = s_gi[r*384 + d],  iz = s_gi[r*384 + 128 + d], inn = s_gi[r*384 + 256 + d];
        float hr = s_gh[r*384 + d],  hz = s_gh[r*384 + 128 + d], hn  = s_gh[r*384 + 256 + d];
        float rg = sigf(ir + hr);
        float zg = sigf(iz + hz);
        float nh = tanhf(inn + rg*hn);
        float lv = (1.0f - zg)*nh + zg*s_lat[idx];
        s_lat[idx] = lv;
        g_lat[row0*128 + idx] = lv;
    }
    __syncthreads();

    for (int idx = t; idx < 4*32; idx += 256) s_gi[idx] = query[row0*32 + idx];
    __syncthreads();
    {
        int r = t >> 6, o = t & 63;
        float acc = q_b[o];
        #pragma unroll
        for (int k=0;k<32;k++) acc = fmaf(s_gi[r*32+k], q_w[k*64+o], acc);
        s_obs[t] = fmaxf(acc, 0.0f);
    }
    __syncthreads();

    {
        float acc[4];
        #pragma unroll
        for (int r=0;r<4;r++) acc[r] = nh_b1[t];
        #pragma unroll 4
        for (int k=0;k<128;k++){
            float w = nh_w1[k*256 + t];
            #pragma unroll
            for (int r=0;r<4;r++) acc[r] = fmaf(s_lat[r*128+k], w, acc[r]);
        }
        #pragma unroll 4
        for (int k=0;k<256;k++){
            float w = nh_w1[(128+k)*256 + t];
            #pragma unroll
            for (int r=0;r<4;r++) acc[r] = fmaf(s_emb[r*256+k], w, acc[r]);
        }
        #pragma unroll 4
        for (int k=0;k<64;k++){
            float w = nh_w1[(384+k)*256 + t];
            #pragma unroll
            for (int r=0;r<4;r++) acc[r] = fmaf(s_obs[r*64+k], w, acc[r]);
        }
        #pragma unroll
        for (int r=0;r<4;r++) s_gh[r*256+t] = fmaxf(acc[r], 0.0f);
    }
    __syncthreads();

    {
        const int w = t >> 5, l = t & 31;
        if (w < 4){
            float p = 0.0f;
            for (int o = l; o < 256; o += 32) p = fmaf(s_gh[w*256 + o], nh_w2[o], p);
            #pragma unroll
            for (int off = 16; off; off >>= 1) p += __shfl_down_sync(0xffffffffu, p, off);
            if (l == 0) out_next[row0 + w] = p + nh_b2[0];
        }
    }
}

// ---------------------------------------------------------------------------
// Kernel B: EL/ER/OL/OR = lat @ W_slice (+bias). grid (128,4).
// ---------------------------------------------------------------------------
__global__ __launch_bounds__(256)
void elKernel(const float* __restrict__ eh_w1, const float* __restrict__ eh_b1,
              const float* __restrict__ oh_w1, const float* __restrict__ oh_b1)
{
    __shared__ float s_lat[8*128];
    const int t = threadIdx.x;
    const int row0 = blockIdx.x * 8;
    const int m = blockIdx.y;

    const float* W; const float* bias = nullptr; float* dst;
    if (m == 0)      { W = eh_w1;            bias = eh_b1; dst = g_EL; }
    else if (m == 1) { W = eh_w1 + 128*256;                dst = g_ER; }
    else if (m == 2) { W = oh_w1;            bias = oh_b1; dst = g_OL; }
    else             { W = oh_w1 + 128*256;                dst = g_OR; }

    for (int idx = t; idx < 1024; idx += 256) s_lat[idx] = g_lat[row0*128 + idx];
    __syncthreads();

    float acc[8];
    float bv = bias ? bias[t] : 0.0f;
    #pragma unroll
    for (int r=0;r<8;r++) acc[r] = bv;
    #pragma unroll 4
    for (int k=0;k<128;k++){
        float w = W[k*256 + t];
        #pragma unroll
        for (int r=0;r<8;r++) acc[r] = fmaf(s_lat[r*128+k], w, acc[r]);
    }
    #pragma unroll
    for (int r=0;r<8;r++) dst[(row0+r)*256 + t] = acc[r];
}

// ---------------------------------------------------------------------------
// Kernel P: pre-convert pair-head |diff| weights and op layer-2 to fp16.
// ---------------------------------------------------------------------------
__global__ __launch_bounds__(256)
void prepB(const float* __restrict__ eh_w1, const float* __restrict__ oh_w1,
           const float* __restrict__ oh_w2)
{
    int gi0 = blockIdx.x * 1024 + threadIdx.x;
    #pragma unroll
    for (int i = 0; i < 4; i++){
        int gi = gi0 + i*256;            // 0..65535 over (s,n,k)
        int s   = gi >> 14;
        int rem = gi & 16383;
        int n   = rem >> 7;
        int k   = rem & 127;
        int head = s >> 1, half = s & 1;
        const float* w = head ? oh_w1 : eh_w1;
        g_Bfp[(s*128 + n)*128 + k] = __float2half(w[(256 + k)*256 + half*128 + n]);
    }
    // w2o fp16: [half][n(8)][k(128)] = 2048 entries, block 0 only
    if (blockIdx.x == 0){
        for (int idx = threadIdx.x; idx < 2048; idx += 256){
            int half = idx >> 10, rem = idx & 1023;
            int n = rem >> 7, k = rem & 127;
            g_w2of[idx] = __float2half(oh_w2[(half*128 + k)*8 + n]);
        }
    }
}

// ---------------------------------------------------------------------------
// Kernel C: pair MLP. CTA tile 16i x 32j = 512 pairs, 512 threads, 16 warps.
// Warp w owns A rows [w*32, w*32+32) (i = i0+w, j = j0 + row). N=128 hidden
// per stage in 2 chunks of 64. Op layer-2 fused as a second mma (fp16 relu
// fragments x w2o fragments). Edge layer-2 scalar fma + quad shfl.
// ---------------------------------------------------------------------------
#define OFF_A    0                         // 512 rows * 256B = 131072
#define OFF_B    131072                    // 128 rows * 256B = 32768
#define OFF_ELI  163840                    // 16*130*4  = 8320
#define OFF_ERJ  172160                    // 32*130*4  = 16640
#define OFF_W2E  188800                    // 256*4 = 1024
#define OFF_W2O  189824                    // 8 rows * 272B = 2176
#define PAIR_SMEM 192000

__global__ __launch_bounds__(512, 1)
void pairKernel(const float* __restrict__ eh_w2, const float* __restrict__ eh_b2,
                const float* __restrict__ oh_b2,
                float* __restrict__ out)
{
    extern __shared__ __align__(16) char sm[];
    float* s_li  = (float*)(sm + OFF_ELI);   // prologue staging [16][128]
    float* s_lj  = (float*)(sm + OFF_ERJ);   // prologue staging [32][128]
    float* s_eli = (float*)(sm + OFF_ELI);   // per-stage [16][130]
    float* s_erj = (float*)(sm + OFF_ERJ);   // per-stage [32][130]
    float* s_w2e = (float*)(sm + OFF_W2E);   // [256] (both halves, loaded once)

    const uint32_t smb = smem_u32(sm);
    const int t    = threadIdx.x;
    const int wid  = t >> 5;
    const int lane = t & 31;
    const int b    = blockIdx.z;
    const int i0   = blockIdx.y * 16;
    const int j0   = blockIdx.x * 32;
    const int base = b * NN;

    // ---- prologue: stage lat rows + w2e ----
    for (int idx = t; idx < 2048; idx += 512) s_li[idx] = g_lat[(base + i0)*128 + idx];
    for (int idx = t; idx < 4096; idx += 512) s_lj[idx] = g_lat[(base + j0)*128 + idx];
    if (t < 256) s_w2e[t] = eh_w2[t];
    __syncthreads();

    // ---- build A = |li - lj| fp16, 512 rows x 256B, XOR swizzle ----
    for (int c = t; c < 8192; c += 512){
        int p = c >> 4, kg = c & 15;          // p: pair row, kg: 16B chunk
        int il = p >> 5, jl = p & 31;
        const float4* li4 = (const float4*)&s_li[il*128 + kg*8];
        const float4* lj4 = (const float4*)&s_lj[jl*128 + kg*8];
        float4 x0 = li4[0], x1 = li4[1], y0 = lj4[0], y1 = lj4[1];
        float a[8] = { fabsf(x0.x-y0.x), fabsf(x0.y-y0.y), fabsf(x0.z-y0.z), fabsf(x0.w-y0.w),
                       fabsf(x1.x-y1.x), fabsf(x1.y-y1.y), fabsf(x1.z-y1.z), fabsf(x1.w-y1.w) };
        uint32_t hp[4];
        #pragma unroll
        for (int q = 0; q < 4; q++) hp[q] = packh2(a[2*q], a[2*q+1]);
        uint32_t boff = (uint32_t)(p*256 + ((kg ^ (p & 7)) << 4));
        *(uint4*)(sm + OFF_A + boff) = make_uint4(hp[0],hp[1],hp[2],hp[3]);
    }

    // ldmatrix geometry
    const uint32_t sw    = (uint32_t)(lane & 7);
    const uint32_t aBase0 = smb + OFF_A
        + (uint32_t)(wid*32 + (lane & 7) + ((lane >> 3) & 1)*8) * 256;
    const uint32_t aBase1 = aBase0 + 16*256;
    const uint32_t kbitA = (uint32_t)((lane >> 4) & 1);
    const uint32_t bBase = smb + OFF_B
        + (uint32_t)((lane & 7) + ((lane >> 4) & 1)*8) * 256;
    const uint32_t kbitB = (uint32_t)((lane >> 3) & 1);
    const uint32_t wbBase = smb + OFF_W2O + (uint32_t)(lane & 7)*272
        + (uint32_t)((lane >> 3) & 1)*16;

    // epilogue geometry: thread owns rows r0,r0+8 (mb0), r0+16,r0+24 (mb1)
    const int r0  = lane >> 2;
    const int cq  = 2*(lane & 3);
    const int ig  = i0 + wid;

    float eacc[4] = {0.0f, 0.0f, 0.0f, 0.0f};
    float opA[4] = {0.0f, 0.0f, 0.0f, 0.0f};
    float opB[4] = {0.0f, 0.0f, 0.0f, 0.0f};

    for (int s = 0; s < 4; s++){
        const int head = s >> 1, half = s & 1;
        __syncthreads();     // A-build done (s=0) / prev stage epilogue done

        // stage B fp16 (swizzled)
        const __half* srcB = &g_Bfp[(size_t)s*16384];
        for (int idx = t; idx < 2048; idx += 512){
            int n = idx >> 4, kg = idx & 15;
            uint4 v = *(const uint4*)(srcB + n*128 + kg*8);
            *(uint4*)(sm + OFF_B + n*256 + ((kg ^ (n & 7)) << 4)) = v;
        }
        // stage EL (16 rows) / ER (32 rows)
        const float* gl = head ? g_OL : g_EL;
        const float* gr = head ? g_OR : g_ER;
        for (int idx = t; idx < 2048; idx += 512){
            int r = idx >> 7, c = idx & 127;
            s_eli[r*130 + c] = gl[(base + i0 + r)*256 + half*128 + c];
        }
        for (int idx = t; idx < 4096; idx += 512){
            int r = idx >> 7, c = idx & 127;
            s_erj[r*130 + c] = gr[(base + j0 + r)*256 + half*128 + c];
        }
        // stage w2o fp16 for this half (op head only): [8][128] -> 272B rows
        if (head == 1 && t < 512){
            int n = t >> 6, kp = t & 63;
            uint32_t v = *(const uint32_t*)&g_w2of[half*1024 + n*128 + kp*2];
            *(uint32_t*)(sm + OFF_W2O + n*272 + kp*4) = v;
        }
        __syncthreads();

        #pragma unroll
        for (int chunk = 0; chunk < 2; chunk++){
            float acc0[8][4], acc1[8][4];
            #pragma unroll
            for (int nt=0;nt<8;nt++)
                #pragma unroll
                for (int v=0;v<4;v++){ acc0[nt][v] = 0.0f; acc1[nt][v] = 0.0f; }

            #pragma unroll
            for (int ks = 0; ks < 8; ks++){
                const uint32_t aoff = ((((uint32_t)(2*ks) + kbitA) ^ sw) << 4);
                uint32_t p0,p1,p2,p3, q0,q1,q2,q3;
                ldsm4(p0,p1,p2,p3, aBase0 + aoff);
                ldsm4(q0,q1,q2,q3, aBase1 + aoff);
                const uint32_t bch = ((((uint32_t)(2*ks) + kbitB) ^ sw) << 4);
                #pragma unroll
                for (int ntp = 0; ntp < 4; ntp++){
                    uint32_t baddr = bBase + (uint32_t)(chunk*64 + ntp*16)*256 + bch;
                    uint32_t b0,b1,b2,b3;
                    ldsm4(b0,b1,b2,b3, baddr);
                    mma16816(acc0[2*ntp],   p0,p1,p2,p3, b0,b1);
                    mma16816(acc0[2*ntp+1], p0,p1,p2,p3, b2,b3);
                    mma16816(acc1[2*ntp],   q0,q1,q2,q3, b0,b1);
                    mma16816(acc1[2*ntp+1], q0,q1,q2,q3, b2,b3);
                }
            }

            // ---- epilogue for this 64-col chunk ----
            #pragma unroll
            for (int qf = 0; qf < 4; qf++){
                uint32_t fa[4], fb[4];
                #pragma unroll
                for (int e = 0; e < 2; e++){
                    const int nt = qf*2 + e;
                    const int c0 = chunk*64 + nt*8 + cq;
                    const float2 el = *(const float2*)&s_eli[wid*130 + c0];
                    const float2 e0 = *(const float2*)&s_erj[r0*130 + c0];
                    const float2 e1 = *(const float2*)&s_erj[(r0+8)*130 + c0];
                    const float2 e2 = *(const float2*)&s_erj[(r0+16)*130 + c0];
                    const float2 e3 = *(const float2*)&s_erj[(r0+24)*130 + c0];
                    float h00 = fmaxf(acc0[nt][0] + el.x + e0.x, 0.0f);
                    float h01 = fmaxf(acc0[nt][1] + el.y + e0.y, 0.0f);
                    float h10 = fmaxf(acc0[nt][2] + el.x + e1.x, 0.0f);
                    float h11 = fmaxf(acc0[nt][3] + el.y + e1.y, 0.0f);
                    float h20 = fmaxf(acc1[nt][0] + el.x + e2.x, 0.0f);
                    float h21 = fmaxf(acc1[nt][1] + el.y + e2.y, 0.0f);
                    float h30 = fmaxf(acc1[nt][2] + el.x + e3.x, 0.0f);
                    float h31 = fmaxf(acc1[nt][3] + el.y + e3.y, 0.0f);
                    if (head == 0){
                        const float2 w2 = *(const float2*)&s_w2e[half*128 + c0];
                        eacc[0] = fmaf(h00, w2.x, fmaf(h01, w2.y, eacc[0]));
                        eacc[1] = fmaf(h10, w2.x, fmaf(h11, w2.y, eacc[1]));
                        eacc[2] = fmaf(h20, w2.x, fmaf(h21, w2.y, eacc[2]));
                        eacc[3] = fmaf(h30, w2.x, fmaf(h31, w2.y, eacc[3]));
                    } else {
                        fa[e*2]   = packh2(h00, h01);
                        fa[e*2+1] = packh2(h10, h11);
                        fb[e*2]   = packh2(h20, h21);
                        fb[e*2+1] = packh2(h30, h31);
                    }
                }
                if (head == 1){
                    uint32_t wb0, wb1;
                    ldsm2(wb0, wb1, wbBase + (uint32_t)(chunk*128 + qf*32));
                    mma16816(opA, fa[0],fa[1],fa[2],fa[3], wb0, wb1);
                    mma16816(opB, fb[0],fb[1],fb[2],fb[3], wb0, wb1);
                }
            }
        }

        if (s == 1){
            #pragma unroll
            for (int rh = 0; rh < 4; rh++){
                float v = eacc[rh];
                v += __shfl_xor_sync(0xffffffffu, v, 1);
                v += __shfl_xor_sync(0xffffffffu, v, 2);
                eacc[rh] = v;
            }
            if ((lane & 3) == 0){
                float b2 = eh_b2[0];
                #pragma unroll
                for (int rh = 0; rh < 4; rh++){
                    int jg = j0 + r0 + rh*8;
                    float v = eacc[rh] + b2;
                    if (ig == jg) v = -8.0f;
                    out[EDGE_OFF + b*NN*NN + ig*NN + jg] = v;
                }
            }
        }
    }

    // ---- op output: C layout rows r0,r0+8 (opA), r0+16,r0+24 (opB) ----
    {
        const float bo0 = oh_b2[cq], bo1 = oh_b2[cq + 1];
        #pragma unroll
        for (int mb = 0; mb < 2; mb++){
            const float* oc = mb ? opB : opA;
            #pragma unroll
            for (int rr = 0; rr < 2; rr++){
                int jg = j0 + r0 + mb*16 + rr*8;
                float2* dst = (float2*)&out[OP_OFF
                    + ((size_t)(b*NN*NN + ig*NN + jg))*NOPS + cq];
                *dst = make_float2(oc[rr*2] + bo0, oc[rr*2+1] + bo1);
            }
        }
    }
}

// ---------------------------------------------------------------------------
// Launch
// ---------------------------------------------------------------------------
extern "C" void kernel_launch(void* const* d_in, const int* in_sizes, int n_in,
                              void* d_out, int out_size)
{
    const float* obs    = (const float*)d_in[0];
    const float* latent = (const float*)d_in[1];
    const float* query  = (const float*)d_in[2];
    const float* enc_w1 = (const float*)d_in[3];
    const float* enc_b1 = (const float*)d_in[4];
    const float* enc_w2 = (const float*)d_in[5];
    const float* enc_b2 = (const float*)d_in[6];
    const float* upd_w  = (const float*)d_in[7];
    const float* upd_b  = (const float*)d_in[8];
    const float* gru_wi = (const float*)d_in[9];
    const float* gru_bi = (const float*)d_in[10];
    const float* gru_wh = (const float*)d_in[11];
    const float* gru_bh = (const float*)d_in[12];
    const float* eh_w1  = (const float*)d_in[13];
    const float* eh_b1  = (const float*)d_in[14];
    const float* eh_w2  = (const float*)d_in[15];
    const float* eh_b2  = (const float*)d_in[16];
    const float* oh_w1  = (const float*)d_in[17];
    const float* oh_b1  = (const float*)d_in[18];
    const float* oh_w2  = (const float*)d_in[19];
    const float* oh_b2  = (const float*)d_in[20];
    const float* q_w    = (const float*)d_in[21];
    const float* q_b    = (const float*)d_in[22];
    const float* nh_w1  = (const float*)d_in[23];
    const float* nh_b1  = (const float*)d_in[24];
    const float* nh_w2  = (const float*)d_in[25];
    const float* nh_b2  = (const float*)d_in[26];

    float* out = (float*)d_out;

    static bool inited = false;
    if (!inited){
        cudaFuncSetAttribute(pairKernel, cudaFuncAttributeMaxDynamicSharedMemorySize, PAIR_SMEM);
        inited = true;
    }

    prepB<<<64, 256>>>(eh_w1, oh_w1, oh_w2);

    nodeKernel<<<256, 256>>>(obs, latent, query,
                             enc_w1, enc_b1, enc_w2, enc_b2,
                             upd_w, upd_b,
                             gru_wi, gru_bi, gru_wh, gru_bh,
                             q_w, q_b, nh_w1, nh_b1, nh_w2, nh_b2,
                             out + NEXT_OFF);

    elKernel<<<dim3(128, 4), 256>>>(eh_w1, eh_b1, oh_w1, oh_b1);

    pairKernel<<<dim3(8, 16, 4), 512, PAIR_SMEM>>>(eh_w2, eh_b2, oh_b2, out);
}

// round 10
// speedup vs baseline: 7.7991x; 1.3304x over previous
#include <cuda_runtime.h>
#include <cuda_bf16.h>
#include <cuda_fp16.h>
#include <math.h>
#include <stdint.h>

// ---------------------------------------------------------------------------
// Problem constants
// ---------------------------------------------------------------------------
#define BB   4
#define NN   256
#define OBS  64
#define QDIM 32
#define HH   256
#define DD   128
#define NOPS 8
#define QE   64
#define BN   (BB*NN)          // 1024 rows

#define EDGE_OFF 0
#define OP_OFF   (BB*NN*NN)                 // 262144
#define NEXT_OFF (OP_OFF + BB*NN*NN*NOPS)   // 2359296

// ---------------------------------------------------------------------------
// Device scratch
// ---------------------------------------------------------------------------
__device__ float g_lat[BN*DD];
__device__ __half g_ELh[BN*HH];
__device__ __half g_ERh[BN*HH];
__device__ __half g_OLh[BN*HH];
__device__ __half g_ORh[BN*HH];
// fp16 pair-head weights: [s(4)][n(128)][k(128)], s = head*2 + half
__device__ __half g_Bfp[4*128*128];
// fp16 op layer-2 weights: [half(2)][n(8)][k(128)]
__device__ __half g_w2of[2*8*128];

__device__ __forceinline__ float sigf(float x){ return 1.0f/(1.0f+expf(-x)); }

__device__ __forceinline__ uint32_t smem_u32(const void* p){
    uint32_t a;
    asm("{ .reg .u64 t; cvta.to.shared.u64 t, %1; cvt.u32.u64 %0, t; }"
        : "=r"(a) : "l"(p));
    return a;
}

__device__ __forceinline__ void ldsm4(uint32_t& r0, uint32_t& r1, uint32_t& r2,
                                      uint32_t& r3, uint32_t addr){
    asm volatile("ldmatrix.sync.aligned.m8n8.x4.shared.b16 {%0,%1,%2,%3}, [%4];"
                 : "=r"(r0), "=r"(r1), "=r"(r2), "=r"(r3) : "r"(addr));
}
__device__ __forceinline__ void ldsm2(uint32_t& r0, uint32_t& r1, uint32_t addr){
    asm volatile("ldmatrix.sync.aligned.m8n8.x2.shared.b16 {%0,%1}, [%2];"
                 : "=r"(r0), "=r"(r1) : "r"(addr));
}
__device__ __forceinline__ void mma16816(float* d, uint32_t a0, uint32_t a1,
                                         uint32_t a2, uint32_t a3,
                                         uint32_t b0, uint32_t b1){
    asm volatile(
        "mma.sync.aligned.m16n8k16.row.col.f32.f16.f16.f32 "
        "{%0,%1,%2,%3}, {%4,%5,%6,%7}, {%8,%9}, {%0,%1,%2,%3};"
        : "+f"(d[0]), "+f"(d[1]), "+f"(d[2]), "+f"(d[3])
        : "r"(a0), "r"(a1), "r"(a2), "r"(a3), "r"(b0), "r"(b1));
}
__device__ __forceinline__ uint32_t packh2(float a, float b){
    __half2 h = __floats2half2_rn(a, b);
    return *reinterpret_cast<uint32_t*>(&h);
}

// ---------------------------------------------------------------------------
// Kernel A: per-node pipeline. 4 rows/block, 256 blocks.
// ---------------------------------------------------------------------------
__global__ __launch_bounds__(256)
void nodeKernel(const float* __restrict__ obs, const float* __restrict__ latent,
                const float* __restrict__ query,
                const float* __restrict__ enc_w1, const float* __restrict__ enc_b1,
                const float* __restrict__ enc_w2, const float* __restrict__ enc_b2,
                const float* __restrict__ upd_w,  const float* __restrict__ upd_b,
                const float* __restrict__ gru_wi, const float* __restrict__ gru_bi,
                const float* __restrict__ gru_wh, const float* __restrict__ gru_bh,
                const float* __restrict__ q_w,    const float* __restrict__ q_b,
                const float* __restrict__ nh_w1,  const float* __restrict__ nh_b1,
                const float* __restrict__ nh_w2,  const float* __restrict__ nh_b2,
                float* __restrict__ out_next)
{
    __shared__ float s_obs[4*64];
    __shared__ float s_h1 [4*256];
    __shared__ float s_emb[4*256];
    __shared__ float s_gi [4*384];
    __shared__ float s_gh [4*384];

    const int t    = threadIdx.x;
    const int row0 = blockIdx.x * 4;

    s_obs[t] = obs[row0*64 + t];
    __syncthreads();

    {
        float acc[4];
        #pragma unroll
        for (int r=0;r<4;r++) acc[r] = enc_b1[t];
        #pragma unroll 4
        for (int k=0;k<64;k++){
            float w = enc_w1[k*256 + t];
            #pragma unroll
            for (int r=0;r<4;r++) acc[r] = fmaf(s_obs[r*64+k], w, acc[r]);
        }
        #pragma unroll
        for (int r=0;r<4;r++) s_h1[r*256+t] = fmaxf(acc[r], 0.0f);
    }
    __syncthreads();

    {
        float acc[4];
        #pragma unroll
        for (int r=0;r<4;r++) acc[r] = enc_b2[t];
        #pragma unroll 4
        for (int k=0;k<256;k++){
            float w = enc_w2[k*256 + t];
            #pragma unroll
            for (int r=0;r<4;r++) acc[r] = fmaf(s_h1[r*256+k], w, acc[r]);
        }
        __syncthreads();
        #pragma unroll
        for (int r=0;r<4;r++) s_emb[r*256+t] = fmaxf(acc[r], 0.0f);
    }
    __syncthreads();

    float* s_upd = s_h1;
    float* s_lat = s_h1 + 512;

    {
        const int o = t & 127;
        const int rbase = (t >> 7) * 2;
        float acc[2];
        #pragma unroll
        for (int rr=0;rr<2;rr++) acc[rr] = upd_b[o];
        #pragma unroll 4
        for (int k=0;k<256;k++){
            float w = upd_w[k*128 + o];
            #pragma unroll
            for (int rr=0;rr<2;rr++) acc[rr] = fmaf(s_emb[(rbase+rr)*256+k], w, acc[rr]);
        }
        #pragma unroll
        for (int rr=0;rr<2;rr++) s_upd[(rbase+rr)*128+o] = acc[rr];
    }
    for (int idx = t; idx < 512; idx += 256) s_lat[idx] = latent[row0*128 + idx];
    __syncthreads();

    for (int o = t; o < 384; o += 256){
        float ai[4], ah[4];
        #pragma unroll
        for (int r=0;r<4;r++){ ai[r] = gru_bi[o]; ah[r] = gru_bh[o]; }
        #pragma unroll 4
        for (int k=0;k<128;k++){
            float wi = gru_wi[k*384 + o];
            float wh = gru_wh[k*384 + o];
            #pragma unroll
            for (int r=0;r<4;r++){
                ai[r] = fmaf(s_upd[r*128+k], wi, ai[r]);
                ah[r] = fmaf(s_lat[r*128+k], wh, ah[r]);
            }
        }
        #pragma unroll
        for (int r=0;r<4;r++){ s_gi[r*384+o] = ai[r]; s_gh[r*384+o] = ah[r]; }
    }
    __syncthreads();

    for (int idx = t; idx < 512; idx += 256){
        int r = idx >> 7, d = idx & 127;
        float ir = s_gi[r*384 + d],  iz = s_gi[r*384 + 128 + d], inn = s_gi[r*384 + 256 + d];
        float hr = s_gh[r*384 + d],  hz = s_gh[r*384 + 128 + d], hn  = s_gh[r*384 + 256 + d];
        float rg = sigf(ir + hr);
        float zg = sigf(iz + hz);
        float nh = tanhf(inn + rg*hn);
        float lv = (1.0f - zg)*nh + zg*s_lat[idx];
        s_lat[idx] = lv;
        g_lat[row0*128 + idx] = lv;
    }
    __syncthreads();

    for (int idx = t; idx < 4*32; idx += 256) s_gi[idx] = query[row0*32 + idx];
    __syncthreads();
    {
        int r = t >> 6, o = t & 63;
        float acc = q_b[o];
        #pragma unroll
        for (int k=0;k<32;k++) acc = fmaf(s_gi[r*32+k], q_w[k*64+o], acc);
        s_obs[t] = fmaxf(acc, 0.0f);
    }
    __syncthreads();

    {
        float acc[4];
        #pragma unroll
        for (int r=0;r<4;r++) acc[r] = nh_b1[t];
        #pragma unroll 4
        for (int k=0;k<128;k++){
            float w = nh_w1[k*256 + t];
            #pragma unroll
            for (int r=0;r<4;r++) acc[r] = fmaf(s_lat[r*128+k], w, acc[r]);
        }
        #pragma unroll 4
        for (int k=0;k<256;k++){
            float w = nh_w1[(128+k)*256 + t];
            #pragma unroll
            for (int r=0;r<4;r++) acc[r] = fmaf(s_emb[r*256+k], w, acc[r]);
        }
        #pragma unroll 4
        for (int k=0;k<64;k++){
            float w = nh_w1[(384+k)*256 + t];
            #pragma unroll
            for (int r=0;r<4;r++) acc[r] = fmaf(s_obs[r*64+k], w, acc[r]);
        }
        #pragma unroll
        for (int r=0;r<4;r++) s_gh[r*256+t] = fmaxf(acc[r], 0.0f);
    }
    __syncthreads();

    {
        const int w = t >> 5, l = t & 31;
        if (w < 4){
            float p = 0.0f;
            for (int o = l; o < 256; o += 32) p = fmaf(s_gh[w*256 + o], nh_w2[o], p);
            #pragma unroll
            for (int off = 16; off; off >>= 1) p += __shfl_down_sync(0xffffffffu, p, off);
            if (l == 0) out_next[row0 + w] = p + nh_b2[0];
        }
    }
}

// ---------------------------------------------------------------------------
// Kernel B: EL/ER/OL/OR = lat @ W_slice (+bias), stored fp16. grid (128,4).
// ---------------------------------------------------------------------------
__global__ __launch_bounds__(256)
void elKernel(const float* __restrict__ eh_w1, const float* __restrict__ eh_b1,
              const float* __restrict__ oh_w1, const float* __restrict__ oh_b1)
{
    __shared__ float s_lat[8*128];
    const int t = threadIdx.x;
    const int row0 = blockIdx.x * 8;
    const int m = blockIdx.y;

    const float* W; const float* bias = nullptr; __half* dst;
    if (m == 0)      { W = eh_w1;            bias = eh_b1; dst = g_ELh; }
    else if (m == 1) { W = eh_w1 + 128*256;                dst = g_ERh; }
    else if (m == 2) { W = oh_w1;            bias = oh_b1; dst = g_OLh; }
    else             { W = oh_w1 + 128*256;                dst = g_ORh; }

    for (int idx = t; idx < 1024; idx += 256) s_lat[idx] = g_lat[row0*128 + idx];
    __syncthreads();

    float acc[8];
    float bv = bias ? bias[t] : 0.0f;
    #pragma unroll
    for (int r=0;r<8;r++) acc[r] = bv;
    #pragma unroll 4
    for (int k=0;k<128;k++){
        float w = W[k*256 + t];
        #pragma unroll
        for (int r=0;r<8;r++) acc[r] = fmaf(s_lat[r*128+k], w, acc[r]);
    }
    #pragma unroll
    for (int r=0;r<8;r++) dst[(row0+r)*256 + t] = __float2half(acc[r]);
}

// ---------------------------------------------------------------------------
// Kernel P: pre-convert pair-head |diff| weights and op layer-2 to fp16.
// ---------------------------------------------------------------------------
__global__ __launch_bounds__(256)
void prepB(const float* __restrict__ eh_w1, const float* __restrict__ oh_w1,
           const float* __restrict__ oh_w2)
{
    int gi0 = blockIdx.x * 1024 + threadIdx.x;
    #pragma unroll
    for (int i = 0; i < 4; i++){
        int gi = gi0 + i*256;            // 0..65535 over (s,n,k)
        int s   = gi >> 14;
        int rem = gi & 16383;
        int n   = rem >> 7;
        int k   = rem & 127;
        int head = s >> 1, half = s & 1;
        const float* w = head ? oh_w1 : eh_w1;
        g_Bfp[(s*128 + n)*128 + k] = __float2half(w[(256 + k)*256 + half*128 + n]);
    }
    // w2o fp16: [half][n(8)][k(128)] = 2048 entries, block 0 only
    if (blockIdx.x == 0){
        for (int idx = threadIdx.x; idx < 2048; idx += 256){
            int half = idx >> 10, rem = idx & 1023;
            int n = rem >> 7, k = rem & 127;
            g_w2of[idx] = __float2half(oh_w2[(half*128 + k)*8 + n]);
        }
    }
}

// ---------------------------------------------------------------------------
// Kernel C: pair MLP. CTA tile 8i x 32j = 256 pairs, 256 threads, 8 warps.
// TWO CTAs per SM (smem 112.4KB, regs capped at 128) so barriers/staging of
// one CTA overlap with the other's mainloop. Warp w owns A rows [w*32,w*32+32)
// (i = i0+w, j = j0+row). N=128 hidden per stage in 2 chunks of 64. EL/ER
// tables fp16 (stride 136 halfs, conflict-free LDS.32). Op layer-2 fused mma.
// ---------------------------------------------------------------------------
#define OFF_A    0                         // 256 rows * 256B = 65536
#define OFF_B    65536                     // 128 rows * 256B = 32768
#define OFF_ELI  98304                     // 8*136*2  = 2176
#define OFF_ERJ  100480                    // 32*136*2 = 8704
#define OFF_W2E  109184                    // 256*4 = 1024
#define OFF_W2O  110208                    // 8 rows * 272B = 2176
#define PAIR_SMEM 112384

__global__ __launch_bounds__(256, 2)
void pairKernel(const float* __restrict__ eh_w2, const float* __restrict__ eh_b2,
                const float* __restrict__ oh_b2,
                float* __restrict__ out)
{
    extern __shared__ __align__(16) char sm[];
    float*  s_li   = (float*)(sm + OFF_B);          // prologue staging [8][128]
    float*  s_lj   = (float*)(sm + OFF_B + 4096);   // prologue staging [32][128]
    __half* s_eli  = (__half*)(sm + OFF_ELI);       // per-stage [8][136]
    __half* s_erj  = (__half*)(sm + OFF_ERJ);       // per-stage [32][136]
    float*  s_w2e  = (float*)(sm + OFF_W2E);        // [256] (both halves)

    const uint32_t smb = smem_u32(sm);
    const int t    = threadIdx.x;
    const int wid  = t >> 5;
    const int lane = t & 31;
    const int b    = blockIdx.z;
    const int i0   = blockIdx.y * 8;
    const int j0   = blockIdx.x * 32;
    const int base = b * NN;

    // ---- prologue: stage lat rows (into B region) + w2e ----
    for (int idx = t; idx < 1024; idx += 256) s_li[idx] = g_lat[(base + i0)*128 + idx];
    for (int idx = t; idx < 4096; idx += 256) s_lj[idx] = g_lat[(base + j0)*128 + idx];
    if (t < 256) s_w2e[t] = eh_w2[t];
    __syncthreads();

    // ---- build A = |li - lj| fp16, 256 rows x 256B, XOR swizzle ----
    for (int c = t; c < 4096; c += 256){
        int p = c >> 4, kg = c & 15;          // p: pair row, kg: 16B chunk
        int il = p >> 5, jl = p & 31;
        const float4* li4 = (const float4*)&s_li[il*128 + kg*8];
        const float4* lj4 = (const float4*)&s_lj[jl*128 + kg*8];
        float4 x0 = li4[0], x1 = li4[1], y0 = lj4[0], y1 = lj4[1];
        float a[8] = { fabsf(x0.x-y0.x), fabsf(x0.y-y0.y), fabsf(x0.z-y0.z), fabsf(x0.w-y0.w),
                       fabsf(x1.x-y1.x), fabsf(x1.y-y1.y), fabsf(x1.z-y1.z), fabsf(x1.w-y1.w) };
        uint32_t hp[4];
        #pragma unroll
        for (int q = 0; q < 4; q++) hp[q] = packh2(a[2*q], a[2*q+1]);
        uint32_t boff = (uint32_t)(p*256 + ((kg ^ (p & 7)) << 4));
        *(uint4*)(sm + OFF_A + boff) = make_uint4(hp[0],hp[1],hp[2],hp[3]);
    }

    // ldmatrix geometry
    const uint32_t sw    = (uint32_t)(lane & 7);
    const uint32_t aBase0 = smb + OFF_A
        + (uint32_t)(wid*32 + (lane & 7) + ((lane >> 3) & 1)*8) * 256;
    const uint32_t aBase1 = aBase0 + 16*256;
    const uint32_t kbitA = (uint32_t)((lane >> 4) & 1);
    const uint32_t bBase = smb + OFF_B
        + (uint32_t)((lane & 7) + ((lane >> 4) & 1)*8) * 256;
    const uint32_t kbitB = (uint32_t)((lane >> 3) & 1);
    const uint32_t wbBase = smb + OFF_W2O + (uint32_t)(lane & 7)*272
        + (uint32_t)((lane >> 3) & 1)*16;

    // epilogue geometry: thread owns rows r0,r0+8 (mb0), r0+16,r0+24 (mb1)
    const int r0  = lane >> 2;
    const int cq  = 2*(lane & 3);
    const int ig  = i0 + wid;

    float eacc[4] = {0.0f, 0.0f, 0.0f, 0.0f};
    float opA[4] = {0.0f, 0.0f, 0.0f, 0.0f};
    float opB[4] = {0.0f, 0.0f, 0.0f, 0.0f};

    for (int s = 0; s < 4; s++){
        const int head = s >> 1, half = s & 1;
        __syncthreads();     // A-build done (s=0) / prev stage epilogue done

        // stage B fp16 (swizzled)
        const __half* srcB = &g_Bfp[(size_t)s*16384];
        for (int idx = t; idx < 2048; idx += 256){
            int n = idx >> 4, kg = idx & 15;
            uint4 v = *(const uint4*)(srcB + n*128 + kg*8);
            *(uint4*)(sm + OFF_B + n*256 + ((kg ^ (n & 7)) << 4)) = v;
        }
        // stage EL (8 rows) / ER (32 rows), fp16, 16B chunks
        const __half* gl = head ? g_OLh : g_ELh;
        const __half* gr = head ? g_ORh : g_ERh;
        for (int idx = t; idx < 128; idx += 256){
            int r = idx >> 4, kg = idx & 15;
            uint4 v = *(const uint4*)(gl + (base + i0 + r)*256 + half*128 + kg*8);
            *(uint4*)(sm + OFF_ELI + r*272 + kg*16) = v;
        }
        for (int idx = t; idx < 512; idx += 256){
            int r = idx >> 4, kg = idx & 15;
            uint4 v = *(const uint4*)(gr + (base + j0 + r)*256 + half*128 + kg*8);
            *(uint4*)(sm + OFF_ERJ + r*272 + kg*16) = v;
        }
        // stage w2o fp16 for this half (op head only): [8][128] -> 272B rows
        if (head == 1){
            for (int idx = t; idx < 512; idx += 256){
                int n = idx >> 6, kp = idx & 63;
                uint32_t v = *(const uint32_t*)&g_w2of[half*1024 + n*128 + kp*2];
                *(uint32_t*)(sm + OFF_W2O + n*272 + kp*4) = v;
            }
        }
        __syncthreads();

        #pragma unroll
        for (int chunk = 0; chunk < 2; chunk++){
            float acc0[8][4], acc1[8][4];
            #pragma unroll
            for (int nt=0;nt<8;nt++)
                #pragma unroll
                for (int v=0;v<4;v++){ acc0[nt][v] = 0.0f; acc1[nt][v] = 0.0f; }

            #pragma unroll
            for (int ks = 0; ks < 8; ks++){
                const uint32_t aoff = ((((uint32_t)(2*ks) + kbitA) ^ sw) << 4);
                uint32_t p0,p1,p2,p3, q0,q1,q2,q3;
                ldsm4(p0,p1,p2,p3, aBase0 + aoff);
                ldsm4(q0,q1,q2,q3, aBase1 + aoff);
                const uint32_t bch = ((((uint32_t)(2*ks) + kbitB) ^ sw) << 4);
                #pragma unroll
                for (int ntp = 0; ntp < 4; ntp++){
                    uint32_t baddr = bBase + (uint32_t)(chunk*64 + ntp*16)*256 + bch;
                    uint32_t b0,b1,b2,b3;
                    ldsm4(b0,b1,b2,b3, baddr);
                    mma16816(acc0[2*ntp],   p0,p1,p2,p3, b0,b1);
                    mma16816(acc0[2*ntp+1], p0,p1,p2,p3, b2,b3);
                    mma16816(acc1[2*ntp],   q0,q1,q2,q3, b0,b1);
                    mma16816(acc1[2*ntp+1], q0,q1,q2,q3, b2,b3);
                }
            }

            // ---- epilogue for this 64-col chunk (fp16 tables, f32 math) ----
            #pragma unroll
            for (int qf = 0; qf < 4; qf++){
                uint32_t fa[4], fb[4];
                #pragma unroll
                for (int e = 0; e < 2; e++){
                    const int nt = qf*2 + e;
                    const int c0 = chunk*64 + nt*8 + cq;
                    float2 el = __half22float2(*(const __half2*)&s_eli[wid*136 + c0]);
                    float2 e0 = __half22float2(*(const __half2*)&s_erj[r0*136 + c0]);
                    float2 e1 = __half22float2(*(const __half2*)&s_erj[(r0+8)*136 + c0]);
                    float2 e2 = __half22float2(*(const __half2*)&s_erj[(r0+16)*136 + c0]);
                    float2 e3 = __half22float2(*(const __half2*)&s_erj[(r0+24)*136 + c0]);
                    float h00 = fmaxf(acc0[nt][0] + el.x + e0.x, 0.0f);
                    float h01 = fmaxf(acc0[nt][1] + el.y + e0.y, 0.0f);
                    float h10 = fmaxf(acc0[nt][2] + el.x + e1.x, 0.0f);
                    float h11 = fmaxf(acc0[nt][3] + el.y + e1.y, 0.0f);
                    float h20 = fmaxf(acc1[nt][0] + el.x + e2.x, 0.0f);
                    float h21 = fmaxf(acc1[nt][1] + el.y + e2.y, 0.0f);
                    float h30 = fmaxf(acc1[nt][2] + el.x + e3.x, 0.0f);
                    float h31 = fmaxf(acc1[nt][3] + el.y + e3.y, 0.0f);
                    if (head == 0){
                        const float2 w2 = *(const float2*)&s_w2e[half*128 + c0];
                        eacc[0] = fmaf(h00, w2.x, fmaf(h01, w2.y, eacc[0]));
                        eacc[1] = fmaf(h10, w2.x, fmaf(h11, w2.y, eacc[1]));
                        eacc[2] = fmaf(h20, w2.x, fmaf(h21, w2.y, eacc[2]));
                        eacc[3] = fmaf(h30, w2.x, fmaf(h31, w2.y, eacc[3]));
                    } else {
                        fa[e*2]   = packh2(h00, h01);
                        fa[e*2+1] = packh2(h10, h11);
                        fb[e*2]   = packh2(h20, h21);
                        fb[e*2+1] = packh2(h30, h31);
                    }
                }
                if (head == 1){
                    uint32_t wb0, wb1;
                    ldsm2(wb0, wb1, wbBase + (uint32_t)(chunk*128 + qf*32));
                    mma16816(opA, fa[0],fa[1],fa[2],fa[3], wb0, wb1);
                    mma16816(opB, fb[0],fb[1],fb[2],fb[3], wb0, wb1);
                }
            }
        }

        if (s == 1){
            #pragma unroll
            for (int rh = 0; rh < 4; rh++){
                float v = eacc[rh];
                v += __shfl_xor_sync(0xffffffffu, v, 1);
                v += __shfl_xor_sync(0xffffffffu, v, 2);
                eacc[rh] = v;
            }
            if ((lane & 3) == 0){
                float b2 = eh_b2[0];
                #pragma unroll
                for (int rh = 0; rh < 4; rh++){
                    int jg = j0 + r0 + rh*8;
                    float v = eacc[rh] + b2;
                    if (ig == jg) v = -8.0f;
                    out[EDGE_OFF + b*NN*NN + ig*NN + jg] = v;
                }
            }
        }
    }

    // ---- op output: C layout rows r0,r0+8 (opA), r0+16,r0+24 (opB) ----
    {
        const float bo0 = oh_b2[cq], bo1 = oh_b2[cq + 1];
        #pragma unroll
        for (int mb = 0; mb < 2; mb++){
            const float* oc = mb ? opB : opA;
            #pragma unroll
            for (int rr = 0; rr < 2; rr++){
                int jg = j0 + r0 + mb*16 + rr*8;
                float2* dst = (float2*)&out[OP_OFF
                    + ((size_t)(b*NN*NN + ig*NN + jg))*NOPS + cq];
                *dst = make_float2(oc[rr*2] + bo0, oc[rr*2+1] + bo1);
            }
        }
    }
}

// ---------------------------------------------------------------------------
// Launch
// ---------------------------------------------------------------------------
extern "C" void kernel_launch(void* const* d_in, const int* in_sizes, int n_in,
                              void* d_out, int out_size)
{
    const float* obs    = (const float*)d_in[0];
    const float* latent = (const float*)d_in[1];
    const float* query  = (const float*)d_in[2];
    const float* enc_w1 = (const float*)d_in[3];
    const float* enc_b1 = (const float*)d_in[4];
    const float* enc_w2 = (const float*)d_in[5];
    const float* enc_b2 = (const float*)d_in[6];
    const float* upd_w  = (const float*)d_in[7];
    const float* upd_b  = (const float*)d_in[8];
    const float* gru_wi = (const float*)d_in[9];
    const float* gru_bi = (const float*)d_in[10];
    const float* gru_wh = (const float*)d_in[11];
    const float* gru_bh = (const float*)d_in[12];
    const float* eh_w1  = (const float*)d_in[13];
    const float* eh_b1  = (const float*)d_in[14];
    const float* eh_w2  = (const float*)d_in[15];
    const float* eh_b2  = (const float*)d_in[16];
    const float* oh_w1  = (const float*)d_in[17];
    const float* oh_b1  = (const float*)d_in[18];
    const float* oh_w2  = (const float*)d_in[19];
    const float* oh_b2  = (const float*)d_in[20];
    const float* q_w    = (const float*)d_in[21];
    const float* q_b    = (const float*)d_in[22];
    const float* nh_w1  = (const float*)d_in[23];
    const float* nh_b1  = (const float*)d_in[24];
    const float* nh_w2  = (const float*)d_in[25];
    const float* nh_b2  = (const float*)d_in[26];

    float* out = (float*)d_out;

    static bool inited = false;
    if (!inited){
        cudaFuncSetAttribute(pairKernel, cudaFuncAttributeMaxDynamicSharedMemorySize, PAIR_SMEM);
        inited = true;
    }

    prepB<<<64, 256>>>(eh_w1, oh_w1, oh_w2);

    nodeKernel<<<256, 256>>>(obs, latent, query,
                             enc_w1, enc_b1, enc_w2, enc_b2,
                             upd_w, upd_b,
                             gru_wi, gru_bi, gru_wh, gru_bh,
                             q_w, q_b, nh_w1, nh_b1, nh_w2, nh_b2,
                             out + NEXT_OFF);

    elKernel<<<dim3(128, 4), 256>>>(eh_w1, eh_b1, oh_w1, oh_b1);

    pairKernel<<<dim3(8, 32, 4), 256, PAIR_SMEM>>>(eh_w2, eh_b2, oh_b2, out);
}

// round 11
// speedup vs baseline: 7.8669x; 1.0087x over previous
#include <cuda_runtime.h>
#include <cuda_bf16.h>
#include <cuda_fp16.h>
#include <math.h>
#include <stdint.h>

// ---------------------------------------------------------------------------
// Problem constants
// ---------------------------------------------------------------------------
#define BB   4
#define NN   256
#define OBS  64
#define QDIM 32
#define HH   256
#define DD   128
#define NOPS 8
#define QE   64
#define BN   (BB*NN)          // 1024 rows

#define EDGE_OFF 0
#define OP_OFF   (BB*NN*NN)                 // 262144
#define NEXT_OFF (OP_OFF + BB*NN*NN*NOPS)   // 2359296

// ---------------------------------------------------------------------------
// Device scratch
// ---------------------------------------------------------------------------
__device__ float g_lat[BN*DD];
__device__ __half g_ELh[BN*HH];
__device__ __half g_ERh[BN*HH];
__device__ __half g_OLh[BN*HH];
__device__ __half g_ORh[BN*HH];
// fp16 pair-head weights: [s(4)][n(128)][k(128)], s = head*2 + half
__device__ __half g_Bfp[4*128*128];
// fp16 op layer-2 weights: [half(2)][n(8)][k(128)]
__device__ __half g_w2of[2*8*128];

__device__ __forceinline__ float sigf(float x){ return 1.0f/(1.0f+expf(-x)); }

__device__ __forceinline__ uint32_t smem_u32(const void* p){
    uint32_t a;
    asm("{ .reg .u64 t; cvta.to.shared.u64 t, %1; cvt.u32.u64 %0, t; }"
        : "=r"(a) : "l"(p));
    return a;
}

__device__ __forceinline__ void ldsm4(uint32_t& r0, uint32_t& r1, uint32_t& r2,
                                      uint32_t& r3, uint32_t addr){
    asm volatile("ldmatrix.sync.aligned.m8n8.x4.shared.b16 {%0,%1,%2,%3}, [%4];"
                 : "=r"(r0), "=r"(r1), "=r"(r2), "=r"(r3) : "r"(addr));
}
__device__ __forceinline__ void ldsm2(uint32_t& r0, uint32_t& r1, uint32_t addr){
    asm volatile("ldmatrix.sync.aligned.m8n8.x2.shared.b16 {%0,%1}, [%2];"
                 : "=r"(r0), "=r"(r1) : "r"(addr));
}
__device__ __forceinline__ void mma16816(float* d, uint32_t a0, uint32_t a1,
                                         uint32_t a2, uint32_t a3,
                                         uint32_t b0, uint32_t b1){
    asm volatile(
        "mma.sync.aligned.m16n8k16.row.col.f32.f16.f16.f32 "
        "{%0,%1,%2,%3}, {%4,%5,%6,%7}, {%8,%9}, {%0,%1,%2,%3};"
        : "+f"(d[0]), "+f"(d[1]), "+f"(d[2]), "+f"(d[3])
        : "r"(a0), "r"(a1), "r"(a2), "r"(a3), "r"(b0), "r"(b1));
}
__device__ __forceinline__ uint32_t packh2(float a, float b){
    __half2 h = __floats2half2_rn(a, b);
    return *reinterpret_cast<uint32_t*>(&h);
}

// ---------------------------------------------------------------------------
// Kernel A: per-node pipeline, 2 rows/block x 512 blocks, PLUS 64 extra
// blocks (512..575) that do the fp16 weight pre-conversion (merged prepB).
// ---------------------------------------------------------------------------
__global__ __launch_bounds__(256)
void nodeKernel(const float* __restrict__ obs, const float* __restrict__ latent,
                const float* __restrict__ query,
                const float* __restrict__ enc_w1, const float* __restrict__ enc_b1,
                const float* __restrict__ enc_w2, const float* __restrict__ enc_b2,
                const float* __restrict__ upd_w,  const float* __restrict__ upd_b,
                const float* __restrict__ gru_wi, const float* __restrict__ gru_bi,
                const float* __restrict__ gru_wh, const float* __restrict__ gru_bh,
                const float* __restrict__ q_w,    const float* __restrict__ q_b,
                const float* __restrict__ nh_w1,  const float* __restrict__ nh_b1,
                const float* __restrict__ nh_w2,  const float* __restrict__ nh_b2,
                const float* __restrict__ eh_w1,  const float* __restrict__ oh_w1,
                const float* __restrict__ oh_w2,
                float* __restrict__ out_next)
{
    const int t = threadIdx.x;

    if (blockIdx.x >= 512){
        // ---- merged prepB: fp16 conversion of pair-head weights ----
        int bx = blockIdx.x - 512;
        int gi0 = bx * 1024 + t;
        #pragma unroll
        for (int i = 0; i < 4; i++){
            int gi = gi0 + i*256;            // 0..65535 over (s,n,k)
            int s   = gi >> 14;
            int rem = gi & 16383;
            int n   = rem >> 7;
            int k   = rem & 127;
            int head = s >> 1, half = s & 1;
            const float* w = head ? oh_w1 : eh_w1;
            g_Bfp[(s*128 + n)*128 + k] = __float2half(w[(256 + k)*256 + half*128 + n]);
        }
        if (bx == 0){
            for (int idx = t; idx < 2048; idx += 256){
                int half = idx >> 10, rem = idx & 1023;
                int n = rem >> 7, k = rem & 127;
                g_w2of[idx] = __float2half(oh_w2[(half*128 + k)*8 + n]);
            }
        }
        return;
    }

    __shared__ float s_obs[2*64];     // later q_emb [2][64]
    __shared__ float s_h1 [2*256];    // later: [0:256)=upd, [256:512)=lat
    __shared__ float s_emb[2*256];
    __shared__ float s_gi [2*384];    // later query tmp [2][32]
    __shared__ float s_gh [2*384];    // later nh hidden [2][256]

    const int row0 = blockIdx.x * 2;

    if (t < 128) s_obs[t] = obs[row0*64 + t];
    __syncthreads();

    // h1 = relu(obs @ enc_w1 + b1)
    {
        float acc[2];
        float bv = enc_b1[t];
        acc[0] = bv; acc[1] = bv;
        #pragma unroll 4
        for (int k=0;k<64;k++){
            float w = enc_w1[k*256 + t];
            acc[0] = fmaf(s_obs[k], w, acc[0]);
            acc[1] = fmaf(s_obs[64+k], w, acc[1]);
        }
        s_h1[t]       = fmaxf(acc[0], 0.0f);
        s_h1[256 + t] = fmaxf(acc[1], 0.0f);
    }
    __syncthreads();

    // node_emb = relu(h1 @ enc_w2 + b2)
    {
        float acc[2];
        float bv = enc_b2[t];
        acc[0] = bv; acc[1] = bv;
        #pragma unroll 4
        for (int k=0;k<256;k++){
            float w = enc_w2[k*256 + t];
            acc[0] = fmaf(s_h1[k], w, acc[0]);
            acc[1] = fmaf(s_h1[256+k], w, acc[1]);
        }
        __syncthreads();
        s_emb[t]       = fmaxf(acc[0], 0.0f);
        s_emb[256 + t] = fmaxf(acc[1], 0.0f);
    }
    __syncthreads();

    float* s_upd = s_h1;          // [2][128]
    float* s_lat = s_h1 + 256;    // [2][128]

    // upd = node_emb @ upd_w + b   (thread t: row=t>>7, o=t&127)
    {
        const int o = t & 127;
        const int r = t >> 7;
        float acc = upd_b[o];
        #pragma unroll 4
        for (int k=0;k<256;k++)
            acc = fmaf(s_emb[r*256+k], upd_w[k*128 + o], acc);
        s_upd[r*128 + o] = acc;
    }
    if (t < 256) s_lat[t] = latent[row0*128 + t];
    __syncthreads();

    // gi / gh
    for (int o = t; o < 384; o += 256){
        float ai[2], ah[2];
        float bi = gru_bi[o], bh = gru_bh[o];
        ai[0] = bi; ai[1] = bi; ah[0] = bh; ah[1] = bh;
        #pragma unroll 4
        for (int k=0;k<128;k++){
            float wi = gru_wi[k*384 + o];
            float wh = gru_wh[k*384 + o];
            ai[0] = fmaf(s_upd[k], wi, ai[0]);
            ai[1] = fmaf(s_upd[128+k], wi, ai[1]);
            ah[0] = fmaf(s_lat[k], wh, ah[0]);
            ah[1] = fmaf(s_lat[128+k], wh, ah[1]);
        }
        s_gi[o] = ai[0]; s_gi[384+o] = ai[1];
        s_gh[o] = ah[0]; s_gh[384+o] = ah[1];
    }
    __syncthreads();

    // GRU elementwise (256 elems)
    {
        int r = t >> 7, d = t & 127;
        float ir = s_gi[r*384 + d],  iz = s_gi[r*384 + 128 + d], inn = s_gi[r*384 + 256 + d];
        float hr = s_gh[r*384 + d],  hz = s_gh[r*384 + 128 + d], hn  = s_gh[r*384 + 256 + d];
        float rg = sigf(ir + hr);
        float zg = sigf(iz + hz);
        float nh = tanhf(inn + rg*hn);
        float lv = (1.0f - zg)*nh + zg*s_lat[t];
        s_lat[t] = lv;
        g_lat[row0*128 + t] = lv;
    }
    __syncthreads();

    // q_emb = relu(query @ q_w + b)
    if (t < 64) s_gi[t] = query[row0*32 + t];
    __syncthreads();
    if (t < 128){
        int r = t >> 6, o = t & 63;
        float acc = q_b[o];
        #pragma unroll
        for (int k=0;k<32;k++) acc = fmaf(s_gi[r*32+k], q_w[k*64+o], acc);
        s_obs[t] = fmaxf(acc, 0.0f);
    }
    __syncthreads();

    // nh hidden = relu([lat, emb, q] @ nh_w1 + b)
    {
        float acc[2];
        float bv = nh_b1[t];
        acc[0] = bv; acc[1] = bv;
        #pragma unroll 4
        for (int k=0;k<128;k++){
            float w = nh_w1[k*256 + t];
            acc[0] = fmaf(s_lat[k], w, acc[0]);
            acc[1] = fmaf(s_lat[128+k], w, acc[1]);
        }
        #pragma unroll 4
        for (int k=0;k<256;k++){
            float w = nh_w1[(128+k)*256 + t];
            acc[0] = fmaf(s_emb[k], w, acc[0]);
            acc[1] = fmaf(s_emb[256+k], w, acc[1]);
        }
        #pragma unroll 4
        for (int k=0;k<64;k++){
            float w = nh_w1[(384+k)*256 + t];
            acc[0] = fmaf(s_obs[k], w, acc[0]);
            acc[1] = fmaf(s_obs[64+k], w, acc[1]);
        }
        s_gh[t]       = fmaxf(acc[0], 0.0f);
        s_gh[256 + t] = fmaxf(acc[1], 0.0f);
    }
    __syncthreads();

    // next_pred (warps 0-1, one row each)
    {
        const int w = t >> 5, l = t & 31;
        if (w < 2){
            float p = 0.0f;
            for (int o = l; o < 256; o += 32) p = fmaf(s_gh[w*256 + o], nh_w2[o], p);
            #pragma unroll
            for (int off = 16; off; off >>= 1) p += __shfl_down_sync(0xffffffffu, p, off);
            if (l == 0) out_next[row0 + w] = p + nh_b2[0];
        }
    }
}

// ---------------------------------------------------------------------------
// Kernel B: EL/ER/OL/OR = lat @ W_slice (+bias), stored fp16. grid (128,4).
// ---------------------------------------------------------------------------
__global__ __launch_bounds__(256)
void elKernel(const float* __restrict__ eh_w1, const float* __restrict__ eh_b1,
              const float* __restrict__ oh_w1, const float* __restrict__ oh_b1)
{
    __shared__ float s_lat[8*128];
    const int t = threadIdx.x;
    const int row0 = blockIdx.x * 8;
    const int m = blockIdx.y;

    const float* W; const float* bias = nullptr; __half* dst;
    if (m == 0)      { W = eh_w1;            bias = eh_b1; dst = g_ELh; }
    else if (m == 1) { W = eh_w1 + 128*256;                dst = g_ERh; }
    else if (m == 2) { W = oh_w1;            bias = oh_b1; dst = g_OLh; }
    else             { W = oh_w1 + 128*256;                dst = g_ORh; }

    for (int idx = t; idx < 1024; idx += 256) s_lat[idx] = g_lat[row0*128 + idx];
    __syncthreads();

    float acc[8];
    float bv = bias ? bias[t] : 0.0f;
    #pragma unroll
    for (int r=0;r<8;r++) acc[r] = bv;
    #pragma unroll 4
    for (int k=0;k<128;k++){
        float w = W[k*256 + t];
        #pragma unroll
        for (int r=0;r<8;r++) acc[r] = fmaf(s_lat[r*128+k], w, acc[r]);
    }
    #pragma unroll
    for (int r=0;r<8;r++) dst[(row0+r)*256 + t] = __float2half(acc[r]);
}

// ---------------------------------------------------------------------------
// Kernel C: pair MLP. CTA tile 8i x 32j = 256 pairs, 256 threads, 8 warps.
// TWO CTAs per SM (smem 112.4KB, regs capped at 128). Unchanged from R10.
// ---------------------------------------------------------------------------
#define OFF_A    0                         // 256 rows * 256B = 65536
#define OFF_B    65536                     // 128 rows * 256B = 32768
#define OFF_ELI  98304                     // 8*136*2  = 2176
#define OFF_ERJ  100480                    // 32*136*2 = 8704
#define OFF_W2E  109184                    // 256*4 = 1024
#define OFF_W2O  110208                    // 8 rows * 272B = 2176
#define PAIR_SMEM 112384

__global__ __launch_bounds__(256, 2)
void pairKernel(const float* __restrict__ eh_w2, const float* __restrict__ eh_b2,
                const float* __restrict__ oh_b2,
                float* __restrict__ out)
{
    extern __shared__ __align__(16) char sm[];
    float*  s_li   = (float*)(sm + OFF_B);          // prologue staging [8][128]
    float*  s_lj   = (float*)(sm + OFF_B + 4096);   // prologue staging [32][128]
    __half* s_eli  = (__half*)(sm + OFF_ELI);       // per-stage [8][136]
    __half* s_erj  = (__half*)(sm + OFF_ERJ);       // per-stage [32][136]
    float*  s_w2e  = (float*)(sm + OFF_W2E);        // [256] (both halves)

    const uint32_t smb = smem_u32(sm);
    const int t    = threadIdx.x;
    const int wid  = t >> 5;
    const int lane = t & 31;
    const int b    = blockIdx.z;
    const int i0   = blockIdx.y * 8;
    const int j0   = blockIdx.x * 32;
    const int base = b * NN;

    // ---- prologue: stage lat rows (into B region) + w2e ----
    for (int idx = t; idx < 1024; idx += 256) s_li[idx] = g_lat[(base + i0)*128 + idx];
    for (int idx = t; idx < 4096; idx += 256) s_lj[idx] = g_lat[(base + j0)*128 + idx];
    if (t < 256) s_w2e[t] = eh_w2[t];
    __syncthreads();

    // ---- build A = |li - lj| fp16, 256 rows x 256B, XOR swizzle ----
    for (int c = t; c < 4096; c += 256){
        int p = c >> 4, kg = c & 15;          // p: pair row, kg: 16B chunk
        int il = p >> 5, jl = p & 31;
        const float4* li4 = (const float4*)&s_li[il*128 + kg*8];
        const float4* lj4 = (const float4*)&s_lj[jl*128 + kg*8];
        float4 x0 = li4[0], x1 = li4[1], y0 = lj4[0], y1 = lj4[1];
        float a[8] = { fabsf(x0.x-y0.x), fabsf(x0.y-y0.y), fabsf(x0.z-y0.z), fabsf(x0.w-y0.w),
                       fabsf(x1.x-y1.x), fabsf(x1.y-y1.y), fabsf(x1.z-y1.z), fabsf(x1.w-y1.w) };
        uint32_t hp[4];
        #pragma unroll
        for (int q = 0; q < 4; q++) hp[q] = packh2(a[2*q], a[2*q+1]);
        uint32_t boff = (uint32_t)(p*256 + ((kg ^ (p & 7)) << 4));
        *(uint4*)(sm + OFF_A + boff) = make_uint4(hp[0],hp[1],hp[2],hp[3]);
    }

    // ldmatrix geometry
    const uint32_t sw    = (uint32_t)(lane & 7);
    const uint32_t aBase0 = smb + OFF_A
        + (uint32_t)(wid*32 + (lane & 7) + ((lane >> 3) & 1)*8) * 256;
    const uint32_t aBase1 = aBase0 + 16*256;
    const uint32_t kbitA = (uint32_t)((lane >> 4) & 1);
    const uint32_t bBase = smb + OFF_B
        + (uint32_t)((lane & 7) + ((lane >> 4) & 1)*8) * 256;
    const uint32_t kbitB = (uint32_t)((lane >> 3) & 1);
    const uint32_t wbBase = smb + OFF_W2O + (uint32_t)(lane & 7)*272
        + (uint32_t)((lane >> 3) & 1)*16;

    // epilogue geometry: thread owns rows r0,r0+8 (mb0), r0+16,r0+24 (mb1)
    const int r0  = lane >> 2;
    const int cq  = 2*(lane & 3);
    const int ig  = i0 + wid;

    float eacc[4] = {0.0f, 0.0f, 0.0f, 0.0f};
    float opA[4] = {0.0f, 0.0f, 0.0f, 0.0f};
    float opB[4] = {0.0f, 0.0f, 0.0f, 0.0f};

    for (int s = 0; s < 4; s++){
        const int head = s >> 1, half = s & 1;
        __syncthreads();     // A-build done (s=0) / prev stage epilogue done

        // stage B fp16 (swizzled)
        const __half* srcB = &g_Bfp[(size_t)s*16384];
        for (int idx = t; idx < 2048; idx += 256){
            int n = idx >> 4, kg = idx & 15;
            uint4 v = *(const uint4*)(srcB + n*128 + kg*8);
            *(uint4*)(sm + OFF_B + n*256 + ((kg ^ (n & 7)) << 4)) = v;
        }
        // stage EL (8 rows) / ER (32 rows), fp16, 16B chunks
        const __half* gl = head ? g_OLh : g_ELh;
        const __half* gr = head ? g_ORh : g_ERh;
        for (int idx = t; idx < 128; idx += 256){
            int r = idx >> 4, kg = idx & 15;
            uint4 v = *(const uint4*)(gl + (base + i0 + r)*256 + half*128 + kg*8);
            *(uint4*)(sm + OFF_ELI + r*272 + kg*16) = v;
        }
        for (int idx = t; idx < 512; idx += 256){
            int r = idx >> 4, kg = idx & 15;
            uint4 v = *(const uint4*)(gr + (base + j0 + r)*256 + half*128 + kg*8);
            *(uint4*)(sm + OFF_ERJ + r*272 + kg*16) = v;
        }
        // stage w2o fp16 for this half (op head only): [8][128] -> 272B rows
        if (head == 1){
            for (int idx = t; idx < 512; idx += 256){
                int n = idx >> 6, kp = idx & 63;
                uint32_t v = *(const uint32_t*)&g_w2of[half*1024 + n*128 + kp*2];
                *(uint32_t*)(sm + OFF_W2O + n*272 + kp*4) = v;
            }
        }
        __syncthreads();

        #pragma unroll
        for (int chunk = 0; chunk < 2; chunk++){
            float acc0[8][4], acc1[8][4];
            #pragma unroll
            for (int nt=0;nt<8;nt++)
                #pragma unroll
                for (int v=0;v<4;v++){ acc0[nt][v] = 0.0f; acc1[nt][v] = 0.0f; }

            #pragma unroll
            for (int ks = 0; ks < 8; ks++){
                const uint32_t aoff = ((((uint32_t)(2*ks) + kbitA) ^ sw) << 4);
                uint32_t p0,p1,p2,p3, q0,q1,q2,q3;
                ldsm4(p0,p1,p2,p3, aBase0 + aoff);
                ldsm4(q0,q1,q2,q3, aBase1 + aoff);
                const uint32_t bch = ((((uint32_t)(2*ks) + kbitB) ^ sw) << 4);
                #pragma unroll
                for (int ntp = 0; ntp < 4; ntp++){
                    uint32_t baddr = bBase + (uint32_t)(chunk*64 + ntp*16)*256 + bch;
                    uint32_t b0,b1,b2,b3;
                    ldsm4(b0,b1,b2,b3, baddr);
                    mma16816(acc0[2*ntp],   p0,p1,p2,p3, b0,b1);
                    mma16816(acc0[2*ntp+1], p0,p1,p2,p3, b2,b3);
                    mma16816(acc1[2*ntp],   q0,q1,q2,q3, b0,b1);
                    mma16816(acc1[2*ntp+1], q0,q1,q2,q3, b2,b3);
                }
            }

            // ---- epilogue for this 64-col chunk (fp16 tables, f32 math) ----
            #pragma unroll
            for (int qf = 0; qf < 4; qf++){
                uint32_t fa[4], fb[4];
                #pragma unroll
                for (int e = 0; e < 2; e++){
                    const int nt = qf*2 + e;
                    const int c0 = chunk*64 + nt*8 + cq;
                    float2 el = __half22float2(*(const __half2*)&s_eli[wid*136 + c0]);
                    float2 e0 = __half22float2(*(const __half2*)&s_erj[r0*136 + c0]);
                    float2 e1 = __half22float2(*(const __half2*)&s_erj[(r0+8)*136 + c0]);
                    float2 e2 = __half22float2(*(const __half2*)&s_erj[(r0+16)*136 + c0]);
                    float2 e3 = __half22float2(*(const __half2*)&s_erj[(r0+24)*136 + c0]);
                    float h00 = fmaxf(acc0[nt][0] + el.x + e0.x, 0.0f);
                    float h01 = fmaxf(acc0[nt][1] + el.y + e0.y, 0.0f);
                    float h10 = fmaxf(acc0[nt][2] + el.x + e1.x, 0.0f);
                    float h11 = fmaxf(acc0[nt][3] + el.y + e1.y, 0.0f);
                    float h20 = fmaxf(acc1[nt][0] + el.x + e2.x, 0.0f);
                    float h21 = fmaxf(acc1[nt][1] + el.y + e2.y, 0.0f);
                    float h30 = fmaxf(acc1[nt][2] + el.x + e3.x, 0.0f);
                    float h31 = fmaxf(acc1[nt][3] + el.y + e3.y, 0.0f);
                    if (head == 0){
                        const float2 w2 = *(const float2*)&s_w2e[half*128 + c0];
                        eacc[0] = fmaf(h00, w2.x, fmaf(h01, w2.y, eacc[0]));
                        eacc[1] = fmaf(h10, w2.x, fmaf(h11, w2.y, eacc[1]));
                        eacc[2] = fmaf(h20, w2.x, fmaf(h21, w2.y, eacc[2]));
                        eacc[3] = fmaf(h30, w2.x, fmaf(h31, w2.y, eacc[3]));
                    } else {
                        fa[e*2]   = packh2(h00, h01);
                        fa[e*2+1] = packh2(h10, h11);
                        fb[e*2]   = packh2(h20, h21);
                        fb[e*2+1] = packh2(h30, h31);
                    }
                }
                if (head == 1){
                    uint32_t wb0, wb1;
                    ldsm2(wb0, wb1, wbBase + (uint32_t)(chunk*128 + qf*32));
                    mma16816(opA, fa[0],fa[1],fa[2],fa[3], wb0, wb1);
                    mma16816(opB, fb[0],fb[1],fb[2],fb[3], wb0, wb1);
                }
            }
        }

        if (s == 1){
            #pragma unroll
            for (int rh = 0; rh < 4; rh++){
                float v = eacc[rh];
                v += __shfl_xor_sync(0xffffffffu, v, 1);
                v += __shfl_xor_sync(0xffffffffu, v, 2);
                eacc[rh] = v;
            }
            if ((lane & 3) == 0){
                float b2 = eh_b2[0];
                #pragma unroll
                for (int rh = 0; rh < 4; rh++){
                    int jg = j0 + r0 + rh*8;
                    float v = eacc[rh] + b2;
                    if (ig == jg) v = -8.0f;
                    out[EDGE_OFF + b*NN*NN + ig*NN + jg] = v;
                }
            }
        }
    }

    // ---- op output: C layout rows r0,r0+8 (opA), r0+16,r0+24 (opB) ----
    {
        const float bo0 = oh_b2[cq], bo1 = oh_b2[cq + 1];
        #pragma unroll
        for (int mb = 0; mb < 2; mb++){
            const float* oc = mb ? opB : opA;
            #pragma unroll
            for (int rr = 0; rr < 2; rr++){
                int jg = j0 + r0 + mb*16 + rr*8;
                float2* dst = (float2*)&out[OP_OFF
                    + ((size_t)(b*NN*NN + ig*NN + jg))*NOPS + cq];
                *dst = make_float2(oc[rr*2] + bo0, oc[rr*2+1] + bo1);
            }
        }
    }
}

// ---------------------------------------------------------------------------
// Launch
// ---------------------------------------------------------------------------
extern "C" void kernel_launch(void* const* d_in, const int* in_sizes, int n_in,
                              void* d_out, int out_size)
{
    const float* obs    = (const float*)d_in[0];
    const float* latent = (const float*)d_in[1];
    const float* query  = (const float*)d_in[2];
    const float* enc_w1 = (const float*)d_in[3];
    const float* enc_b1 = (const float*)d_in[4];
    const float* enc_w2 = (const float*)d_in[5];
    const float* enc_b2 = (const float*)d_in[6];
    const float* upd_w  = (const float*)d_in[7];
    const float* upd_b  = (const float*)d_in[8];
    const float* gru_wi = (const float*)d_in[9];
    const float* gru_bi = (const float*)d_in[10];
    const float* gru_wh = (const float*)d_in[11];
    const float* gru_bh = (const float*)d_in[12];
    const float* eh_w1  = (const float*)d_in[13];
    const float* eh_b1  = (const float*)d_in[14];
    const float* eh_w2  = (const float*)d_in[15];
    const float* eh_b2  = (const float*)d_in[16];
    const float* oh_w1  = (const float*)d_in[17];
    const float* oh_b1  = (const float*)d_in[18];
    const float* oh_w2  = (const float*)d_in[19];
    const float* oh_b2  = (const float*)d_in[20];
    const float* q_w    = (const float*)d_in[21];
    const float* q_b    = (const float*)d_in[22];
    const float* nh_w1  = (const float*)d_in[23];
    const float* nh_b1  = (const float*)d_in[24];
    const float* nh_w2  = (const float*)d_in[25];
    const float* nh_b2  = (const float*)d_in[26];

    float* out = (float*)d_out;

    static bool inited = false;
    if (!inited){
        cudaFuncSetAttribute(pairKernel, cudaFuncAttributeMaxDynamicSharedMemorySize, PAIR_SMEM);
        inited = true;
    }

    nodeKernel<<<576, 256>>>(obs, latent, query,
                             enc_w1, enc_b1, enc_w2, enc_b2,
                             upd_w, upd_b,
                             gru_wi, gru_bi, gru_wh, gru_bh,
                             q_w, q_b, nh_w1, nh_b1, nh_w2, nh_b2,
                             eh_w1, oh_w1, oh_w2,
                             out + NEXT_OFF);

    elKernel<<<dim3(128, 4), 256>>>(eh_w1, eh_b1, oh_w1, oh_b1);

    pairKernel<<<dim3(8, 32, 4), 256, PAIR_SMEM>>>(eh_w2, eh_b2, oh_b2, out);
}